// round 1
// baseline (speedup 1.0000x reference)
#include <cuda_runtime.h>
#include <math.h>

// ---------------- device scratch (no allocs allowed) ----------------
__device__ __align__(16) float2 d_Y[4096ull * 4096ull];   // FFT(x) per (b,i) plane, 128MB
__device__ float d_G[64 * 4096];                          // G'[i,h,w], 1MB
__device__ float d_sp4[4 * 64 * 4096];                    // conv partials, 4MB

// ---------------- complex helpers ----------------
__device__ __forceinline__ float2 cmul(float2 a, float2 b) {
    return make_float2(a.x * b.x - a.y * b.y, a.x * b.y + a.y * b.x);
}
__device__ __forceinline__ float2 cadd(float2 a, float2 b) { return make_float2(a.x + b.x, a.y + b.y); }
__device__ __forceinline__ float2 csub(float2 a, float2 b) { return make_float2(a.x - b.x, a.y - b.y); }

// 8-point DIF FFT in registers, natural-order output. SGN=-1 fwd, +1 inv.
template <int SGN>
__device__ __forceinline__ void fft8(float2 v[8]) {
    const float S = (float)SGN;
    const float C = 0.70710678118654752440f;
    float2 t0 = cadd(v[0], v[4]), t4 = csub(v[0], v[4]);
    float2 t1 = cadd(v[1], v[5]), t5 = csub(v[1], v[5]);
    float2 t2 = cadd(v[2], v[6]), t6 = csub(v[2], v[6]);
    float2 t3 = cadd(v[3], v[7]), t7 = csub(v[3], v[7]);
    t5 = cmul(t5, make_float2(C, S * C));
    t6 = make_float2(-S * t6.y, S * t6.x);
    t7 = cmul(t7, make_float2(-C, S * C));
    float2 u0 = cadd(t0, t2), u2 = csub(t0, t2);
    float2 u1 = cadd(t1, t3);
    float2 d13 = csub(t1, t3);
    float2 u3 = make_float2(-S * d13.y, S * d13.x);
    float2 u4 = cadd(t4, t6), u6 = csub(t4, t6);
    float2 u5 = cadd(t5, t7);
    float2 d57 = csub(t5, t7);
    float2 u7 = make_float2(-S * d57.y, S * d57.x);
    v[0] = cadd(u0, u1); v[4] = csub(u0, u1);
    v[2] = cadd(u2, u3); v[6] = csub(u2, u3);
    v[1] = cadd(u4, u5); v[5] = csub(u4, u5);
    v[3] = cadd(u6, u7); v[7] = csub(u6, u7);
}

// One pass (rows or cols) of a 64x64 2D FFT held in shared memory.
// 512 threads; group g = tid>>3 owns line g; t = tid&7 is its lane.
// 64-pt FFT via N = 8*8 decomposition: n = 8*n1 + n2, k = k1 + 8*k2.
template <int SGN, bool ROWS>
__device__ __forceinline__ void fft_pass(float2* sm, int tid) {
    const int g = tid >> 3;
    const int t = tid & 7;
#define LIDX(n) (ROWS ? (g * 65 + (n)) : ((n) * 65 + g))
    float2 v[8];
#pragma unroll
    for (int n1 = 0; n1 < 8; n1++) v[n1] = sm[LIDX(8 * n1 + t)];
    fft8<SGN>(v);  // DFT over n1 at fixed n2=t  -> A[k1][t]
#pragma unroll
    for (int k1 = 1; k1 < 8; k1++) {  // twiddle W64^{SGN * t * k1}
        float sn, cs;
        __sincosf((float)SGN * 6.283185307179586f * (float)(t * k1) * (1.0f / 64.0f), &sn, &cs);
        v[k1] = cmul(v[k1], make_float2(cs, sn));
    }
    __syncwarp();
#pragma unroll
    for (int k1 = 0; k1 < 8; k1++) sm[LIDX(8 * k1 + t)] = v[k1];  // A at [k1*8 + n2]
    __syncwarp();
#pragma unroll
    for (int n2 = 0; n2 < 8; n2++) v[n2] = sm[LIDX(t * 8 + n2)];  // thread t takes k1=t
    fft8<SGN>(v);  // DFT over n2 -> X[t + 8*k2]
    __syncwarp();
#pragma unroll
    for (int k2 = 0; k2 < 8; k2++) sm[LIDX(t + 8 * k2)] = v[k2];
#undef LIDX
}

// ---------------- kernel 1: forward FFT2 of each (b,i) plane ----------------
__global__ __launch_bounds__(512) void fwd_fft_kernel(const float* __restrict__ x) {
    __shared__ float2 sm[64 * 65];
    const int plane = blockIdx.x;
    const int tid = threadIdx.x;
    const float* xp = x + (size_t)plane * 4096;
    for (int k = tid; k < 4096; k += 512)
        sm[(k >> 6) * 65 + (k & 63)] = make_float2(xp[k], 0.f);
    __syncthreads();
    fft_pass<-1, true>(sm, tid);
    __syncthreads();
    fft_pass<-1, false>(sm, tid);
    __syncthreads();
    float2* yp = d_Y + (size_t)plane * 4096;
    for (int k = tid; k < 4096; k += 512)
        yp[k] = sm[(k >> 6) * 65 + (k & 63)];
}

// ---------------- kernel 2: attention + log-Gabor combine -> G'[i,h,w] ----------------
__global__ __launch_bounds__(256) void attn_kernel(
    const float* __restrict__ f0, const float* __restrict__ theta,
    const float* __restrict__ sigma, const float* __restrict__ theta0,
    const float* __restrict__ w1, const float* __restrict__ b1,
    const float* __restrict__ w2, const float* __restrict__ b2) {
    __shared__ __align__(16) float s_w1[64 * 64];  // [c][o], channel-shifted
    __shared__ float s_w2[3 * 64];
    __shared__ float s_b1[64];
    __shared__ float s_b2[3];
    __shared__ float s_lf0[3], s_i2ls2[3], s_th[3], s_i2t02[3];
    const int i = blockIdx.x;
    const int tid = threadIdx.x;

    for (int k = tid; k < 4096; k += 256) {
        int c = k >> 6, o = k & 63;
        s_w1[c * 64 + o] = w1[o * 64 + ((c + 32) & 63)];
    }
    if (tid < 64) s_b1[tid] = b1[tid];
    if (tid < 192) s_w2[tid] = w2[tid];
    if (tid < 3) {
        s_b2[tid] = b2[tid];
        int ip = (i + 32) & 63;
        int idx = tid * 64 + ip;  // [S, O=1, I]
        s_lf0[tid] = logf(f0[idx]);
        float ls = logf(sigma[idx]);
        s_i2ls2[tid] = 1.f / (2.f * ls * ls);
        s_th[tid] = theta[idx];
        float t0v = theta0[idx];
        s_i2t02[tid] = 1.f / (2.f * t0v * t0v);
    }
    __syncthreads();

    const float2* Yp = d_Y + (size_t)i * 64 * 4096;
    const int pbeg = blockIdx.y * 1024;
    for (int p = pbeg + tid; p < pbeg + 1024; p += 256) {
        float h[64];
#pragma unroll
        for (int o = 0; o < 64; o++) h[o] = s_b1[o];
        for (int c = 0; c < 64; c++) {
            float2 yv = Yp[(size_t)c * 4096 + p];
            float m = sqrtf(yv.x * yv.x + yv.y * yv.y);
            const float4* wr = (const float4*)&s_w1[c * 64];
#pragma unroll
            for (int o4 = 0; o4 < 16; o4++) {
                float4 wv = wr[o4];
                h[4 * o4 + 0] = fmaf(wv.x, m, h[4 * o4 + 0]);
                h[4 * o4 + 1] = fmaf(wv.y, m, h[4 * o4 + 1]);
                h[4 * o4 + 2] = fmaf(wv.z, m, h[4 * o4 + 2]);
                h[4 * o4 + 3] = fmaf(wv.w, m, h[4 * o4 + 3]);
            }
        }
        float l0 = s_b2[0], l1 = s_b2[1], l2 = s_b2[2];
#pragma unroll
        for (int o = 0; o < 64; o++) {
            float hv = fmaxf(h[o], 0.f);
            l0 = fmaf(s_w2[o], hv, l0);
            l1 = fmaf(s_w2[64 + o], hv, l1);
            l2 = fmaf(s_w2[128 + o], hv, l2);
        }
        float mx = fmaxf(l0, fmaxf(l1, l2));
        float e0 = __expf(l0 - mx), e1 = __expf(l1 - mx), e2 = __expf(l2 - mx);
        float inv = 1.f / (e0 + e1 + e2);
        float aw[3] = {e0 * inv, e1 * inv, e2 * inv};
        // filter at shifted grid coords
        int hh = ((p >> 6) + 32) & 63;
        int ww = ((p & 63) + 32) & 63;
        float yv_ = -1.f + 2.f * (float)hh * (1.f / 63.f);
        float xv_ = -1.f + 2.f * (float)ww * (1.f / 63.f);
        float r2 = xv_ * xv_ + yv_ * yv_ + 1e-6f;
        float lr = 0.5f * logf(r2);
        float phi = atan2f(yv_, xv_);
        float G = 0.f;
#pragma unroll
        for (int s = 0; s < 3; s++) {
            float dl = lr - s_lf0[s];
            float dp = phi - s_th[s];
            float F = __expf(-(dl * dl) * s_i2ls2[s] - (dp * dp) * s_i2t02[s]);
            G = fmaf(F, aw[s], G);
        }
        d_G[i * 4096 + p] = G;
    }
}

// ---------------- kernel 3: 3x3 spatial conv (channel-split partials) ----------------
__global__ __launch_bounds__(256) void conv_kernel(const float* __restrict__ x,
                                                   const float* __restrict__ cw) {
    __shared__ float sp[66 * 66];
    __shared__ float sw[16][9];
    const int b = blockIdx.x, cg = blockIdx.y, tid = threadIdx.x;
    const int c0 = cg * 16;
    for (int k = tid; k < 66 * 66; k += 256) sp[k] = 0.f;
    for (int k = tid; k < 144; k += 256) sw[k / 9][k % 9] = cw[c0 * 9 + k];
    float acc[16];
#pragma unroll
    for (int q = 0; q < 16; q++) acc[q] = 0.f;
    const float* xb = x + ((size_t)b * 64 + c0) * 4096;
    for (int c = 0; c < 16; c++) {
        __syncthreads();
        for (int k = tid; k < 4096; k += 256)
            sp[((k >> 6) + 1) * 66 + (k & 63) + 1] = xb[c * 4096 + k];
        __syncthreads();
#pragma unroll
        for (int q = 0; q < 16; q++) {
            int p = tid + q * 256;
            int hh = p >> 6, ww = p & 63;
            float a = acc[q];
            const float* wr = sw[c];
#pragma unroll
            for (int kh = 0; kh < 3; kh++)
#pragma unroll
                for (int kw = 0; kw < 3; kw++)
                    a = fmaf(sp[(hh + kh) * 66 + ww + kw], wr[kh * 3 + kw], a);
            acc[q] = a;
        }
    }
    float* o = d_sp4 + ((size_t)cg * 64 + b) * 4096;
#pragma unroll
    for (int q = 0; q < 16; q++) o[tid + q * 256] = acc[q];
}

// ---------------- kernel 4: masked pointwise * IFFT2 * mix epilogue ----------------
__global__ __launch_bounds__(512) void inv_kernel(const float* __restrict__ fbs,
                                                  const float* __restrict__ mixp,
                                                  float* __restrict__ out) {
    __shared__ float2 sm[64 * 65];
    const int plane = blockIdx.x;
    const int b = plane >> 6, i = plane & 63;
    const int tid = threadIdx.x;
    const float mix = mixp[0];
    const float c1 = 1.f - mix;
    const int bb = (b + 32) & 63;
    const int si = (int)floorf((fbs[bb * 2 + 0] + 1.f) * 0.5f * 64.f);
    const int ei = (int)floorf((fbs[bb * 2 + 1] + 1.f) * 0.5f * 64.f);
    const int ii = (i + 32) & 63;
    float* op = out + (size_t)plane * 4096;
    const float* sA = d_sp4 + (size_t)b * 4096;
    const float* sB = sA + 64 * 4096;
    const float* sC = sB + 64 * 4096;
    const float* sD = sC + 64 * 4096;

    if (!(ii >= si && ii < ei)) {  // whole z-plane masked to zero
        for (int k = tid; k < 4096; k += 512)
            op[k] = c1 * (sA[k] + sB[k] + sC[k] + sD[k]);
        return;
    }

    const float2* Yp = d_Y + (size_t)plane * 4096;
    const float* Gp = d_G + i * 4096;
    for (int k = tid; k < 4096; k += 512) {
        int hh = ((k >> 6) + 32) & 63;
        float g = (hh >= si && hh < ei) ? Gp[k] : 0.f;
        float2 y = Yp[k];
        sm[(k >> 6) * 65 + (k & 63)] = make_float2(y.x * g, y.y * g);
    }
    __syncthreads();
    fft_pass<1, true>(sm, tid);
    __syncthreads();
    fft_pass<1, false>(sm, tid);
    __syncthreads();
    const float scale = mix * (1.f / 4096.f);
    for (int k = tid; k < 4096; k += 512) {
        float xf = sm[(k >> 6) * 65 + (k & 63)].x;
        op[k] = fmaf(scale, xf, c1 * (sA[k] + sB[k] + sC[k] + sD[k]));
    }
}

// ---------------- launch ----------------
extern "C" void kernel_launch(void* const* d_in, const int* in_sizes, int n_in,
                              void* d_out, int out_size) {
    const float* x      = (const float*)d_in[0];
    const float* f0     = (const float*)d_in[1];
    const float* theta  = (const float*)d_in[2];
    const float* sigma  = (const float*)d_in[3];
    const float* theta0 = (const float*)d_in[4];
    const float* fbs    = (const float*)d_in[5];
    const float* mix    = (const float*)d_in[6];
    const float* w1     = (const float*)d_in[7];
    const float* b1     = (const float*)d_in[8];
    const float* w2     = (const float*)d_in[9];
    const float* b2     = (const float*)d_in[10];
    const float* conv_w = (const float*)d_in[11];
    float* out = (float*)d_out;

    conv_kernel<<<dim3(64, 4), 256>>>(x, conv_w);
    fwd_fft_kernel<<<4096, 512>>>(x);
    attn_kernel<<<dim3(64, 4), 256>>>(f0, theta, sigma, theta0, w1, b1, w2, b2);
    inv_kernel<<<4096, 512>>>(fbs, mix, out);
}

// round 2
// speedup vs baseline: 1.3797x; 1.3797x over previous
#include <cuda_runtime.h>
#include <cuda_fp16.h>
#include <math.h>

// ---------------- device scratch (no allocs allowed) ----------------
__device__ __align__(16) float2 d_Y[4096ull * 4096ull];   // complex FFT planes (only masked-in planes written)
__device__ __align__(16) __half d_Mh[4096ull * 4096ull];  // |FFT| magnitudes, fp16, 32MB
__device__ float d_G[64 * 4096];                          // G'[i,h,w], 1MB
__device__ float d_sp4[4 * 64 * 4096];                    // conv partials, 4MB
__device__ float d_sp[64 * 4096];                         // reduced conv, 1MB

// ---------------- complex helpers ----------------
__device__ __forceinline__ float2 cmul(float2 a, float2 b) {
    return make_float2(a.x * b.x - a.y * b.y, a.x * b.y + a.y * b.x);
}
__device__ __forceinline__ float2 cadd(float2 a, float2 b) { return make_float2(a.x + b.x, a.y + b.y); }
__device__ __forceinline__ float2 csub(float2 a, float2 b) { return make_float2(a.x - b.x, a.y - b.y); }

// packed f32x2 FMA (FFMA2) helpers
__device__ __forceinline__ void fma2(unsigned long long& d, unsigned long long a,
                                     unsigned long long b, unsigned long long c) {
    asm("fma.rn.f32x2 %0, %1, %2, %3;" : "=l"(d) : "l"(a), "l"(b), "l"(c));
}
__device__ __forceinline__ unsigned long long pack2(float lo, float hi) {
    unsigned long long v;
    asm("mov.b64 %0, {%1, %2};" : "=l"(v) : "f"(lo), "f"(hi));
    return v;
}
__device__ __forceinline__ void unpack2(unsigned long long v, float& lo, float& hi) {
    asm("mov.b64 {%0, %1}, %2;" : "=f"(lo), "=f"(hi) : "l"(v));
}

// 8-point DIF FFT in registers, natural-order output. SGN=-1 fwd, +1 inv.
template <int SGN>
__device__ __forceinline__ void fft8(float2 v[8]) {
    const float S = (float)SGN;
    const float C = 0.70710678118654752440f;
    float2 t0 = cadd(v[0], v[4]), t4 = csub(v[0], v[4]);
    float2 t1 = cadd(v[1], v[5]), t5 = csub(v[1], v[5]);
    float2 t2 = cadd(v[2], v[6]), t6 = csub(v[2], v[6]);
    float2 t3 = cadd(v[3], v[7]), t7 = csub(v[3], v[7]);
    t5 = cmul(t5, make_float2(C, S * C));
    t6 = make_float2(-S * t6.y, S * t6.x);
    t7 = cmul(t7, make_float2(-C, S * C));
    float2 u0 = cadd(t0, t2), u2 = csub(t0, t2);
    float2 u1 = cadd(t1, t3);
    float2 d13 = csub(t1, t3);
    float2 u3 = make_float2(-S * d13.y, S * d13.x);
    float2 u4 = cadd(t4, t6), u6 = csub(t4, t6);
    float2 u5 = cadd(t5, t7);
    float2 d57 = csub(t5, t7);
    float2 u7 = make_float2(-S * d57.y, S * d57.x);
    v[0] = cadd(u0, u1); v[4] = csub(u0, u1);
    v[2] = cadd(u2, u3); v[6] = csub(u2, u3);
    v[1] = cadd(u4, u5); v[5] = csub(u4, u5);
    v[3] = cadd(u6, u7); v[7] = csub(u6, u7);
}

// One pass (rows or cols) of a 64x64 2D FFT in shared memory.
// s_tw holds W64^{-n} (forward sign); inverse conjugates at compile time.
template <int SGN, bool ROWS>
__device__ __forceinline__ void fft_pass(float2* sm, const float2* s_tw, int tid) {
    const int g = tid >> 3;
    const int t = tid & 7;
#define LIDX(n) (ROWS ? (g * 65 + (n)) : ((n) * 65 + g))
    float2 v[8];
#pragma unroll
    for (int n1 = 0; n1 < 8; n1++) v[n1] = sm[LIDX(8 * n1 + t)];
    fft8<SGN>(v);
#pragma unroll
    for (int k1 = 1; k1 < 8; k1++) {
        float2 w = s_tw[(t * k1) & 63];
        if (SGN == 1) w.y = -w.y;
        v[k1] = cmul(v[k1], w);
    }
    __syncwarp();
#pragma unroll
    for (int k1 = 0; k1 < 8; k1++) sm[LIDX(8 * k1 + t)] = v[k1];
    __syncwarp();
#pragma unroll
    for (int n2 = 0; n2 < 8; n2++) v[n2] = sm[LIDX(t * 8 + n2)];
    fft8<SGN>(v);
    __syncwarp();
#pragma unroll
    for (int k2 = 0; k2 < 8; k2++) sm[LIDX(t + 8 * k2)] = v[k2];
#undef LIDX
}

// ---------------- kernel 1: forward FFT2, fp16 magnitudes, masked complex store ----------------
__global__ __launch_bounds__(512) void fwd_fft_kernel(const float* __restrict__ x,
                                                      const float* __restrict__ fbs) {
    __shared__ float2 sm[64 * 65];
    __shared__ float2 s_tw[64];
    const int plane = blockIdx.x;
    const int b = plane >> 6, i = plane & 63;
    const int tid = threadIdx.x;
    if (tid < 64) {
        float sn, cs;
        __sincosf(-6.283185307179586f * (float)tid * (1.0f / 64.0f), &sn, &cs);
        s_tw[tid] = make_float2(cs, sn);
    }
    const float* xp = x + (size_t)plane * 4096;
    for (int k = tid; k < 4096; k += 512)
        sm[(k >> 6) * 65 + (k & 63)] = make_float2(xp[k], 0.f);
    __syncthreads();
    fft_pass<-1, true>(sm, s_tw, tid);
    __syncthreads();
    fft_pass<-1, false>(sm, s_tw, tid);
    __syncthreads();
    // mask: keep complex plane iff inverse path will read it
    const int bb = (b + 32) & 63;
    const int si = (int)floorf((fbs[bb * 2 + 0] + 1.f) * 0.5f * 64.f);
    const int ei = (int)floorf((fbs[bb * 2 + 1] + 1.f) * 0.5f * 64.f);
    const int ii = (i + 32) & 63;
    const bool keep = (ii >= si && ii < ei);
    __half* mp = d_Mh + (size_t)plane * 4096;
    if (keep) {
        float2* yp = d_Y + (size_t)plane * 4096;
        for (int k = tid; k < 4096; k += 512) {
            float2 v = sm[(k >> 6) * 65 + (k & 63)];
            yp[k] = v;
            mp[k] = __float2half(sqrtf(v.x * v.x + v.y * v.y));
        }
    } else {
        for (int k = tid; k < 4096; k += 512) {
            float2 v = sm[(k >> 6) * 65 + (k & 63)];
            mp[k] = __float2half(sqrtf(v.x * v.x + v.y * v.y));
        }
    }
}

// ---------------- kernel 2: attention + log-Gabor combine -> G'[i,h,w] ----------------
__global__ __launch_bounds__(256) void attn_kernel(
    const float* __restrict__ f0, const float* __restrict__ theta,
    const float* __restrict__ sigma, const float* __restrict__ theta0,
    const float* __restrict__ w1, const float* __restrict__ b1,
    const float* __restrict__ w2, const float* __restrict__ b2) {
    __shared__ __align__(16) float s_w1[64 * 64];  // [c][o], channel-shifted
    __shared__ float s_w2[3 * 64];
    __shared__ float s_b1[64];
    __shared__ float s_b2[3];
    __shared__ float s_lf0[3], s_i2ls2[3], s_th[3], s_i2t02[3];
    const int i = blockIdx.x;
    const int tid = threadIdx.x;

    for (int k = tid; k < 4096; k += 256) {
        int c = k >> 6, o = k & 63;
        s_w1[c * 64 + o] = w1[o * 64 + ((c + 32) & 63)];
    }
    if (tid < 64) s_b1[tid] = b1[tid];
    if (tid < 192) s_w2[tid] = w2[tid];
    if (tid < 3) {
        s_b2[tid] = b2[tid];
        int ip = (i + 32) & 63;
        int idx = tid * 64 + ip;
        s_lf0[tid] = logf(f0[idx]);
        float ls = logf(sigma[idx]);
        s_i2ls2[tid] = 1.f / (2.f * ls * ls);
        s_th[tid] = theta[idx];
        float t0v = theta0[idx];
        s_i2t02[tid] = 1.f / (2.f * t0v * t0v);
    }
    __syncthreads();

    const __half* Mp = d_Mh + (size_t)i * 64 * 4096;
    const int pbeg = blockIdx.y * 1024;
    for (int p = pbeg + tid; p < pbeg + 1024; p += 256) {
        unsigned long long h2[32];
#pragma unroll
        for (int j = 0; j < 32; j++) h2[j] = pack2(s_b1[2 * j], s_b1[2 * j + 1]);
#pragma unroll 2
        for (int c = 0; c < 64; c++) {
            float m = __half2float(Mp[(size_t)c * 4096 + p]);
            unsigned long long mm;
            asm("mov.b64 %0, {%1, %1};" : "=l"(mm) : "f"(m));
            const ulonglong2* wr = (const ulonglong2*)&s_w1[c * 64];
#pragma unroll
            for (int j = 0; j < 16; j++) {
                ulonglong2 wv = wr[j];
                fma2(h2[2 * j], wv.x, mm, h2[2 * j]);
                fma2(h2[2 * j + 1], wv.y, mm, h2[2 * j + 1]);
            }
        }
        float l0 = s_b2[0], l1 = s_b2[1], l2 = s_b2[2];
#pragma unroll
        for (int j = 0; j < 32; j++) {
            float a, bq;
            unpack2(h2[j], a, bq);
            a = fmaxf(a, 0.f);
            bq = fmaxf(bq, 0.f);
            l0 = fmaf(s_w2[2 * j], a, fmaf(s_w2[2 * j + 1], bq, l0));
            l1 = fmaf(s_w2[64 + 2 * j], a, fmaf(s_w2[64 + 2 * j + 1], bq, l1));
            l2 = fmaf(s_w2[128 + 2 * j], a, fmaf(s_w2[128 + 2 * j + 1], bq, l2));
        }
        float mx = fmaxf(l0, fmaxf(l1, l2));
        float e0 = __expf(l0 - mx), e1 = __expf(l1 - mx), e2 = __expf(l2 - mx);
        float inv = 1.f / (e0 + e1 + e2);
        float aw[3] = {e0 * inv, e1 * inv, e2 * inv};
        int hh = ((p >> 6) + 32) & 63;
        int ww = ((p & 63) + 32) & 63;
        float yv_ = -1.f + 2.f * (float)hh * (1.f / 63.f);
        float xv_ = -1.f + 2.f * (float)ww * (1.f / 63.f);
        float r2 = xv_ * xv_ + yv_ * yv_ + 1e-6f;
        float lr = 0.5f * logf(r2);
        float phi = atan2f(yv_, xv_);
        float G = 0.f;
#pragma unroll
        for (int s = 0; s < 3; s++) {
            float dl = lr - s_lf0[s];
            float dp = phi - s_th[s];
            float F = __expf(-(dl * dl) * s_i2ls2[s] - (dp * dp) * s_i2t02[s]);
            G = fmaf(F, aw[s], G);
        }
        d_G[i * 4096 + p] = G;
    }
}

// ---------------- kernel 3: 3x3 spatial conv (channel-split partials) ----------------
__global__ __launch_bounds__(256) void conv_kernel(const float* __restrict__ x,
                                                   const float* __restrict__ cw) {
    __shared__ float sp[66 * 66];
    __shared__ float sw[16][9];
    const int b = blockIdx.x, cg = blockIdx.y, tid = threadIdx.x;
    const int c0 = cg * 16;
    for (int k = tid; k < 66 * 66; k += 256) sp[k] = 0.f;
    for (int k = tid; k < 144; k += 256) sw[k / 9][k % 9] = cw[c0 * 9 + k];
    float acc[16];
#pragma unroll
    for (int q = 0; q < 16; q++) acc[q] = 0.f;
    const float* xb = x + ((size_t)b * 64 + c0) * 4096;
    for (int c = 0; c < 16; c++) {
        __syncthreads();
        for (int k = tid; k < 4096; k += 256)
            sp[((k >> 6) + 1) * 66 + (k & 63) + 1] = xb[c * 4096 + k];
        __syncthreads();
#pragma unroll
        for (int q = 0; q < 16; q++) {
            int p = tid + q * 256;
            int hh = p >> 6, ww = p & 63;
            float a = acc[q];
            const float* wr = sw[c];
#pragma unroll
            for (int kh = 0; kh < 3; kh++)
#pragma unroll
                for (int kw = 0; kw < 3; kw++)
                    a = fmaf(sp[(hh + kh) * 66 + ww + kw], wr[kh * 3 + kw], a);
            acc[q] = a;
        }
    }
    float* o = d_sp4 + ((size_t)cg * 64 + b) * 4096;
#pragma unroll
    for (int q = 0; q < 16; q++) o[tid + q * 256] = acc[q];
}

// ---------------- kernel 3b: reduce 4 conv partials ----------------
__global__ __launch_bounds__(256) void reduce_kernel() {
    const int b = blockIdx.x, tid = threadIdx.x;
    const float* A = d_sp4 + (size_t)b * 4096;
    for (int k = tid; k < 4096; k += 256)
        d_sp[b * 4096 + k] = A[k] + A[64 * 4096 + k] + A[128 * 4096 + k] + A[192 * 4096 + k];
}

// ---------------- kernel 4: masked pointwise * IFFT2 * mix epilogue ----------------
__global__ __launch_bounds__(512) void inv_kernel(const float* __restrict__ fbs,
                                                  const float* __restrict__ mixp,
                                                  float* __restrict__ out) {
    __shared__ float2 sm[64 * 65];
    __shared__ float2 s_tw[64];
    const int plane = blockIdx.x;
    const int b = plane >> 6, i = plane & 63;
    const int tid = threadIdx.x;
    const float mix = mixp[0];
    const float c1 = 1.f - mix;
    const int bb = (b + 32) & 63;
    const int si = (int)floorf((fbs[bb * 2 + 0] + 1.f) * 0.5f * 64.f);
    const int ei = (int)floorf((fbs[bb * 2 + 1] + 1.f) * 0.5f * 64.f);
    const int ii = (i + 32) & 63;
    float* op = out + (size_t)plane * 4096;
    const float* sb = d_sp + (size_t)b * 4096;

    if (!(ii >= si && ii < ei)) {  // whole z-plane masked to zero
        for (int k = tid; k < 4096; k += 512)
            op[k] = c1 * sb[k];
        return;
    }

    if (tid < 64) {
        float sn, cs;
        __sincosf(-6.283185307179586f * (float)tid * (1.0f / 64.0f), &sn, &cs);
        s_tw[tid] = make_float2(cs, sn);
    }
    const float2* Yp = d_Y + (size_t)plane * 4096;
    const float* Gp = d_G + i * 4096;
    for (int k = tid; k < 4096; k += 512) {
        int hh = ((k >> 6) + 32) & 63;
        float g = (hh >= si && hh < ei) ? Gp[k] : 0.f;
        float2 y = Yp[k];
        sm[(k >> 6) * 65 + (k & 63)] = make_float2(y.x * g, y.y * g);
    }
    __syncthreads();
    fft_pass<1, true>(sm, s_tw, tid);
    __syncthreads();
    fft_pass<1, false>(sm, s_tw, tid);
    __syncthreads();
    const float scale = mix * (1.f / 4096.f);
    for (int k = tid; k < 4096; k += 512) {
        float xf = sm[(k >> 6) * 65 + (k & 63)].x;
        op[k] = fmaf(scale, xf, c1 * sb[k]);
    }
}

// ---------------- launch ----------------
extern "C" void kernel_launch(void* const* d_in, const int* in_sizes, int n_in,
                              void* d_out, int out_size) {
    const float* x      = (const float*)d_in[0];
    const float* f0     = (const float*)d_in[1];
    const float* theta  = (const float*)d_in[2];
    const float* sigma  = (const float*)d_in[3];
    const float* theta0 = (const float*)d_in[4];
    const float* fbs    = (const float*)d_in[5];
    const float* mix    = (const float*)d_in[6];
    const float* w1     = (const float*)d_in[7];
    const float* b1     = (const float*)d_in[8];
    const float* w2     = (const float*)d_in[9];
    const float* b2     = (const float*)d_in[10];
    const float* conv_w = (const float*)d_in[11];
    float* out = (float*)d_out;

    conv_kernel<<<dim3(64, 4), 256>>>(x, conv_w);
    fwd_fft_kernel<<<4096, 512>>>(x, fbs);
    attn_kernel<<<dim3(64, 4), 256>>>(f0, theta, sigma, theta0, w1, b1, w2, b2);
    reduce_kernel<<<64, 256>>>();
    inv_kernel<<<4096, 512>>>(fbs, mix, out);
}

// round 3
// speedup vs baseline: 2.2595x; 1.6377x over previous
#include <cuda_runtime.h>
#include <cuda_fp16.h>
#include <math.h>
#include <stdint.h>

// ---------------- device scratch (no allocs allowed) ----------------
__device__ __align__(16) __half d_Mh[4096ull * 4096ull];  // |FFT| magnitudes, fp16, 32MB
__device__ __align__(16) __half d_w1h[64 * 64];           // channel-shifted w1, fp16
__device__ float d_G[64 * 4096];                          // G'[i,h,w], 1MB
__device__ float d_sp4[4 * 64 * 4096];                    // conv partials, 4MB
__device__ float d_sp[64 * 4096];                         // reduced conv, 1MB

// ---------------- complex helpers ----------------
__device__ __forceinline__ float2 cmul(float2 a, float2 b) {
    return make_float2(a.x * b.x - a.y * b.y, a.x * b.y + a.y * b.x);
}
__device__ __forceinline__ float2 cadd(float2 a, float2 b) { return make_float2(a.x + b.x, a.y + b.y); }
__device__ __forceinline__ float2 csub(float2 a, float2 b) { return make_float2(a.x - b.x, a.y - b.y); }

// ---------------- MMA helpers ----------------
__device__ __forceinline__ void ldsm_x4(uint32_t (&r)[4], uint32_t addr) {
    asm volatile("ldmatrix.sync.aligned.m8n8.x4.shared.b16 {%0,%1,%2,%3}, [%4];"
                 : "=r"(r[0]), "=r"(r[1]), "=r"(r[2]), "=r"(r[3]) : "r"(addr));
}
__device__ __forceinline__ void ldsm_x2_trans(uint32_t (&r)[2], uint32_t addr) {
    asm volatile("ldmatrix.sync.aligned.m8n8.x2.trans.shared.b16 {%0,%1}, [%2];"
                 : "=r"(r[0]), "=r"(r[1]) : "r"(addr));
}
__device__ __forceinline__ void mma16816(float (&d)[4], const uint32_t (&a)[4], const uint32_t (&b)[2]) {
    asm volatile(
        "mma.sync.aligned.m16n8k16.row.col.f32.f16.f16.f32 "
        "{%0,%1,%2,%3},{%4,%5,%6,%7},{%8,%9},{%0,%1,%2,%3};"
        : "+f"(d[0]), "+f"(d[1]), "+f"(d[2]), "+f"(d[3])
        : "r"(a[0]), "r"(a[1]), "r"(a[2]), "r"(a[3]), "r"(b[0]), "r"(b[1]));
}

// 8-point DIF FFT in registers, natural-order output. SGN=-1 fwd, +1 inv.
template <int SGN>
__device__ __forceinline__ void fft8(float2 v[8]) {
    const float S = (float)SGN;
    const float C = 0.70710678118654752440f;
    float2 t0 = cadd(v[0], v[4]), t4 = csub(v[0], v[4]);
    float2 t1 = cadd(v[1], v[5]), t5 = csub(v[1], v[5]);
    float2 t2 = cadd(v[2], v[6]), t6 = csub(v[2], v[6]);
    float2 t3 = cadd(v[3], v[7]), t7 = csub(v[3], v[7]);
    t5 = cmul(t5, make_float2(C, S * C));
    t6 = make_float2(-S * t6.y, S * t6.x);
    t7 = cmul(t7, make_float2(-C, S * C));
    float2 u0 = cadd(t0, t2), u2 = csub(t0, t2);
    float2 u1 = cadd(t1, t3);
    float2 d13 = csub(t1, t3);
    float2 u3 = make_float2(-S * d13.y, S * d13.x);
    float2 u4 = cadd(t4, t6), u6 = csub(t4, t6);
    float2 u5 = cadd(t5, t7);
    float2 d57 = csub(t5, t7);
    float2 u7 = make_float2(-S * d57.y, S * d57.x);
    v[0] = cadd(u0, u1); v[4] = csub(u0, u1);
    v[2] = cadd(u2, u3); v[6] = csub(u2, u3);
    v[1] = cadd(u4, u5); v[5] = csub(u4, u5);
    v[3] = cadd(u6, u7); v[7] = csub(u6, u7);
}

// One pass (rows or cols) of a 64x64 2D FFT in shared memory.
template <int SGN, bool ROWS>
__device__ __forceinline__ void fft_pass(float2* sm, const float2* s_tw, int tid) {
    const int g = tid >> 3;
    const int t = tid & 7;
#define LIDX(n) (ROWS ? (g * 65 + (n)) : ((n) * 65 + g))
    float2 v[8];
#pragma unroll
    for (int n1 = 0; n1 < 8; n1++) v[n1] = sm[LIDX(8 * n1 + t)];
    fft8<SGN>(v);
#pragma unroll
    for (int k1 = 1; k1 < 8; k1++) {
        float2 w = s_tw[(t * k1) & 63];
        if (SGN == 1) w.y = -w.y;
        v[k1] = cmul(v[k1], w);
    }
    __syncwarp();
#pragma unroll
    for (int k1 = 0; k1 < 8; k1++) sm[LIDX(8 * k1 + t)] = v[k1];
    __syncwarp();
#pragma unroll
    for (int n2 = 0; n2 < 8; n2++) v[n2] = sm[LIDX(t * 8 + n2)];
    fft8<SGN>(v);
    __syncwarp();
#pragma unroll
    for (int k2 = 0; k2 < 8; k2++) sm[LIDX(t + 8 * k2)] = v[k2];
#undef LIDX
}

// ---------------- kernel 0: prep (w1 -> fp16 with channel roll) ----------------
__global__ __launch_bounds__(256) void prep_kernel(const float* __restrict__ w1) {
    const int tid = threadIdx.x;
    for (int k = tid; k < 4096; k += 256) {
        int o = k >> 6, c = k & 63;
        d_w1h[k] = __float2half(w1[o * 64 + ((c + 32) & 63)]);
    }
}

// ---------------- kernel 1: 3x3 spatial conv (channel-split partials) ----------------
__global__ __launch_bounds__(256) void conv_kernel(const float* __restrict__ x,
                                                   const float* __restrict__ cw) {
    __shared__ float sp[66 * 66];
    __shared__ float sw[16][9];
    const int b = blockIdx.x, cg = blockIdx.y, tid = threadIdx.x;
    const int c0 = cg * 16;
    for (int k = tid; k < 66 * 66; k += 256) sp[k] = 0.f;
    for (int k = tid; k < 144; k += 256) sw[k / 9][k % 9] = cw[c0 * 9 + k];
    float acc[16];
#pragma unroll
    for (int q = 0; q < 16; q++) acc[q] = 0.f;
    const float* xb = x + ((size_t)b * 64 + c0) * 4096;
    for (int c = 0; c < 16; c++) {
        __syncthreads();
        for (int k = tid; k < 4096; k += 256)
            sp[((k >> 6) + 1) * 66 + (k & 63) + 1] = xb[c * 4096 + k];
        __syncthreads();
#pragma unroll
        for (int q = 0; q < 16; q++) {
            int p = tid + q * 256;
            int hh = p >> 6, ww = p & 63;
            float a = acc[q];
            const float* wr = sw[c];
#pragma unroll
            for (int kh = 0; kh < 3; kh++)
#pragma unroll
                for (int kw = 0; kw < 3; kw++)
                    a = fmaf(sp[(hh + kh) * 66 + ww + kw], wr[kh * 3 + kw], a);
            acc[q] = a;
        }
    }
    float* o = d_sp4 + ((size_t)cg * 64 + b) * 4096;
#pragma unroll
    for (int q = 0; q < 16; q++) o[tid + q * 256] = acc[q];
}

// ---------------- kernel 2: forward FFT2 -> fp16 magnitudes (+ conv reduce piggyback) ----------------
__global__ __launch_bounds__(512) void fwd_fft_kernel(const float* __restrict__ x) {
    __shared__ float2 sm[64 * 65];
    __shared__ float2 s_tw[64];
    const int plane = blockIdx.x;
    const int tid = threadIdx.x;
    if (tid < 64) {
        float sn, cs;
        __sincosf(-6.283185307179586f * (float)tid * (1.0f / 64.0f), &sn, &cs);
        s_tw[tid] = make_float2(cs, sn);
    }
    const float4* xp4 = (const float4*)(x + (size_t)plane * 4096);
#pragma unroll
    for (int q = tid; q < 1024; q += 512) {
        float4 v = xp4[q];
        int r = q >> 4, c = (q & 15) * 4;
        float2* row = &sm[r * 65 + c];
        row[0] = make_float2(v.x, 0.f);
        row[1] = make_float2(v.y, 0.f);
        row[2] = make_float2(v.z, 0.f);
        row[3] = make_float2(v.w, 0.f);
    }
    __syncthreads();
    fft_pass<-1, true>(sm, s_tw, tid);
    __syncthreads();
    fft_pass<-1, false>(sm, s_tw, tid);
    __syncthreads();
    __half2* mp2 = (__half2*)(d_Mh + (size_t)plane * 4096);
#pragma unroll
    for (int q = tid; q < 2048; q += 512) {
        int r = q >> 5, c = (q & 31) * 2;
        float2 a = sm[r * 65 + c];
        float2 b = sm[r * 65 + c + 1];
        mp2[q] = __floats2half2_rn(sqrtf(a.x * a.x + a.y * a.y),
                                   sqrtf(b.x * b.x + b.y * b.y));
    }
    // piggyback: reduce conv partials (conv ran before this kernel)
    if (plane < 64) {
        const float4* A = (const float4*)(d_sp4 + (size_t)plane * 4096);
        float4* O = (float4*)(d_sp + (size_t)plane * 4096);
#pragma unroll
        for (int q = tid; q < 1024; q += 512) {
            float4 a = A[q], b = A[65536 + q], c = A[131072 + q], d = A[196608 + q];
            O[q] = make_float4(a.x + b.x + c.x + d.x, a.y + b.y + c.y + d.y,
                               a.z + b.z + c.z + d.z, a.w + b.w + c.w + d.w);
        }
    }
}

// ---------------- kernel 3: tensor-core attention + log-Gabor combine -> G'[i,h,w] ----------------
__global__ __launch_bounds__(256) void attn_kernel(
    const float* __restrict__ f0, const float* __restrict__ theta,
    const float* __restrict__ sigma, const float* __restrict__ theta0,
    const float* __restrict__ b1, const float* __restrict__ w2,
    const float* __restrict__ b2) {
    __shared__ __align__(16) __half sA[64 * 72];    // W1s [o][c], padded
    __shared__ __align__(16) __half sM[64 * 264];   // M tile [c][p] fp16; reused as H [o][p]
    __shared__ float s_w2[3 * 64];
    __shared__ float s_b1[64];
    __shared__ float s_lf0[3], s_i2ls2[3], s_th[3], s_i2t02[3], s_b2[3];
    const int i = blockIdx.x;
    const int pbeg = blockIdx.y * 256;
    const int tid = threadIdx.x;

    // load A (w1 fp16, channel-rolled) : 4096 halfs = 512 uint4
    {
        const uint4* src = (const uint4*)d_w1h;
        for (int t = tid; t < 512; t += 256) {
            int o = t >> 3, cc = (t & 7) * 8;
            *(uint4*)&sA[o * 72 + cc] = src[t];
        }
    }
    // load M tile: rows c=0..63, 256 halfs each
    for (int t = tid; t < 2048; t += 256) {
        int c = t >> 5, q = t & 31;
        uint4 v = *(const uint4*)(d_Mh + ((size_t)(i * 64 + c)) * 4096 + pbeg + q * 8);
        *(uint4*)&sM[c * 264 + q * 8] = v;
    }
    if (tid < 64) s_b1[tid] = b1[tid];
    if (tid < 192) s_w2[tid] = w2[tid];
    if (tid < 3) {
        s_b2[tid] = b2[tid];
        int ip = (i + 32) & 63;
        int idx = tid * 64 + ip;
        s_lf0[tid] = logf(f0[idx]);
        float ls = logf(sigma[idx]);
        s_i2ls2[tid] = 1.f / (2.f * ls * ls);
        s_th[tid] = theta[idx];
        float t0v = theta0[idx];
        s_i2t02[tid] = 1.f / (2.f * t0v * t0v);
    }
    __syncthreads();

    // GEMM: C[64 o][256 p] = A[64,64] x M[64,256]; 8 warps: 4 o-tiles x 2 p-halves
    const int wid = tid >> 5, lane = tid & 31;
    const int o0 = (wid & 3) << 4, pw = (wid >> 2) << 7;
    const uint32_t sA_addr = (uint32_t)__cvta_generic_to_shared(sA);
    const uint32_t sM_addr = (uint32_t)__cvta_generic_to_shared(sM);

    uint32_t a[4][4];
#pragma unroll
    for (int ks = 0; ks < 4; ks++) {
        uint32_t addr = sA_addr + (uint32_t)(((o0 + (lane & 15)) * 72 + ks * 16 + ((lane >> 4) << 3)) * 2);
        ldsm_x4(a[ks], addr);
    }
    float acc[16][4];
#pragma unroll
    for (int j = 0; j < 16; j++)
#pragma unroll
        for (int q = 0; q < 4; q++) acc[j][q] = 0.f;
#pragma unroll
    for (int j = 0; j < 16; j++) {
#pragma unroll
        for (int ks = 0; ks < 4; ks++) {
            uint32_t b[2];
            uint32_t addr = sM_addr + (uint32_t)(((ks * 16 + (lane & 15)) * 264 + pw + j * 8) * 2);
            ldsm_x2_trans(b, addr);
            mma16816(acc[j], a[ks], b);
        }
    }
    __syncthreads();  // all reads of sM done; now overwrite with H

    // relu(h + b1) -> sM (as H[o][p] fp16)
    {
        const int r0 = o0 + (lane >> 2);
        const int cbase = pw + (lane & 3) * 2;
        float b1a = s_b1[r0], b1b = s_b1[r0 + 8];
#pragma unroll
        for (int j = 0; j < 16; j++) {
            int c = cbase + j * 8;
            *(
                __half2*)&sM[r0 * 264 + c] =
                __floats2half2_rn(fmaxf(acc[j][0] + b1a, 0.f), fmaxf(acc[j][1] + b1a, 0.f));
            *(
                __half2*)&sM[(r0 + 8) * 264 + c] =
                __floats2half2_rn(fmaxf(acc[j][2] + b1b, 0.f), fmaxf(acc[j][3] + b1b, 0.f));
        }
    }
    __syncthreads();

    // layer 2 + softmax + filter; one pixel per thread
    {
        float l0 = s_b2[0], l1 = s_b2[1], l2 = s_b2[2];
#pragma unroll
        for (int o = 0; o < 64; o++) {
            float hv = __half2float(sM[o * 264 + tid]);
            l0 = fmaf(s_w2[o], hv, l0);
            l1 = fmaf(s_w2[64 + o], hv, l1);
            l2 = fmaf(s_w2[128 + o], hv, l2);
        }
        float mx = fmaxf(l0, fmaxf(l1, l2));
        float e0 = __expf(l0 - mx), e1 = __expf(l1 - mx), e2 = __expf(l2 - mx);
        float inv = 1.f / (e0 + e1 + e2);
        float aw0 = e0 * inv, aw1 = e1 * inv, aw2 = e2 * inv;
        const int p = pbeg + tid;
        int hh = ((p >> 6) + 32) & 63;
        int ww = ((p & 63) + 32) & 63;
        float yv_ = -1.f + 2.f * (float)hh * (1.f / 63.f);
        float xv_ = -1.f + 2.f * (float)ww * (1.f / 63.f);
        float r2 = xv_ * xv_ + yv_ * yv_ + 1e-6f;
        float lr = 0.5f * logf(r2);
        float phi = atan2f(yv_, xv_);
        float G = 0.f;
        float awv[3] = {aw0, aw1, aw2};
#pragma unroll
        for (int s = 0; s < 3; s++) {
            float dl = lr - s_lf0[s];
            float dp = phi - s_th[s];
            float F = __expf(-(dl * dl) * s_i2ls2[s] - (dp * dp) * s_i2t02[s]);
            G = fmaf(F, awv[s], G);
        }
        d_G[i * 4096 + p] = G;
    }
}

// ---------------- kernel 4: masked fwd-FFT + pointwise + IFFT + mix epilogue ----------------
__global__ __launch_bounds__(512) void inv_kernel(const float* __restrict__ x,
                                                  const float* __restrict__ fbs,
                                                  const float* __restrict__ mixp,
                                                  float* __restrict__ out) {
    __shared__ float2 sm[64 * 65];
    __shared__ float2 s_tw[64];
    const int plane = blockIdx.x;
    const int b = plane >> 6, i = plane & 63;
    const int tid = threadIdx.x;
    const float mix = mixp[0];
    const float c1 = 1.f - mix;
    const int bb = (b + 32) & 63;
    const int si = (int)floorf((fbs[bb * 2 + 0] + 1.f) * 0.5f * 64.f);
    const int ei = (int)floorf((fbs[bb * 2 + 1] + 1.f) * 0.5f * 64.f);
    const int ii = (i + 32) & 63;
    float4* op4 = (float4*)(out + (size_t)plane * 4096);
    const float4* sb4 = (const float4*)(d_sp + (size_t)b * 4096);

    if (!(ii >= si && ii < ei)) {  // whole z-plane masked to zero
#pragma unroll
        for (int q = tid; q < 1024; q += 512) {
            float4 s = sb4[q];
            op4[q] = make_float4(c1 * s.x, c1 * s.y, c1 * s.z, c1 * s.w);
        }
        return;
    }

    if (tid < 64) {
        float sn, cs;
        __sincosf(-6.283185307179586f * (float)tid * (1.0f / 64.0f), &sn, &cs);
        s_tw[tid] = make_float2(cs, sn);
    }
    // forward FFT of this plane (recomputed; cheaper than storing complex Y)
    const float4* xp4 = (const float4*)(x + (size_t)plane * 4096);
#pragma unroll
    for (int q = tid; q < 1024; q += 512) {
        float4 v = xp4[q];
        int r = q >> 4, c = (q & 15) * 4;
        float2* row = &sm[r * 65 + c];
        row[0] = make_float2(v.x, 0.f);
        row[1] = make_float2(v.y, 0.f);
        row[2] = make_float2(v.z, 0.f);
        row[3] = make_float2(v.w, 0.f);
    }
    __syncthreads();
    fft_pass<-1, true>(sm, s_tw, tid);
    __syncthreads();
    fft_pass<-1, false>(sm, s_tw, tid);
    __syncthreads();
    // pointwise: Z *= G * mask(h)
    const float* Gp = d_G + i * 4096;
    for (int k = tid; k < 4096; k += 512) {
        int hh = ((k >> 6) + 32) & 63;
        float g = (hh >= si && hh < ei) ? Gp[k] : 0.f;
        float2 z = sm[(k >> 6) * 65 + (k & 63)];
        sm[(k >> 6) * 65 + (k & 63)] = make_float2(z.x * g, z.y * g);
    }
    __syncthreads();
    fft_pass<1, true>(sm, s_tw, tid);
    __syncthreads();
    fft_pass<1, false>(sm, s_tw, tid);
    __syncthreads();
    const float scale = mix * (1.f / 4096.f);
#pragma unroll
    for (int q = tid; q < 1024; q += 512) {
        int r = q >> 4, c = (q & 15) * 4;
        const float2* row = &sm[r * 65 + c];
        float4 s = sb4[q];
        op4[q] = make_float4(fmaf(scale, row[0].x, c1 * s.x),
                             fmaf(scale, row[1].x, c1 * s.y),
                             fmaf(scale, row[2].x, c1 * s.z),
                             fmaf(scale, row[3].x, c1 * s.w));
    }
}

// ---------------- launch ----------------
extern "C" void kernel_launch(void* const* d_in, const int* in_sizes, int n_in,
                              void* d_out, int out_size) {
    const float* x      = (const float*)d_in[0];
    const float* f0     = (const float*)d_in[1];
    const float* theta  = (const float*)d_in[2];
    const float* sigma  = (const float*)d_in[3];
    const float* theta0 = (const float*)d_in[4];
    const float* fbs    = (const float*)d_in[5];
    const float* mix    = (const float*)d_in[6];
    const float* w1     = (const float*)d_in[7];
    const float* b1     = (const float*)d_in[8];
    const float* w2     = (const float*)d_in[9];
    const float* b2     = (const float*)d_in[10];
    const float* conv_w = (const float*)d_in[11];
    float* out = (float*)d_out;

    prep_kernel<<<1, 256>>>(w1);
    conv_kernel<<<dim3(64, 4), 256>>>(x, conv_w);
    fwd_fft_kernel<<<4096, 512>>>(x);
    attn_kernel<<<dim3(64, 16), 256>>>(f0, theta, sigma, theta0, b1, w2, b2);
    inv_kernel<<<4096, 512>>>(x, fbs, mix, out);
}

// round 4
// speedup vs baseline: 2.5785x; 1.1412x over previous
#include <cuda_runtime.h>
#include <cuda_fp16.h>
#include <math.h>
#include <stdint.h>

// ---------------- device scratch (no allocs allowed) ----------------
__device__ __align__(16) __half d_Mh[4096ull * 4096ull];  // |FFT| magnitudes, fp16, 32MB
__device__ float d_G[64 * 4096];                          // G'[i,h,w], 1MB
__device__ float d_sp4[4 * 64 * 4096];                    // conv partials, 4MB
__device__ float d_sp[64 * 4096];                         // reduced conv, 1MB

// ---------------- complex helpers ----------------
__device__ __forceinline__ float2 cmul(float2 a, float2 b) {
    return make_float2(a.x * b.x - a.y * b.y, a.x * b.y + a.y * b.x);
}
__device__ __forceinline__ float2 cadd(float2 a, float2 b) { return make_float2(a.x + b.x, a.y + b.y); }
__device__ __forceinline__ float2 csub(float2 a, float2 b) { return make_float2(a.x - b.x, a.y - b.y); }

// ---------------- MMA helpers ----------------
__device__ __forceinline__ void ldsm_x4(uint32_t (&r)[4], uint32_t addr) {
    asm volatile("ldmatrix.sync.aligned.m8n8.x4.shared.b16 {%0,%1,%2,%3}, [%4];"
                 : "=r"(r[0]), "=r"(r[1]), "=r"(r[2]), "=r"(r[3]) : "r"(addr));
}
__device__ __forceinline__ void ldsm_x2_trans(uint32_t (&r)[2], uint32_t addr) {
    asm volatile("ldmatrix.sync.aligned.m8n8.x2.trans.shared.b16 {%0,%1}, [%2];"
                 : "=r"(r[0]), "=r"(r[1]) : "r"(addr));
}
__device__ __forceinline__ void mma16816(float (&d)[4], const uint32_t (&a)[4], const uint32_t (&b)[2]) {
    asm volatile(
        "mma.sync.aligned.m16n8k16.row.col.f32.f16.f16.f32 "
        "{%0,%1,%2,%3},{%4,%5,%6,%7},{%8,%9},{%0,%1,%2,%3};"
        : "+f"(d[0]), "+f"(d[1]), "+f"(d[2]), "+f"(d[3])
        : "r"(a[0]), "r"(a[1]), "r"(a[2]), "r"(a[3]), "r"(b[0]), "r"(b[1]));
}

// ---------------- FFT smem layout ----------------
// Logical element (row r, col c) of the 64x64 plane lives at:
//   phys(r, c) = r*72 + (c ^ (r & 7))     [float2 units]
// Stride 72 (=8 mod 16 banks) + XOR-by-row makes both row-pass and
// col-pass accesses (nearly) bank-conflict-free.
#define FFT_SM_F2 (64 * 72)
__device__ __forceinline__ int fft_phys(int r, int c) { return r * 72 + (c ^ (r & 7)); }

// 8-point DIF FFT in registers, natural-order output. SGN=-1 fwd, +1 inv.
template <int SGN>
__device__ __forceinline__ void fft8(float2 v[8]) {
    const float S = (float)SGN;
    const float C = 0.70710678118654752440f;
    float2 t0 = cadd(v[0], v[4]), t4 = csub(v[0], v[4]);
    float2 t1 = cadd(v[1], v[5]), t5 = csub(v[1], v[5]);
    float2 t2 = cadd(v[2], v[6]), t6 = csub(v[2], v[6]);
    float2 t3 = cadd(v[3], v[7]), t7 = csub(v[3], v[7]);
    t5 = cmul(t5, make_float2(C, S * C));
    t6 = make_float2(-S * t6.y, S * t6.x);
    t7 = cmul(t7, make_float2(-C, S * C));
    float2 u0 = cadd(t0, t2), u2 = csub(t0, t2);
    float2 u1 = cadd(t1, t3);
    float2 d13 = csub(t1, t3);
    float2 u3 = make_float2(-S * d13.y, S * d13.x);
    float2 u4 = cadd(t4, t6), u6 = csub(t4, t6);
    float2 u5 = cadd(t5, t7);
    float2 d57 = csub(t5, t7);
    float2 u7 = make_float2(-S * d57.y, S * d57.x);
    v[0] = cadd(u0, u1); v[4] = csub(u0, u1);
    v[2] = cadd(u2, u3); v[6] = csub(u2, u3);
    v[1] = cadd(u4, u5); v[5] = csub(u4, u5);
    v[3] = cadd(u6, u7); v[7] = csub(u6, u7);
}

// One pass (rows or cols) of a 64x64 2D FFT in shared memory.
// Line g handled by 8 threads (t=0..7) of the same warp.
// Intermediate A[k1][t] stored at line-local slot 8*k1 + (t^k1) (ownership
// swizzle) so stage-2 loads are conflict-free.
template <int SGN, bool ROWS>
__device__ __forceinline__ void fft_pass(float2* sm, const float2* s_tw, int tid) {
    const int g = tid >> 3;
    const int t = tid & 7;
#define LIDX(m) (ROWS ? fft_phys(g, (m)) : fft_phys((m), g))
    float2 v[8];
#pragma unroll
    for (int n1 = 0; n1 < 8; n1++) v[n1] = sm[LIDX(8 * n1 + t)];
    fft8<SGN>(v);
#pragma unroll
    for (int k1 = 1; k1 < 8; k1++) {
        float2 w = s_tw[(t * k1) & 63];
        if (SGN == 1) w.y = -w.y;
        v[k1] = cmul(v[k1], w);
    }
    __syncwarp();
#pragma unroll
    for (int k1 = 0; k1 < 8; k1++) sm[LIDX(8 * k1 + (t ^ k1))] = v[k1];
    __syncwarp();
#pragma unroll
    for (int n2 = 0; n2 < 8; n2++) v[n2] = sm[LIDX(8 * t + (n2 ^ t))];
    fft8<SGN>(v);
    __syncwarp();
#pragma unroll
    for (int k2 = 0; k2 < 8; k2++) sm[LIDX(t + 8 * k2)] = v[k2];
#undef LIDX
}

// ---------------- kernel 1: 3x3 spatial conv (channel-split partials) ----------------
__global__ __launch_bounds__(256) void conv_kernel(const float* __restrict__ x,
                                                   const float* __restrict__ cw) {
    __shared__ float sp[66 * 66];
    __shared__ float sw[16][9];
    const int b = blockIdx.x, cg = blockIdx.y, tid = threadIdx.x;
    const int c0 = cg * 16;
    for (int k = tid; k < 66 * 66; k += 256) sp[k] = 0.f;
    for (int k = tid; k < 144; k += 256) sw[k / 9][k % 9] = cw[c0 * 9 + k];
    float acc[16];
#pragma unroll
    for (int q = 0; q < 16; q++) acc[q] = 0.f;
    const float* xb = x + ((size_t)b * 64 + c0) * 4096;
    for (int c = 0; c < 16; c++) {
        __syncthreads();
        for (int k = tid; k < 4096; k += 256)
            sp[((k >> 6) + 1) * 66 + (k & 63) + 1] = xb[c * 4096 + k];
        __syncthreads();
#pragma unroll
        for (int q = 0; q < 16; q++) {
            int p = tid + q * 256;
            int hh = p >> 6, ww = p & 63;
            float a = acc[q];
            const float* wr = sw[c];
#pragma unroll
            for (int kh = 0; kh < 3; kh++)
#pragma unroll
                for (int kw = 0; kw < 3; kw++)
                    a = fmaf(sp[(hh + kh) * 66 + ww + kw], wr[kh * 3 + kw], a);
            acc[q] = a;
        }
    }
    float* o = d_sp4 + ((size_t)cg * 64 + b) * 4096;
#pragma unroll
    for (int q = 0; q < 16; q++) o[tid + q * 256] = acc[q];
}

// ---------------- kernel 2: forward FFT2 -> fp16 magnitudes (+ conv reduce piggyback) ----------------
__global__ __launch_bounds__(512) void fwd_fft_kernel(const float* __restrict__ x) {
    __shared__ float2 sm[FFT_SM_F2];
    __shared__ float2 s_tw[64];
    const int plane = blockIdx.x;
    const int tid = threadIdx.x;
    if (tid < 64) {
        float sn, cs;
        __sincosf(-6.283185307179586f * (float)tid * (1.0f / 64.0f), &sn, &cs);
        s_tw[tid] = make_float2(cs, sn);
    }
    const float4* xp4 = (const float4*)(x + (size_t)plane * 4096);
#pragma unroll
    for (int q = tid; q < 1024; q += 512) {
        float4 v = xp4[q];
        int r = q >> 4, c = (q & 15) * 4;
        sm[fft_phys(r, c + 0)] = make_float2(v.x, 0.f);
        sm[fft_phys(r, c + 1)] = make_float2(v.y, 0.f);
        sm[fft_phys(r, c + 2)] = make_float2(v.z, 0.f);
        sm[fft_phys(r, c + 3)] = make_float2(v.w, 0.f);
    }
    __syncthreads();
    fft_pass<-1, true>(sm, s_tw, tid);
    __syncthreads();
    fft_pass<-1, false>(sm, s_tw, tid);
    __syncthreads();
    __half2* mp2 = (__half2*)(d_Mh + (size_t)plane * 4096);
#pragma unroll
    for (int q = tid; q < 2048; q += 512) {
        int r = q >> 5, c = (q & 31) * 2;
        float2 a = sm[fft_phys(r, c)];
        float2 b = sm[fft_phys(r, c + 1)];
        mp2[q] = __floats2half2_rn(sqrtf(a.x * a.x + a.y * a.y),
                                   sqrtf(b.x * b.x + b.y * b.y));
    }
    // piggyback: reduce conv partials (conv ran before this kernel)
    if (plane < 64) {
        const float4* A = (const float4*)(d_sp4 + (size_t)plane * 4096);
        float4* O = (float4*)(d_sp + (size_t)plane * 4096);
#pragma unroll
        for (int q = tid; q < 1024; q += 512) {
            float4 a = A[q], b = A[65536 + q], c = A[131072 + q], d = A[196608 + q];
            O[q] = make_float4(a.x + b.x + c.x + d.x, a.y + b.y + c.y + d.y,
                               a.z + b.z + c.z + d.z, a.w + b.w + c.w + d.w);
        }
    }
}

// ---------------- kernel 3: tensor-core attention + log-Gabor combine -> G'[i,h,w] ----------------
__global__ __launch_bounds__(256) void attn_kernel(
    const float* __restrict__ f0, const float* __restrict__ theta,
    const float* __restrict__ sigma, const float* __restrict__ theta0,
    const float* __restrict__ w1, const float* __restrict__ b1,
    const float* __restrict__ w2, const float* __restrict__ b2) {
    __shared__ __align__(16) __half sA[64 * 72];    // W1s [o][c], padded
    __shared__ __align__(16) __half sM[64 * 264];   // M tile [c][p] fp16; reused as H [o][p]
    __shared__ float s_w2[3 * 64];
    __shared__ float s_b1[64];
    __shared__ float s_lf0[3], s_i2ls2[3], s_th[3], s_i2t02[3], s_b2[3];
    const int i = blockIdx.x;
    const int pbeg = blockIdx.y * 256;
    const int tid = threadIdx.x;

    // load A = w1 (channel-rolled by 32) as fp16
    for (int k = tid; k < 4096; k += 256) {
        int o = k >> 6, c = k & 63;
        sA[o * 72 + c] = __float2half(w1[o * 64 + ((c + 32) & 63)]);
    }
    // load M tile: rows c=0..63, 256 halfs each
    for (int t = tid; t < 2048; t += 256) {
        int c = t >> 5, q = t & 31;
        uint4 v = *(const uint4*)(d_Mh + ((size_t)(i * 64 + c)) * 4096 + pbeg + q * 8);
        *(uint4*)&sM[c * 264 + q * 8] = v;
    }
    if (tid < 64) s_b1[tid] = b1[tid];
    if (tid < 192) s_w2[tid] = w2[tid];
    if (tid < 3) {
        s_b2[tid] = b2[tid];
        int ip = (i + 32) & 63;
        int idx = tid * 64 + ip;
        s_lf0[tid] = logf(f0[idx]);
        float ls = logf(sigma[idx]);
        s_i2ls2[tid] = 1.f / (2.f * ls * ls);
        s_th[tid] = theta[idx];
        float t0v = theta0[idx];
        s_i2t02[tid] = 1.f / (2.f * t0v * t0v);
    }
    __syncthreads();

    // GEMM: C[64 o][256 p] = A[64,64] x M[64,256]; 8 warps: 4 o-tiles x 2 p-halves
    const int wid = tid >> 5, lane = tid & 31;
    const int o0 = (wid & 3) << 4, pw = (wid >> 2) << 7;
    const uint32_t sA_addr = (uint32_t)__cvta_generic_to_shared(sA);
    const uint32_t sM_addr = (uint32_t)__cvta_generic_to_shared(sM);

    uint32_t a[4][4];
#pragma unroll
    for (int ks = 0; ks < 4; ks++) {
        uint32_t addr = sA_addr + (uint32_t)(((o0 + (lane & 15)) * 72 + ks * 16 + ((lane >> 4) << 3)) * 2);
        ldsm_x4(a[ks], addr);
    }
    float acc[16][4];
#pragma unroll
    for (int j = 0; j < 16; j++)
#pragma unroll
        for (int q = 0; q < 4; q++) acc[j][q] = 0.f;
#pragma unroll
    for (int j = 0; j < 16; j++) {
#pragma unroll
        for (int ks = 0; ks < 4; ks++) {
            uint32_t b[2];
            uint32_t addr = sM_addr + (uint32_t)(((ks * 16 + (lane & 15)) * 264 + pw + j * 8) * 2);
            ldsm_x2_trans(b, addr);
            mma16816(acc[j], a[ks], b);
        }
    }
    __syncthreads();  // all reads of sM done; now overwrite with H

    // relu(h + b1) -> sM (as H[o][p] fp16)
    {
        const int r0 = o0 + (lane >> 2);
        const int cbase = pw + (lane & 3) * 2;
        float b1a = s_b1[r0], b1b = s_b1[r0 + 8];
#pragma unroll
        for (int j = 0; j < 16; j++) {
            int c = cbase + j * 8;
            *(__half2*)&sM[r0 * 264 + c] =
                __floats2half2_rn(fmaxf(acc[j][0] + b1a, 0.f), fmaxf(acc[j][1] + b1a, 0.f));
            *(__half2*)&sM[(r0 + 8) * 264 + c] =
                __floats2half2_rn(fmaxf(acc[j][2] + b1b, 0.f), fmaxf(acc[j][3] + b1b, 0.f));
        }
    }
    __syncthreads();

    // layer 2 + softmax + filter; one pixel per thread
    {
        float l0 = s_b2[0], l1 = s_b2[1], l2 = s_b2[2];
#pragma unroll
        for (int o = 0; o < 64; o++) {
            float hv = __half2float(sM[o * 264 + tid]);
            l0 = fmaf(s_w2[o], hv, l0);
            l1 = fmaf(s_w2[64 + o], hv, l1);
            l2 = fmaf(s_w2[128 + o], hv, l2);
        }
        float mx = fmaxf(l0, fmaxf(l1, l2));
        float e0 = __expf(l0 - mx), e1 = __expf(l1 - mx), e2 = __expf(l2 - mx);
        float inv = 1.f / (e0 + e1 + e2);
        const int p = pbeg + tid;
        int hh = ((p >> 6) + 32) & 63;
        int ww = ((p & 63) + 32) & 63;
        float yv_ = -1.f + 2.f * (float)hh * (1.f / 63.f);
        float xv_ = -1.f + 2.f * (float)ww * (1.f / 63.f);
        float r2 = xv_ * xv_ + yv_ * yv_ + 1e-6f;
        float lr = 0.5f * logf(r2);
        float phi = atan2f(yv_, xv_);
        float G = 0.f;
        float awv[3] = {e0 * inv, e1 * inv, e2 * inv};
#pragma unroll
        for (int s = 0; s < 3; s++) {
            float dl = lr - s_lf0[s];
            float dp = phi - s_th[s];
            float F = __expf(-(dl * dl) * s_i2ls2[s] - (dp * dp) * s_i2t02[s]);
            G = fmaf(F, awv[s], G);
        }
        d_G[i * 4096 + p] = G;
    }
}

// ---------------- kernel 4: masked fwd-FFT + pointwise + IFFT + mix epilogue ----------------
__global__ __launch_bounds__(512) void inv_kernel(const float* __restrict__ x,
                                                  const float* __restrict__ fbs,
                                                  const float* __restrict__ mixp,
                                                  float* __restrict__ out) {
    __shared__ float2 sm[FFT_SM_F2];
    __shared__ float2 s_tw[64];
    const int plane = blockIdx.x;
    const int b = plane >> 6, i = plane & 63;
    const int tid = threadIdx.x;
    const float mix = mixp[0];
    const float c1 = 1.f - mix;
    const int bb = (b + 32) & 63;
    const int si = (int)floorf((fbs[bb * 2 + 0] + 1.f) * 0.5f * 64.f);
    const int ei = (int)floorf((fbs[bb * 2 + 1] + 1.f) * 0.5f * 64.f);
    const int ii = (i + 32) & 63;
    float4* op4 = (float4*)(out + (size_t)plane * 4096);
    const float4* sb4 = (const float4*)(d_sp + (size_t)b * 4096);

    if (!(ii >= si && ii < ei)) {  // whole z-plane masked to zero
#pragma unroll
        for (int q = tid; q < 1024; q += 512) {
            float4 s = sb4[q];
            op4[q] = make_float4(c1 * s.x, c1 * s.y, c1 * s.z, c1 * s.w);
        }
        return;
    }

    if (tid < 64) {
        float sn, cs;
        __sincosf(-6.283185307179586f * (float)tid * (1.0f / 64.0f), &sn, &cs);
        s_tw[tid] = make_float2(cs, sn);
    }
    // forward FFT of this plane (recomputed; cheaper than storing complex Y)
    const float4* xp4 = (const float4*)(x + (size_t)plane * 4096);
#pragma unroll
    for (int q = tid; q < 1024; q += 512) {
        float4 v = xp4[q];
        int r = q >> 4, c = (q & 15) * 4;
        sm[fft_phys(r, c + 0)] = make_float2(v.x, 0.f);
        sm[fft_phys(r, c + 1)] = make_float2(v.y, 0.f);
        sm[fft_phys(r, c + 2)] = make_float2(v.z, 0.f);
        sm[fft_phys(r, c + 3)] = make_float2(v.w, 0.f);
    }
    __syncthreads();
    fft_pass<-1, true>(sm, s_tw, tid);
    __syncthreads();
    fft_pass<-1, false>(sm, s_tw, tid);
    __syncthreads();
    // pointwise: Z *= G * mask(h)
    const float* Gp = d_G + i * 4096;
    for (int k = tid; k < 4096; k += 512) {
        int r = k >> 6, c = k & 63;
        int hh = (r + 32) & 63;
        float g = (hh >= si && hh < ei) ? Gp[k] : 0.f;
        float2 z = sm[fft_phys(r, c)];
        sm[fft_phys(r, c)] = make_float2(z.x * g, z.y * g);
    }
    __syncthreads();
    fft_pass<1, true>(sm, s_tw, tid);
    __syncthreads();
    fft_pass<1, false>(sm, s_tw, tid);
    __syncthreads();
    const float scale = mix * (1.f / 4096.f);
#pragma unroll
    for (int q = tid; q < 1024; q += 512) {
        int r = q >> 4, c = (q & 15) * 4;
        float4 s = sb4[q];
        op4[q] = make_float4(fmaf(scale, sm[fft_phys(r, c + 0)].x, c1 * s.x),
                             fmaf(scale, sm[fft_phys(r, c + 1)].x, c1 * s.y),
                             fmaf(scale, sm[fft_phys(r, c + 2)].x, c1 * s.z),
                             fmaf(scale, sm[fft_phys(r, c + 3)].x, c1 * s.w));
    }
}

// ---------------- launch ----------------
extern "C" void kernel_launch(void* const* d_in, const int* in_sizes, int n_in,
                              void* d_out, int out_size) {
    const float* x      = (const float*)d_in[0];
    const float* f0     = (const float*)d_in[1];
    const float* theta  = (const float*)d_in[2];
    const float* sigma  = (const float*)d_in[3];
    const float* theta0 = (const float*)d_in[4];
    const float* fbs    = (const float*)d_in[5];
    const float* mix    = (const float*)d_in[6];
    const float* w1     = (const float*)d_in[7];
    const float* b1     = (const float*)d_in[8];
    const float* w2     = (const float*)d_in[9];
    const float* b2     = (const float*)d_in[10];
    const float* conv_w = (const float*)d_in[11];
    float* out = (float*)d_out;

    conv_kernel<<<dim3(64, 4), 256>>>(x, conv_w);
    fwd_fft_kernel<<<4096, 512>>>(x);
    attn_kernel<<<dim3(64, 16), 256>>>(f0, theta, sigma, theta0, w1, b1, w2, b2);
    inv_kernel<<<4096, 512>>>(x, fbs, mix, out);
}

// round 5
// speedup vs baseline: 2.7784x; 1.0775x over previous
#include <cuda_runtime.h>
#include <cuda_fp16.h>
#include <math.h>
#include <stdint.h>

// ---------------- device scratch (no allocs allowed) ----------------
__device__ __align__(16) __half d_Mh[4096ull * 4096ull];  // |FFT| magnitudes, fp16, 32MB
__device__ float d_G[64 * 4096];                          // G'[i,h,w], 1MB
__device__ float d_sp4[4 * 64 * 4096];                    // conv partials, 4MB
__device__ float d_sp[64 * 4096];                         // reduced conv, 1MB

// ---------------- complex helpers ----------------
__device__ __forceinline__ float2 cmul(float2 a, float2 b) {
    return make_float2(a.x * b.x - a.y * b.y, a.x * b.y + a.y * b.x);
}
__device__ __forceinline__ float2 cadd(float2 a, float2 b) { return make_float2(a.x + b.x, a.y + b.y); }
__device__ __forceinline__ float2 csub(float2 a, float2 b) { return make_float2(a.x - b.x, a.y - b.y); }

// ---------------- MMA helpers ----------------
__device__ __forceinline__ void ldsm_x4(uint32_t (&r)[4], uint32_t addr) {
    asm volatile("ldmatrix.sync.aligned.m8n8.x4.shared.b16 {%0,%1,%2,%3}, [%4];"
                 : "=r"(r[0]), "=r"(r[1]), "=r"(r[2]), "=r"(r[3]) : "r"(addr));
}
__device__ __forceinline__ void ldsm_x2_trans(uint32_t (&r)[2], uint32_t addr) {
    asm volatile("ldmatrix.sync.aligned.m8n8.x2.trans.shared.b16 {%0,%1}, [%2];"
                 : "=r"(r[0]), "=r"(r[1]) : "r"(addr));
}
__device__ __forceinline__ void mma16816(float (&d)[4], const uint32_t (&a)[4], const uint32_t (&b)[2]) {
    asm volatile(
        "mma.sync.aligned.m16n8k16.row.col.f32.f16.f16.f32 "
        "{%0,%1,%2,%3},{%4,%5,%6,%7},{%8,%9},{%0,%1,%2,%3};"
        : "+f"(d[0]), "+f"(d[1]), "+f"(d[2]), "+f"(d[3])
        : "r"(a[0]), "r"(a[1]), "r"(a[2]), "r"(a[3]), "r"(b[0]), "r"(b[1]));
}

// ---------------- FFT smem layout ----------------
// phys(r, c) = r*72 + (c ^ (r & 7))   [float2 units]; conflict-minimized.
#define FFT_SM_F2 (64 * 72)
__device__ __forceinline__ int fft_phys(int r, int c) { return r * 72 + (c ^ (r & 7)); }

// 8-point DIF FFT in registers, natural-order output. SGN=-1 fwd, +1 inv.
template <int SGN>
__device__ __forceinline__ void fft8(float2 v[8]) {
    const float S = (float)SGN;
    const float C = 0.70710678118654752440f;
    float2 t0 = cadd(v[0], v[4]), t4 = csub(v[0], v[4]);
    float2 t1 = cadd(v[1], v[5]), t5 = csub(v[1], v[5]);
    float2 t2 = cadd(v[2], v[6]), t6 = csub(v[2], v[6]);
    float2 t3 = cadd(v[3], v[7]), t7 = csub(v[3], v[7]);
    t5 = cmul(t5, make_float2(C, S * C));
    t6 = make_float2(-S * t6.y, S * t6.x);
    t7 = cmul(t7, make_float2(-C, S * C));
    float2 u0 = cadd(t0, t2), u2 = csub(t0, t2);
    float2 u1 = cadd(t1, t3);
    float2 d13 = csub(t1, t3);
    float2 u3 = make_float2(-S * d13.y, S * d13.x);
    float2 u4 = cadd(t4, t6), u6 = csub(t4, t6);
    float2 u5 = cadd(t5, t7);
    float2 d57 = csub(t5, t7);
    float2 u7 = make_float2(-S * d57.y, S * d57.x);
    v[0] = cadd(u0, u1); v[4] = csub(u0, u1);
    v[2] = cadd(u2, u3); v[6] = csub(u2, u3);
    v[1] = cadd(u4, u5); v[5] = csub(u4, u5);
    v[3] = cadd(u6, u7); v[7] = csub(u6, u7);
}

// One pass (rows or cols) of a 64x64 2D FFT in shared memory.
template <int SGN, bool ROWS>
__device__ __forceinline__ void fft_pass(float2* sm, const float2* s_tw, int tid) {
    const int g = tid >> 3;
    const int t = tid & 7;
#define LIDX(m) (ROWS ? fft_phys(g, (m)) : fft_phys((m), g))
    float2 v[8];
#pragma unroll
    for (int n1 = 0; n1 < 8; n1++) v[n1] = sm[LIDX(8 * n1 + t)];
    fft8<SGN>(v);
#pragma unroll
    for (int k1 = 1; k1 < 8; k1++) {
        float2 w = s_tw[(t * k1) & 63];
        if (SGN == 1) w.y = -w.y;
        v[k1] = cmul(v[k1], w);
    }
    __syncwarp();
#pragma unroll
    for (int k1 = 0; k1 < 8; k1++) sm[LIDX(8 * k1 + (t ^ k1))] = v[k1];
    __syncwarp();
#pragma unroll
    for (int n2 = 0; n2 < 8; n2++) v[n2] = sm[LIDX(8 * t + (n2 ^ t))];
    fft8<SGN>(v);
    __syncwarp();
#pragma unroll
    for (int k2 = 0; k2 < 8; k2++) sm[LIDX(t + 8 * k2)] = v[k2];
#undef LIDX
}

// ---------------- kernel 1: 3x3 spatial conv (channel-split partials) ----------------
__global__ __launch_bounds__(256) void conv_kernel(const float* __restrict__ x,
                                                   const float* __restrict__ cw) {
    __shared__ float sp[66 * 66];
    __shared__ float sw[16][9];
    const int b = blockIdx.x, cg = blockIdx.y, tid = threadIdx.x;
    const int c0 = cg * 16;
    for (int k = tid; k < 66 * 66; k += 256) sp[k] = 0.f;
    for (int k = tid; k < 144; k += 256) sw[k / 9][k % 9] = cw[c0 * 9 + k];
    float acc[16];
#pragma unroll
    for (int q = 0; q < 16; q++) acc[q] = 0.f;
    const float* xb = x + ((size_t)b * 64 + c0) * 4096;
    for (int c = 0; c < 16; c++) {
        __syncthreads();
        for (int k = tid; k < 4096; k += 256)
            sp[((k >> 6) + 1) * 66 + (k & 63) + 1] = xb[c * 4096 + k];
        __syncthreads();
#pragma unroll
        for (int q = 0; q < 16; q++) {
            int p = tid + q * 256;
            int hh = p >> 6, ww = p & 63;
            float a = acc[q];
            const float* wr = sw[c];
#pragma unroll
            for (int kh = 0; kh < 3; kh++)
#pragma unroll
                for (int kw = 0; kw < 3; kw++)
                    a = fmaf(sp[(hh + kh) * 66 + ww + kw], wr[kh * 3 + kw], a);
            acc[q] = a;
        }
    }
    float* o = d_sp4 + ((size_t)cg * 64 + b) * 4096;
#pragma unroll
    for (int q = 0; q < 16; q++) o[tid + q * 256] = acc[q];
}

// ---------------- kernel 2: forward FFT2 -> fp16 magnitudes (+ conv reduce piggyback) ----------------
__global__ __launch_bounds__(512, 2) void fwd_fft_kernel(const float* __restrict__ x) {
    __shared__ float2 sm[FFT_SM_F2];
    __shared__ float2 s_tw[64];
    const int plane = blockIdx.x;
    const int tid = threadIdx.x;
    if (tid < 64) {
        float sn, cs;
        __sincosf(-6.283185307179586f * (float)tid * (1.0f / 64.0f), &sn, &cs);
        s_tw[tid] = make_float2(cs, sn);
    }
    const float4* xp4 = (const float4*)(x + (size_t)plane * 4096);
#pragma unroll
    for (int q = tid; q < 1024; q += 512) {
        float4 v = xp4[q];
        int r = q >> 4, c = (q & 15) * 4;
        sm[fft_phys(r, c + 0)] = make_float2(v.x, 0.f);
        sm[fft_phys(r, c + 1)] = make_float2(v.y, 0.f);
        sm[fft_phys(r, c + 2)] = make_float2(v.z, 0.f);
        sm[fft_phys(r, c + 3)] = make_float2(v.w, 0.f);
    }
    __syncthreads();
    fft_pass<-1, true>(sm, s_tw, tid);
    __syncthreads();
    fft_pass<-1, false>(sm, s_tw, tid);
    __syncthreads();
    __half2* mp2 = (__half2*)(d_Mh + (size_t)plane * 4096);
#pragma unroll
    for (int q = tid; q < 2048; q += 512) {
        int r = q >> 5, c = (q & 31) * 2;
        float2 a = sm[fft_phys(r, c)];
        float2 b = sm[fft_phys(r, c + 1)];
        mp2[q] = __floats2half2_rn(sqrtf(a.x * a.x + a.y * a.y),
                                   sqrtf(b.x * b.x + b.y * b.y));
    }
    // piggyback: reduce conv partials (conv ran before this kernel)
    if (plane < 64) {
        const float4* A = (const float4*)(d_sp4 + (size_t)plane * 4096);
        float4* O = (float4*)(d_sp + (size_t)plane * 4096);
#pragma unroll
        for (int q = tid; q < 1024; q += 512) {
            float4 a = A[q], b = A[65536 + q], c = A[131072 + q], d = A[196608 + q];
            O[q] = make_float4(a.x + b.x + c.x + d.x, a.y + b.y + c.y + d.y,
                               a.z + b.z + c.z + d.z, a.w + b.w + c.w + d.w);
        }
    }
}

// ---------------- kernel 3: tensor-core attention + log-Gabor combine -> G'[i,h,w] ----------------
__global__ __launch_bounds__(256, 2) void attn_kernel(
    const float* __restrict__ f0, const float* __restrict__ theta,
    const float* __restrict__ sigma, const float* __restrict__ theta0,
    const float* __restrict__ w1, const float* __restrict__ b1,
    const float* __restrict__ w2, const float* __restrict__ b2) {
    __shared__ __align__(16) __half sA[64 * 72];    // W1s [o][c], padded
    __shared__ __align__(16) __half sM[64 * 264];   // M tile [c][p] fp16; reused as H [o][p]
    __shared__ float s_w2[3 * 64];
    __shared__ float s_b1[64];
    __shared__ float s_lf0[3], s_i2ls2[3], s_th[3], s_i2t02[3], s_b2[3];
    const int i = blockIdx.x;
    const int pbeg = blockIdx.y * 256;
    const int tid = threadIdx.x;

    // load A = w1 (channel-rolled by 32) as fp16
    for (int k = tid; k < 4096; k += 256) {
        int o = k >> 6, c = k & 63;
        sA[o * 72 + c] = __float2half(w1[o * 64 + ((c + 32) & 63)]);
    }
    // load M tile: rows c=0..63, 256 halfs each
    for (int t = tid; t < 2048; t += 256) {
        int c = t >> 5, q = t & 31;
        uint4 v = *(const uint4*)(d_Mh + ((size_t)(i * 64 + c)) * 4096 + pbeg + q * 8);
        *(uint4*)&sM[c * 264 + q * 8] = v;
    }
    if (tid < 64) s_b1[tid] = b1[tid];
    if (tid < 192) s_w2[tid] = w2[tid];
    if (tid < 3) {
        s_b2[tid] = b2[tid];
        int ip = (i + 32) & 63;
        int idx = tid * 64 + ip;
        s_lf0[tid] = logf(f0[idx]);
        float ls = logf(sigma[idx]);
        s_i2ls2[tid] = 1.f / (2.f * ls * ls);
        s_th[tid] = theta[idx];
        float t0v = theta0[idx];
        s_i2t02[tid] = 1.f / (2.f * t0v * t0v);
    }
    __syncthreads();

    // GEMM: C[64 o][256 p] = A[64,64] x M[64,256]; 8 warps: 4 o-tiles x 2 p-halves
    const int wid = tid >> 5, lane = tid & 31;
    const int o0 = (wid & 3) << 4, pw = (wid >> 2) << 7;
    const uint32_t sA_addr = (uint32_t)__cvta_generic_to_shared(sA);
    const uint32_t sM_addr = (uint32_t)__cvta_generic_to_shared(sM);

    uint32_t a[4][4];
#pragma unroll
    for (int ks = 0; ks < 4; ks++) {
        uint32_t addr = sA_addr + (uint32_t)(((o0 + (lane & 15)) * 72 + ks * 16 + ((lane >> 4) << 3)) * 2);
        ldsm_x4(a[ks], addr);
    }
    float acc[16][4];
#pragma unroll
    for (int j = 0; j < 16; j++)
#pragma unroll
        for (int q = 0; q < 4; q++) acc[j][q] = 0.f;
#pragma unroll
    for (int j = 0; j < 16; j++) {
#pragma unroll
        for (int ks = 0; ks < 4; ks++) {
            uint32_t b[2];
            uint32_t addr = sM_addr + (uint32_t)(((ks * 16 + (lane & 15)) * 264 + pw + j * 8) * 2);
            ldsm_x2_trans(b, addr);
            mma16816(acc[j], a[ks], b);
        }
    }
    __syncthreads();  // all reads of sM done; now overwrite with H

    // relu(h + b1) -> sM (as H[o][p] fp16)
    {
        const int r0 = o0 + (lane >> 2);
        const int cbase = pw + (lane & 3) * 2;
        float b1a = s_b1[r0], b1b = s_b1[r0 + 8];
#pragma unroll
        for (int j = 0; j < 16; j++) {
            int c = cbase + j * 8;
            *(__half2*)&sM[r0 * 264 + c] =
                __floats2half2_rn(fmaxf(acc[j][0] + b1a, 0.f), fmaxf(acc[j][1] + b1a, 0.f));
            *(__half2*)&sM[(r0 + 8) * 264 + c] =
                __floats2half2_rn(fmaxf(acc[j][2] + b1b, 0.f), fmaxf(acc[j][3] + b1b, 0.f));
        }
    }
    __syncthreads();

    // layer 2 + softmax + filter; one pixel per thread
    {
        float l0 = s_b2[0], l1 = s_b2[1], l2 = s_b2[2];
#pragma unroll
        for (int o = 0; o < 64; o++) {
            float hv = __half2float(sM[o * 264 + tid]);
            l0 = fmaf(s_w2[o], hv, l0);
            l1 = fmaf(s_w2[64 + o], hv, l1);
            l2 = fmaf(s_w2[128 + o], hv, l2);
        }
        float mx = fmaxf(l0, fmaxf(l1, l2));
        float e0 = __expf(l0 - mx), e1 = __expf(l1 - mx), e2 = __expf(l2 - mx);
        float inv = 1.f / (e0 + e1 + e2);
        const int p = pbeg + tid;
        int hh = ((p >> 6) + 32) & 63;
        int ww = ((p & 63) + 32) & 63;
        float yv_ = -1.f + 2.f * (float)hh * (1.f / 63.f);
        float xv_ = -1.f + 2.f * (float)ww * (1.f / 63.f);
        float r2 = xv_ * xv_ + yv_ * yv_ + 1e-6f;
        float lr = 0.5f * logf(r2);
        float phi = atan2f(yv_, xv_);
        float G = 0.f;
        float awv[3] = {e0 * inv, e1 * inv, e2 * inv};
#pragma unroll
        for (int s = 0; s < 3; s++) {
            float dl = lr - s_lf0[s];
            float dp = phi - s_th[s];
            float F = __expf(-(dl * dl) * s_i2ls2[s] - (dp * dp) * s_i2t02[s]);
            G = fmaf(F, awv[s], G);
        }
        d_G[i * 4096 + p] = G;
    }
}

// ---------------- kernel 4: masked fwd-FFT + pointwise + IFFT + mix epilogue ----------------
__global__ __launch_bounds__(512, 2) void inv_kernel(const float* __restrict__ x,
                                                     const float* __restrict__ fbs,
                                                     const float* __restrict__ mixp,
                                                     float* __restrict__ out) {
    __shared__ float2 sm[FFT_SM_F2];
    __shared__ float2 s_tw[64];
    const int plane = blockIdx.x;
    const int b = plane >> 6, i = plane & 63;
    const int tid = threadIdx.x;
    const float mix = mixp[0];
    const float c1 = 1.f - mix;
    const int bb = (b + 32) & 63;
    const int si = (int)floorf((fbs[bb * 2 + 0] + 1.f) * 0.5f * 64.f);
    const int ei = (int)floorf((fbs[bb * 2 + 1] + 1.f) * 0.5f * 64.f);
    const int ii = (i + 32) & 63;
    float4* op4 = (float4*)(out + (size_t)plane * 4096);
    const float4* sb4 = (const float4*)(d_sp + (size_t)b * 4096);

    if (!(ii >= si && ii < ei)) {  // whole z-plane masked to zero
#pragma unroll
        for (int q = tid; q < 1024; q += 512) {
            float4 s = sb4[q];
            op4[q] = make_float4(c1 * s.x, c1 * s.y, c1 * s.z, c1 * s.w);
        }
        return;
    }

    if (tid < 64) {
        float sn, cs;
        __sincosf(-6.283185307179586f * (float)tid * (1.0f / 64.0f), &sn, &cs);
        s_tw[tid] = make_float2(cs, sn);
    }
    // forward FFT of this plane (recomputed; cheaper than storing complex Y)
    const float4* xp4 = (const float4*)(x + (size_t)plane * 4096);
#pragma unroll
    for (int q = tid; q < 1024; q += 512) {
        float4 v = xp4[q];
        int r = q >> 4, c = (q & 15) * 4;
        sm[fft_phys(r, c + 0)] = make_float2(v.x, 0.f);
        sm[fft_phys(r, c + 1)] = make_float2(v.y, 0.f);
        sm[fft_phys(r, c + 2)] = make_float2(v.z, 0.f);
        sm[fft_phys(r, c + 3)] = make_float2(v.w, 0.f);
    }
    __syncthreads();
    fft_pass<-1, true>(sm, s_tw, tid);
    __syncthreads();
    fft_pass<-1, false>(sm, s_tw, tid);
    __syncthreads();
    // pointwise: Z *= G * mask(h)
    const float* Gp = d_G + i * 4096;
    for (int k = tid; k < 4096; k += 512) {
        int r = k >> 6, c = k & 63;
        int hh = (r + 32) & 63;
        float g = (hh >= si && hh < ei) ? Gp[k] : 0.f;
        float2 z = sm[fft_phys(r, c)];
        sm[fft_phys(r, c)] = make_float2(z.x * g, z.y * g);
    }
    __syncthreads();
    fft_pass<1, true>(sm, s_tw, tid);
    __syncthreads();
    fft_pass<1, false>(sm, s_tw, tid);
    __syncthreads();
    const float scale = mix * (1.f / 4096.f);
#pragma unroll
    for (int q = tid; q < 1024; q += 512) {
        int r = q >> 4, c = (q & 15) * 4;
        float4 s = sb4[q];
        op4[q] = make_float4(fmaf(scale, sm[fft_phys(r, c + 0)].x, c1 * s.x),
                             fmaf(scale, sm[fft_phys(r, c + 1)].x, c1 * s.y),
                             fmaf(scale, sm[fft_phys(r, c + 2)].x, c1 * s.z),
                             fmaf(scale, sm[fft_phys(r, c + 3)].x, c1 * s.w));
    }
}

// ---------------- launch ----------------
extern "C" void kernel_launch(void* const* d_in, const int* in_sizes, int n_in,
                              void* d_out, int out_size) {
    const float* x      = (const float*)d_in[0];
    const float* f0     = (const float*)d_in[1];
    const float* theta  = (const float*)d_in[2];
    const float* sigma  = (const float*)d_in[3];
    const float* theta0 = (const float*)d_in[4];
    const float* fbs    = (const float*)d_in[5];
    const float* mix    = (const float*)d_in[6];
    const float* w1     = (const float*)d_in[7];
    const float* b1     = (const float*)d_in[8];
    const float* w2     = (const float*)d_in[9];
    const float* b2     = (const float*)d_in[10];
    const float* conv_w = (const float*)d_in[11];
    float* out = (float*)d_out;

    conv_kernel<<<dim3(64, 4), 256>>>(x, conv_w);
    fwd_fft_kernel<<<4096, 512>>>(x);
    attn_kernel<<<dim3(64, 16), 256>>>(f0, theta, sigma, theta0, w1, b1, w2, b2);
    inv_kernel<<<4096, 512>>>(x, fbs, mix, out);
}

// round 6
// speedup vs baseline: 2.8301x; 1.0186x over previous
#include <cuda_runtime.h>
#include <cuda_fp16.h>
#include <math.h>
#include <stdint.h>

// ---------------- device scratch (no allocs allowed) ----------------
__device__ __align__(16) __half d_Mh[4096ull * 4096ull];  // |FFT| magnitudes, fp16, 32MB
__device__ float d_G[64 * 4096];                          // G'[i,h,w], 1MB
__device__ float d_sp4[4 * 64 * 4096];                    // conv partials, 4MB (L2-resident in inv)

// ---------------- complex helpers ----------------
__device__ __forceinline__ float2 cmul(float2 a, float2 b) {
    return make_float2(a.x * b.x - a.y * b.y, a.x * b.y + a.y * b.x);
}
__device__ __forceinline__ float2 cadd(float2 a, float2 b) { return make_float2(a.x + b.x, a.y + b.y); }
__device__ __forceinline__ float2 csub(float2 a, float2 b) { return make_float2(a.x - b.x, a.y - b.y); }

// ---------------- MMA helpers ----------------
__device__ __forceinline__ void ldsm_x4(uint32_t (&r)[4], uint32_t addr) {
    asm volatile("ldmatrix.sync.aligned.m8n8.x4.shared.b16 {%0,%1,%2,%3}, [%4];"
                 : "=r"(r[0]), "=r"(r[1]), "=r"(r[2]), "=r"(r[3]) : "r"(addr));
}
__device__ __forceinline__ void ldsm_x2_trans(uint32_t (&r)[2], uint32_t addr) {
    asm volatile("ldmatrix.sync.aligned.m8n8.x2.trans.shared.b16 {%0,%1}, [%2];"
                 : "=r"(r[0]), "=r"(r[1]) : "r"(addr));
}
__device__ __forceinline__ void mma16816(float (&d)[4], const uint32_t (&a)[4], const uint32_t (&b)[2]) {
    asm volatile(
        "mma.sync.aligned.m16n8k16.row.col.f32.f16.f16.f32 "
        "{%0,%1,%2,%3},{%4,%5,%6,%7},{%8,%9},{%0,%1,%2,%3};"
        : "+f"(d[0]), "+f"(d[1]), "+f"(d[2]), "+f"(d[3])
        : "r"(a[0]), "r"(a[1]), "r"(a[2]), "r"(a[3]), "r"(b[0]), "r"(b[1]));
}

// ---------------- FFT smem layout ----------------
// phys(r, c) = r*72 + (c ^ (r & 7))   [float2 units]; conflict-minimized.
#define FFT_SM_F2 (64 * 72)
__device__ __forceinline__ int fft_phys(int r, int c) { return r * 72 + (c ^ (r & 7)); }

// 8-point DIF FFT in registers, natural-order output. SGN=-1 fwd, +1 inv.
template <int SGN>
__device__ __forceinline__ void fft8(float2 v[8]) {
    const float S = (float)SGN;
    const float C = 0.70710678118654752440f;
    float2 t0 = cadd(v[0], v[4]), t4 = csub(v[0], v[4]);
    float2 t1 = cadd(v[1], v[5]), t5 = csub(v[1], v[5]);
    float2 t2 = cadd(v[2], v[6]), t6 = csub(v[2], v[6]);
    float2 t3 = cadd(v[3], v[7]), t7 = csub(v[3], v[7]);
    t5 = cmul(t5, make_float2(C, S * C));
    t6 = make_float2(-S * t6.y, S * t6.x);
    t7 = cmul(t7, make_float2(-C, S * C));
    float2 u0 = cadd(t0, t2), u2 = csub(t0, t2);
    float2 u1 = cadd(t1, t3);
    float2 d13 = csub(t1, t3);
    float2 u3 = make_float2(-S * d13.y, S * d13.x);
    float2 u4 = cadd(t4, t6), u6 = csub(t4, t6);
    float2 u5 = cadd(t5, t7);
    float2 d57 = csub(t5, t7);
    float2 u7 = make_float2(-S * d57.y, S * d57.x);
    v[0] = cadd(u0, u1); v[4] = csub(u0, u1);
    v[2] = cadd(u2, u3); v[6] = csub(u2, u3);
    v[1] = cadd(u4, u5); v[5] = csub(u4, u5);
    v[3] = cadd(u6, u7); v[7] = csub(u6, u7);
}

// One pass (rows or cols) of a 64x64 2D FFT in shared memory.
template <int SGN, bool ROWS>
__device__ __forceinline__ void fft_pass(float2* sm, const float2* s_tw, int tid) {
    const int g = tid >> 3;
    const int t = tid & 7;
#define LIDX(m) (ROWS ? fft_phys(g, (m)) : fft_phys((m), g))
    float2 v[8];
#pragma unroll
    for (int n1 = 0; n1 < 8; n1++) v[n1] = sm[LIDX(8 * n1 + t)];
    fft8<SGN>(v);
#pragma unroll
    for (int k1 = 1; k1 < 8; k1++) {
        float2 w = s_tw[(t * k1) & 63];
        if (SGN == 1) w.y = -w.y;
        v[k1] = cmul(v[k1], w);
    }
    __syncwarp();
#pragma unroll
    for (int k1 = 0; k1 < 8; k1++) sm[LIDX(8 * k1 + (t ^ k1))] = v[k1];
    __syncwarp();
#pragma unroll
    for (int n2 = 0; n2 < 8; n2++) v[n2] = sm[LIDX(8 * t + (n2 ^ t))];
    fft8<SGN>(v);
    __syncwarp();
#pragma unroll
    for (int k2 = 0; k2 < 8; k2++) sm[LIDX(t + 8 * k2)] = v[k2];
#undef LIDX
}

// ---------------- kernel 1: fused [forward FFT2 -> fp16 mags] + [3x3 conv partials] ----------------
// Blocks [0, 4096): FFT of plane blockIdx.x.  Blocks [4096, 4352): conv (b, channel-group).
__global__ __launch_bounds__(512, 2) void k1_fft_conv(const float* __restrict__ x,
                                                      const float* __restrict__ cw) {
    __shared__ __align__(16) char sh[FFT_SM_F2 * 8 + 512];  // 37376 B union
    const int tid = threadIdx.x;

    if (blockIdx.x < 4096) {
        float2* sm = (float2*)sh;
        float2* s_tw = (float2*)(sh + FFT_SM_F2 * 8);
        const int plane = blockIdx.x;
        if (tid < 64) {
            float sn, cs;
            __sincosf(-6.283185307179586f * (float)tid * (1.0f / 64.0f), &sn, &cs);
            s_tw[tid] = make_float2(cs, sn);
        }
        const float4* xp4 = (const float4*)(x + (size_t)plane * 4096);
#pragma unroll
        for (int q = tid; q < 1024; q += 512) {
            float4 v = xp4[q];
            int r = q >> 4, c = (q & 15) * 4;
            sm[fft_phys(r, c + 0)] = make_float2(v.x, 0.f);
            sm[fft_phys(r, c + 1)] = make_float2(v.y, 0.f);
            sm[fft_phys(r, c + 2)] = make_float2(v.z, 0.f);
            sm[fft_phys(r, c + 3)] = make_float2(v.w, 0.f);
        }
        __syncthreads();
        fft_pass<-1, true>(sm, s_tw, tid);
        __syncthreads();
        fft_pass<-1, false>(sm, s_tw, tid);
        __syncthreads();
        __half2* mp2 = (__half2*)(d_Mh + (size_t)plane * 4096);
#pragma unroll
        for (int q = tid; q < 2048; q += 512) {
            int r = q >> 5, c = (q & 31) * 2;
            float2 a = sm[fft_phys(r, c)];
            float2 b = sm[fft_phys(r, c + 1)];
            mp2[q] = __floats2half2_rn(sqrtf(a.x * a.x + a.y * a.y),
                                       sqrtf(b.x * b.x + b.y * b.y));
        }
    } else {
        // ---- conv path: 512 threads, 16 channels ----
        float* sp = (float*)sh;                 // 66*66 floats = 17424 B
        float* sw = (float*)(sh + 17424);       // 144 floats
        const int idx = blockIdx.x - 4096;
        const int b = idx & 63, cg = idx >> 6;
        const int c0 = cg * 16;
        for (int k = tid; k < 66 * 66; k += 512) sp[k] = 0.f;
        for (int k = tid; k < 144; k += 512) sw[k] = cw[c0 * 9 + k];
        float acc[8];
#pragma unroll
        for (int q = 0; q < 8; q++) acc[q] = 0.f;
        const float* xb = x + ((size_t)b * 64 + c0) * 4096;
        for (int c = 0; c < 16; c++) {
            __syncthreads();
            for (int k = tid; k < 4096; k += 512)
                sp[((k >> 6) + 1) * 66 + (k & 63) + 1] = xb[c * 4096 + k];
            __syncthreads();
            const float* wr = &sw[c * 9];
#pragma unroll
            for (int q = 0; q < 8; q++) {
                int p = tid + q * 512;
                int hh = p >> 6, ww = p & 63;
                float a = acc[q];
#pragma unroll
                for (int kh = 0; kh < 3; kh++)
#pragma unroll
                    for (int kw = 0; kw < 3; kw++)
                        a = fmaf(sp[(hh + kh) * 66 + ww + kw], wr[kh * 3 + kw], a);
                acc[q] = a;
            }
        }
        float* o = d_sp4 + ((size_t)cg * 64 + b) * 4096;
#pragma unroll
        for (int q = 0; q < 8; q++) o[tid + q * 512] = acc[q];
    }
}

// ---------------- kernel 2: tensor-core attention + log-Gabor combine -> G'[i,h,w] ----------------
__global__ __launch_bounds__(256, 2) void attn_kernel(
    const float* __restrict__ f0, const float* __restrict__ theta,
    const float* __restrict__ sigma, const float* __restrict__ theta0,
    const float* __restrict__ w1, const float* __restrict__ b1,
    const float* __restrict__ w2, const float* __restrict__ b2) {
    __shared__ __align__(16) __half sA[64 * 72];    // W1s [o][c], padded
    __shared__ __align__(16) __half sM[64 * 264];   // M tile [c][p] fp16; reused as H [o][p]
    __shared__ float s_w2[3 * 64];
    __shared__ float s_b1[64];
    __shared__ float s_lf0[3], s_i2ls2[3], s_th[3], s_i2t02[3], s_b2[3];
    const int i = blockIdx.x;
    const int pbeg = blockIdx.y * 256;
    const int tid = threadIdx.x;

    for (int k = tid; k < 4096; k += 256) {
        int o = k >> 6, c = k & 63;
        sA[o * 72 + c] = __float2half(w1[o * 64 + ((c + 32) & 63)]);
    }
    for (int t = tid; t < 2048; t += 256) {
        int c = t >> 5, q = t & 31;
        uint4 v = *(const uint4*)(d_Mh + ((size_t)(i * 64 + c)) * 4096 + pbeg + q * 8);
        *(uint4*)&sM[c * 264 + q * 8] = v;
    }
    if (tid < 64) s_b1[tid] = b1[tid];
    if (tid < 192) s_w2[tid] = w2[tid];
    if (tid < 3) {
        s_b2[tid] = b2[tid];
        int ip = (i + 32) & 63;
        int idx = tid * 64 + ip;
        s_lf0[tid] = logf(f0[idx]);
        float ls = logf(sigma[idx]);
        s_i2ls2[tid] = 1.f / (2.f * ls * ls);
        s_th[tid] = theta[idx];
        float t0v = theta0[idx];
        s_i2t02[tid] = 1.f / (2.f * t0v * t0v);
    }
    __syncthreads();

    const int wid = tid >> 5, lane = tid & 31;
    const int o0 = (wid & 3) << 4, pw = (wid >> 2) << 7;
    const uint32_t sA_addr = (uint32_t)__cvta_generic_to_shared(sA);
    const uint32_t sM_addr = (uint32_t)__cvta_generic_to_shared(sM);

    uint32_t a[4][4];
#pragma unroll
    for (int ks = 0; ks < 4; ks++) {
        uint32_t addr = sA_addr + (uint32_t)(((o0 + (lane & 15)) * 72 + ks * 16 + ((lane >> 4) << 3)) * 2);
        ldsm_x4(a[ks], addr);
    }
    float acc[16][4];
#pragma unroll
    for (int j = 0; j < 16; j++)
#pragma unroll
        for (int q = 0; q < 4; q++) acc[j][q] = 0.f;
#pragma unroll
    for (int j = 0; j < 16; j++) {
#pragma unroll
        for (int ks = 0; ks < 4; ks++) {
            uint32_t b[2];
            uint32_t addr = sM_addr + (uint32_t)(((ks * 16 + (lane & 15)) * 264 + pw + j * 8) * 2);
            ldsm_x2_trans(b, addr);
            mma16816(acc[j], a[ks], b);
        }
    }
    __syncthreads();  // all reads of sM done; now overwrite with H

    {
        const int r0 = o0 + (lane >> 2);
        const int cbase = pw + (lane & 3) * 2;
        float b1a = s_b1[r0], b1b = s_b1[r0 + 8];
#pragma unroll
        for (int j = 0; j < 16; j++) {
            int c = cbase + j * 8;
            *(__half2*)&sM[r0 * 264 + c] =
                __floats2half2_rn(fmaxf(acc[j][0] + b1a, 0.f), fmaxf(acc[j][1] + b1a, 0.f));
            *(__half2*)&sM[(r0 + 8) * 264 + c] =
                __floats2half2_rn(fmaxf(acc[j][2] + b1b, 0.f), fmaxf(acc[j][3] + b1b, 0.f));
        }
    }
    __syncthreads();

    {
        float l0 = s_b2[0], l1 = s_b2[1], l2 = s_b2[2];
#pragma unroll
        for (int o = 0; o < 64; o++) {
            float hv = __half2float(sM[o * 264 + tid]);
            l0 = fmaf(s_w2[o], hv, l0);
            l1 = fmaf(s_w2[64 + o], hv, l1);
            l2 = fmaf(s_w2[128 + o], hv, l2);
        }
        float mx = fmaxf(l0, fmaxf(l1, l2));
        float e0 = __expf(l0 - mx), e1 = __expf(l1 - mx), e2 = __expf(l2 - mx);
        float inv = 1.f / (e0 + e1 + e2);
        const int p = pbeg + tid;
        int hh = ((p >> 6) + 32) & 63;
        int ww = ((p & 63) + 32) & 63;
        float yv_ = -1.f + 2.f * (float)hh * (1.f / 63.f);
        float xv_ = -1.f + 2.f * (float)ww * (1.f / 63.f);
        float r2 = xv_ * xv_ + yv_ * yv_ + 1e-6f;
        float lr = 0.5f * logf(r2);
        float phi = atan2f(yv_, xv_);
        float G = 0.f;
        float awv[3] = {e0 * inv, e1 * inv, e2 * inv};
#pragma unroll
        for (int s = 0; s < 3; s++) {
            float dl = lr - s_lf0[s];
            float dp = phi - s_th[s];
            float F = __expf(-(dl * dl) * s_i2ls2[s] - (dp * dp) * s_i2t02[s]);
            G = fmaf(F, awv[s], G);
        }
        d_G[i * 4096 + p] = G;
    }
}

// ---------------- kernel 3: masked fwd-FFT + pointwise + IFFT + mix epilogue ----------------
// Conv partials summed inline (d_sp4 is L2-resident; reused 64x per b).
__device__ __forceinline__ float4 conv_sum4(const float4* A, int q) {
    float4 s0 = A[q], s1 = A[q + 65536], s2 = A[q + 131072], s3 = A[q + 196608];
    return make_float4((s0.x + s1.x) + (s2.x + s3.x), (s0.y + s1.y) + (s2.y + s3.y),
                       (s0.z + s1.z) + (s2.z + s3.z), (s0.w + s1.w) + (s2.w + s3.w));
}

__global__ __launch_bounds__(512, 2) void inv_kernel(const float* __restrict__ x,
                                                     const float* __restrict__ fbs,
                                                     const float* __restrict__ mixp,
                                                     float* __restrict__ out) {
    __shared__ float2 sm[FFT_SM_F2];
    __shared__ float2 s_tw[64];
    const int plane = blockIdx.x;
    const int b = plane >> 6, i = plane & 63;
    const int tid = threadIdx.x;
    const float mix = mixp[0];
    const float c1 = 1.f - mix;
    const int bb = (b + 32) & 63;
    const int si = (int)floorf((fbs[bb * 2 + 0] + 1.f) * 0.5f * 64.f);
    const int ei = (int)floorf((fbs[bb * 2 + 1] + 1.f) * 0.5f * 64.f);
    const int ii = (i + 32) & 63;
    float4* op4 = (float4*)(out + (size_t)plane * 4096);
    const float4* A = ((const float4*)d_sp4) + (size_t)b * 1024;

    if (!(ii >= si && ii < ei)) {  // whole z-plane masked to zero
#pragma unroll
        for (int q = tid; q < 1024; q += 512) {
            float4 s = conv_sum4(A, q);
            op4[q] = make_float4(c1 * s.x, c1 * s.y, c1 * s.z, c1 * s.w);
        }
        return;
    }

    if (tid < 64) {
        float sn, cs;
        __sincosf(-6.283185307179586f * (float)tid * (1.0f / 64.0f), &sn, &cs);
        s_tw[tid] = make_float2(cs, sn);
    }
    const float4* xp4 = (const float4*)(x + (size_t)plane * 4096);
#pragma unroll
    for (int q = tid; q < 1024; q += 512) {
        float4 v = xp4[q];
        int r = q >> 4, c = (q & 15) * 4;
        sm[fft_phys(r, c + 0)] = make_float2(v.x, 0.f);
        sm[fft_phys(r, c + 1)] = make_float2(v.y, 0.f);
        sm[fft_phys(r, c + 2)] = make_float2(v.z, 0.f);
        sm[fft_phys(r, c + 3)] = make_float2(v.w, 0.f);
    }
    __syncthreads();
    fft_pass<-1, true>(sm, s_tw, tid);
    __syncthreads();
    fft_pass<-1, false>(sm, s_tw, tid);
    __syncthreads();
    const float* Gp = d_G + i * 4096;
    for (int k = tid; k < 4096; k += 512) {
        int r = k >> 6, c = k & 63;
        int hh = (r + 32) & 63;
        float g = (hh >= si && hh < ei) ? Gp[k] : 0.f;
        float2 z = sm[fft_phys(r, c)];
        sm[fft_phys(r, c)] = make_float2(z.x * g, z.y * g);
    }
    __syncthreads();
    fft_pass<1, true>(sm, s_tw, tid);
    __syncthreads();
    fft_pass<1, false>(sm, s_tw, tid);
    __syncthreads();
    const float scale = mix * (1.f / 4096.f);
#pragma unroll
    for (int q = tid; q < 1024; q += 512) {
        int r = q >> 4, c = (q & 15) * 4;
        float4 s = conv_sum4(A, q);
        op4[q] = make_float4(fmaf(scale, sm[fft_phys(r, c + 0)].x, c1 * s.x),
                             fmaf(scale, sm[fft_phys(r, c + 1)].x, c1 * s.y),
                             fmaf(scale, sm[fft_phys(r, c + 2)].x, c1 * s.z),
                             fmaf(scale, sm[fft_phys(r, c + 3)].x, c1 * s.w));
    }
}

// ---------------- launch ----------------
extern "C" void kernel_launch(void* const* d_in, const int* in_sizes, int n_in,
                              void* d_out, int out_size) {
    const float* x      = (const float*)d_in[0];
    const float* f0     = (const float*)d_in[1];
    const float* theta  = (const float*)d_in[2];
    const float* sigma  = (const float*)d_in[3];
    const float* theta0 = (const float*)d_in[4];
    const float* fbs    = (const float*)d_in[5];
    const float* mix    = (const float*)d_in[6];
    const float* w1     = (const float*)d_in[7];
    const float* b1     = (const float*)d_in[8];
    const float* w2     = (const float*)d_in[9];
    const float* b2     = (const float*)d_in[10];
    const float* conv_w = (const float*)d_in[11];
    float* out = (float*)d_out;

    k1_fft_conv<<<4352, 512>>>(x, conv_w);
    attn_kernel<<<dim3(64, 16), 256>>>(f0, theta, sigma, theta0, w1, b1, w2, b2);
    inv_kernel<<<4096, 512>>>(x, fbs, mix, out);
}

// round 7
// speedup vs baseline: 3.4796x; 1.2295x over previous
#include <cuda_runtime.h>
#include <cuda_fp16.h>
#include <math.h>
#include <stdint.h>

// ---------------- device scratch (no allocs allowed) ----------------
__device__ __align__(16) __half d_Mh[4096ull * 4096ull];  // |FFT| magnitudes, fp16, 32MB
__device__ float d_G[64 * 4096];                          // G'[i,h,w], 1MB
__device__ float d_sp4[4 * 64 * 4096];                    // conv partials, 4MB
__device__ float d_sp[64 * 4096];                         // reduced conv, 1MB

// ---------------- complex helpers ----------------
__device__ __forceinline__ float2 cmul(float2 a, float2 b) {
    return make_float2(a.x * b.x - a.y * b.y, a.x * b.y + a.y * b.x);
}
__device__ __forceinline__ float2 cadd(float2 a, float2 b) { return make_float2(a.x + b.x, a.y + b.y); }
__device__ __forceinline__ float2 csub(float2 a, float2 b) { return make_float2(a.x - b.x, a.y - b.y); }

// ---------------- MMA helpers ----------------
__device__ __forceinline__ void ldsm_x4(uint32_t (&r)[4], uint32_t addr) {
    asm volatile("ldmatrix.sync.aligned.m8n8.x4.shared.b16 {%0,%1,%2,%3}, [%4];"
                 : "=r"(r[0]), "=r"(r[1]), "=r"(r[2]), "=r"(r[3]) : "r"(addr));
}
__device__ __forceinline__ void ldsm_x2_trans(uint32_t (&r)[2], uint32_t addr) {
    asm volatile("ldmatrix.sync.aligned.m8n8.x2.trans.shared.b16 {%0,%1}, [%2];"
                 : "=r"(r[0]), "=r"(r[1]) : "r"(addr));
}
__device__ __forceinline__ void mma16816(float (&d)[4], const uint32_t (&a)[4], const uint32_t (&b)[2]) {
    asm volatile(
        "mma.sync.aligned.m16n8k16.row.col.f32.f16.f16.f32 "
        "{%0,%1,%2,%3},{%4,%5,%6,%7},{%8,%9},{%0,%1,%2,%3};"
        : "+f"(d[0]), "+f"(d[1]), "+f"(d[2]), "+f"(d[3])
        : "r"(a[0]), "r"(a[1]), "r"(a[2]), "r"(a[3]), "r"(b[0]), "r"(b[1]));
}

// ---------------- FFT smem layout ----------------
#define FFT_SM_F2 (64 * 72)
__device__ __forceinline__ int fft_phys(int r, int c) { return r * 72 + (c ^ (r & 7)); }

// 8-point DIF FFT in registers, natural-order output. SGN=-1 fwd, +1 inv.
template <int SGN>
__device__ __forceinline__ void fft8(float2 v[8]) {
    const float S = (float)SGN;
    const float C = 0.70710678118654752440f;
    float2 t0 = cadd(v[0], v[4]), t4 = csub(v[0], v[4]);
    float2 t1 = cadd(v[1], v[5]), t5 = csub(v[1], v[5]);
    float2 t2 = cadd(v[2], v[6]), t6 = csub(v[2], v[6]);
    float2 t3 = cadd(v[3], v[7]), t7 = csub(v[3], v[7]);
    t5 = cmul(t5, make_float2(C, S * C));
    t6 = make_float2(-S * t6.y, S * t6.x);
    t7 = cmul(t7, make_float2(-C, S * C));
    float2 u0 = cadd(t0, t2), u2 = csub(t0, t2);
    float2 u1 = cadd(t1, t3);
    float2 d13 = csub(t1, t3);
    float2 u3 = make_float2(-S * d13.y, S * d13.x);
    float2 u4 = cadd(t4, t6), u6 = csub(t4, t6);
    float2 u5 = cadd(t5, t7);
    float2 d57 = csub(t5, t7);
    float2 u7 = make_float2(-S * d57.y, S * d57.x);
    v[0] = cadd(u0, u1); v[4] = csub(u0, u1);
    v[2] = cadd(u2, u3); v[6] = csub(u2, u3);
    v[1] = cadd(u4, u5); v[5] = csub(u4, u5);
    v[3] = cadd(u6, u7); v[7] = csub(u6, u7);
}

// Row pass with input already in registers (v[n1] = z[g][8*n1+t]).
template <int SGN>
__device__ __forceinline__ void row_pass_reg(float2 v[8], float2* sm, const float2* s_tw, int tid) {
    const int g = tid >> 3, t = tid & 7;
    fft8<SGN>(v);
#pragma unroll
    for (int k1 = 1; k1 < 8; k1++) {
        float2 w = s_tw[(t * k1) & 63];
        if (SGN == 1) w.y = -w.y;
        v[k1] = cmul(v[k1], w);
    }
    __syncwarp();
#pragma unroll
    for (int k1 = 0; k1 < 8; k1++) sm[fft_phys(g, 8 * k1 + (t ^ k1))] = v[k1];
    __syncwarp();
#pragma unroll
    for (int n2 = 0; n2 < 8; n2++) v[n2] = sm[fft_phys(g, 8 * t + (n2 ^ t))];
    fft8<SGN>(v);
    __syncwarp();
#pragma unroll
    for (int k2 = 0; k2 < 8; k2++) sm[fft_phys(g, t + 8 * k2)] = v[k2];
}

// One pass (rows or cols) of a 64x64 2D FFT in shared memory (LDS-sourced).
template <int SGN, bool ROWS>
__device__ __forceinline__ void fft_pass(float2* sm, const float2* s_tw, int tid) {
    const int g = tid >> 3;
    const int t = tid & 7;
#define LIDX(m) (ROWS ? fft_phys(g, (m)) : fft_phys((m), g))
    float2 v[8];
#pragma unroll
    for (int n1 = 0; n1 < 8; n1++) v[n1] = sm[LIDX(8 * n1 + t)];
    fft8<SGN>(v);
#pragma unroll
    for (int k1 = 1; k1 < 8; k1++) {
        float2 w = s_tw[(t * k1) & 63];
        if (SGN == 1) w.y = -w.y;
        v[k1] = cmul(v[k1], w);
    }
    __syncwarp();
#pragma unroll
    for (int k1 = 0; k1 < 8; k1++) sm[LIDX(8 * k1 + (t ^ k1))] = v[k1];
    __syncwarp();
#pragma unroll
    for (int n2 = 0; n2 < 8; n2++) v[n2] = sm[LIDX(8 * t + (n2 ^ t))];
    fft8<SGN>(v);
    __syncwarp();
#pragma unroll
    for (int k2 = 0; k2 < 8; k2++) sm[LIDX(t + 8 * k2)] = v[k2];
#undef LIDX
}

// ---------------- kernel 1: fused [two-for-one fwd FFT -> fp16 mags] + [3x3 conv] ----------------
// Blocks [0,2048): FFT of plane pair (b, 2u), (b, 2u+1).  Blocks [2048,2304): conv.
__global__ __launch_bounds__(512, 2) void k1_fft_conv(const float* __restrict__ x,
                                                      const float* __restrict__ cw) {
    __shared__ __align__(16) char sh[FFT_SM_F2 * 8 + 512];
    const int tid = threadIdx.x;

    if (blockIdx.x < 2048) {
        float2* sm = (float2*)sh;
        float2* s_tw = (float2*)(sh + FFT_SM_F2 * 8);
        const int b = blockIdx.x >> 5;
        const int i0 = (blockIdx.x & 31) * 2;
        if (tid < 64) {
            float sn, cs;
            __sincosf(-6.283185307179586f * (float)tid * (1.0f / 64.0f), &sn, &cs);
            s_tw[tid] = make_float2(cs, sn);
        }
        __syncthreads();
        const float* xp0 = x + ((size_t)(b * 64 + i0)) * 4096;
        const float* xp1 = xp0 + 4096;
        {
            const int g = tid >> 3, t = tid & 7;
            float2 v[8];
#pragma unroll
            for (int n1 = 0; n1 < 8; n1++) {
                int idx = g * 64 + 8 * n1 + t;
                v[n1] = make_float2(xp0[idx], xp1[idx]);
            }
            row_pass_reg<-1>(v, sm, s_tw, tid);
        }
        __syncthreads();
        fft_pass<-1, false>(sm, s_tw, tid);
        __syncthreads();
        // Hermitian split magnitudes: mag0 = .5|Z[k]+conj(Z[-k])|, mag1 = .5|Z[k]-conj(Z[-k])|
        __half* m0 = d_Mh + ((size_t)(b * 64 + i0)) * 4096;
        __half* m1 = m0 + 4096;
#pragma unroll
        for (int n = 0; n < 8; n++) {
            int k = tid + n * 512;
            int r = k >> 6, c = k & 63;
            float2 Zk = sm[fft_phys(r, c)];
            float2 Zm = sm[fft_phys((64 - r) & 63, (64 - c) & 63)];
            float sx = Zk.x + Zm.x, sy = Zk.y - Zm.y;
            float dx = Zk.x - Zm.x, dy = Zk.y + Zm.y;
            m0[k] = __float2half(0.5f * sqrtf(sx * sx + sy * sy));
            m1[k] = __float2half(0.5f * sqrtf(dx * dx + dy * dy));
        }
    } else {
        // ---- conv path: 512 threads, 16 channels ----
        float* sp = (float*)sh;
        float* sw = (float*)(sh + 17424);
        const int idx = blockIdx.x - 2048;
        const int b = idx & 63, cg = idx >> 6;
        const int c0 = cg * 16;
        for (int k = tid; k < 66 * 66; k += 512) sp[k] = 0.f;
        for (int k = tid; k < 144; k += 512) sw[k] = cw[c0 * 9 + k];
        float acc[8];
#pragma unroll
        for (int q = 0; q < 8; q++) acc[q] = 0.f;
        const float* xb = x + ((size_t)b * 64 + c0) * 4096;
        for (int c = 0; c < 16; c++) {
            __syncthreads();
            for (int k = tid; k < 4096; k += 512)
                sp[((k >> 6) + 1) * 66 + (k & 63) + 1] = xb[c * 4096 + k];
            __syncthreads();
            const float* wr = &sw[c * 9];
#pragma unroll
            for (int q = 0; q < 8; q++) {
                int p = tid + q * 512;
                int hh = p >> 6, ww = p & 63;
                float a = acc[q];
#pragma unroll
                for (int kh = 0; kh < 3; kh++)
#pragma unroll
                    for (int kw = 0; kw < 3; kw++)
                        a = fmaf(sp[(hh + kh) * 66 + ww + kw], wr[kh * 3 + kw], a);
                acc[q] = a;
            }
        }
        float* o = d_sp4 + ((size_t)cg * 64 + b) * 4096;
#pragma unroll
        for (int q = 0; q < 8; q++) o[tid + q * 512] = acc[q];
    }
}

// ---------------- kernel 2: tensor-core attention + log-Gabor -> G' (+ conv reduce) ----------------
// Blocks [0,1024): attention tile (i = bx>>4, ptile = bx&15). Blocks [1024,1088): conv reduce.
__global__ __launch_bounds__(256, 2) void attn_kernel(
    const float* __restrict__ f0, const float* __restrict__ theta,
    const float* __restrict__ sigma, const float* __restrict__ theta0,
    const float* __restrict__ w1, const float* __restrict__ b1,
    const float* __restrict__ w2, const float* __restrict__ b2) {
    const int tid = threadIdx.x;
    if (blockIdx.x >= 1024) {  // conv reduce
        const int b = blockIdx.x - 1024;
        const float4* A = ((const float4*)d_sp4) + (size_t)b * 1024;
        float4* O = ((float4*)d_sp) + (size_t)b * 1024;
#pragma unroll
        for (int q = tid; q < 1024; q += 256) {
            float4 s0 = A[q], s1 = A[q + 65536], s2 = A[q + 131072], s3 = A[q + 196608];
            O[q] = make_float4((s0.x + s1.x) + (s2.x + s3.x), (s0.y + s1.y) + (s2.y + s3.y),
                               (s0.z + s1.z) + (s2.z + s3.z), (s0.w + s1.w) + (s2.w + s3.w));
        }
        return;
    }
    __shared__ __align__(16) __half sA[64 * 72];
    __shared__ __align__(16) __half sM[64 * 264];
    __shared__ float s_w2[3 * 64];
    __shared__ float s_b1[64];
    __shared__ float s_lf0[3], s_i2ls2[3], s_th[3], s_i2t02[3], s_b2[3];
    const int i = blockIdx.x >> 4;
    const int pbeg = (blockIdx.x & 15) * 256;

    for (int k = tid; k < 4096; k += 256) {
        int o = k >> 6, c = k & 63;
        sA[o * 72 + c] = __float2half(w1[o * 64 + ((c + 32) & 63)]);
    }
    for (int t = tid; t < 2048; t += 256) {
        int c = t >> 5, q = t & 31;
        uint4 v = *(const uint4*)(d_Mh + ((size_t)(i * 64 + c)) * 4096 + pbeg + q * 8);
        *(uint4*)&sM[c * 264 + q * 8] = v;
    }
    if (tid < 64) s_b1[tid] = b1[tid];
    if (tid < 192) s_w2[tid] = w2[tid];
    if (tid < 3) {
        s_b2[tid] = b2[tid];
        int ip = (i + 32) & 63;
        int idx = tid * 64 + ip;
        s_lf0[tid] = logf(f0[idx]);
        float ls = logf(sigma[idx]);
        s_i2ls2[tid] = 1.f / (2.f * ls * ls);
        s_th[tid] = theta[idx];
        float t0v = theta0[idx];
        s_i2t02[tid] = 1.f / (2.f * t0v * t0v);
    }
    __syncthreads();

    const int wid = tid >> 5, lane = tid & 31;
    const int o0 = (wid & 3) << 4, pw = (wid >> 2) << 7;
    const uint32_t sA_addr = (uint32_t)__cvta_generic_to_shared(sA);
    const uint32_t sM_addr = (uint32_t)__cvta_generic_to_shared(sM);

    uint32_t a[4][4];
#pragma unroll
    for (int ks = 0; ks < 4; ks++) {
        uint32_t addr = sA_addr + (uint32_t)(((o0 + (lane & 15)) * 72 + ks * 16 + ((lane >> 4) << 3)) * 2);
        ldsm_x4(a[ks], addr);
    }
    float acc[16][4];
#pragma unroll
    for (int j = 0; j < 16; j++)
#pragma unroll
        for (int q = 0; q < 4; q++) acc[j][q] = 0.f;
#pragma unroll
    for (int j = 0; j < 16; j++) {
#pragma unroll
        for (int ks = 0; ks < 4; ks++) {
            uint32_t b[2];
            uint32_t addr = sM_addr + (uint32_t)(((ks * 16 + (lane & 15)) * 264 + pw + j * 8) * 2);
            ldsm_x2_trans(b, addr);
            mma16816(acc[j], a[ks], b);
        }
    }
    __syncthreads();

    {
        const int r0 = o0 + (lane >> 2);
        const int cbase = pw + (lane & 3) * 2;
        float b1a = s_b1[r0], b1b = s_b1[r0 + 8];
#pragma unroll
        for (int j = 0; j < 16; j++) {
            int c = cbase + j * 8;
            *(__half2*)&sM[r0 * 264 + c] =
                __floats2half2_rn(fmaxf(acc[j][0] + b1a, 0.f), fmaxf(acc[j][1] + b1a, 0.f));
            *(__half2*)&sM[(r0 + 8) * 264 + c] =
                __floats2half2_rn(fmaxf(acc[j][2] + b1b, 0.f), fmaxf(acc[j][3] + b1b, 0.f));
        }
    }
    __syncthreads();

    {
        float l0 = s_b2[0], l1 = s_b2[1], l2 = s_b2[2];
#pragma unroll
        for (int o = 0; o < 64; o++) {
            float hv = __half2float(sM[o * 264 + tid]);
            l0 = fmaf(s_w2[o], hv, l0);
            l1 = fmaf(s_w2[64 + o], hv, l1);
            l2 = fmaf(s_w2[128 + o], hv, l2);
        }
        float mx = fmaxf(l0, fmaxf(l1, l2));
        float e0 = __expf(l0 - mx), e1 = __expf(l1 - mx), e2 = __expf(l2 - mx);
        float inv = 1.f / (e0 + e1 + e2);
        const int p = pbeg + tid;
        int hh = ((p >> 6) + 32) & 63;
        int ww = ((p & 63) + 32) & 63;
        float yv_ = -1.f + 2.f * (float)hh * (1.f / 63.f);
        float xv_ = -1.f + 2.f * (float)ww * (1.f / 63.f);
        float r2 = xv_ * xv_ + yv_ * yv_ + 1e-6f;
        float lr = 0.5f * logf(r2);
        float phi = atan2f(yv_, xv_);
        float G = 0.f;
        float awv[3] = {e0 * inv, e1 * inv, e2 * inv};
#pragma unroll
        for (int s = 0; s < 3; s++) {
            float dl = lr - s_lf0[s];
            float dp = phi - s_th[s];
            float F = __expf(-(dl * dl) * s_i2ls2[s] - (dp * dp) * s_i2t02[s]);
            G = fmaf(F, awv[s], G);
        }
        d_G[i * 4096 + p] = G;
    }
}

// ---------------- kernel 3: two-for-one masked filter + IFFT + mix ----------------
// Survivor planes (i in [si-32, ei-32)) paired; even-index survivor handles its pair.
__global__ __launch_bounds__(512, 2) void inv_kernel(const float* __restrict__ x,
                                                     const float* __restrict__ fbs,
                                                     const float* __restrict__ mixp,
                                                     float* __restrict__ out) {
    __shared__ float2 sm[FFT_SM_F2];
    __shared__ float2 s_tw[64];
    const int plane = blockIdx.x;
    const int b = plane >> 6, i = plane & 63;
    const int tid = threadIdx.x;
    const float mix = mixp[0];
    const float c1 = 1.f - mix;
    const int bb = (b + 32) & 63;
    const int si = (int)floorf((fbs[bb * 2 + 0] + 1.f) * 0.5f * 64.f);
    const int ei = (int)floorf((fbs[bb * 2 + 1] + 1.f) * 0.5f * 64.f);
    const int ii = (i + 32) & 63;
    const float4* sb4 = ((const float4*)d_sp) + (size_t)b * 1024;

    if (!(ii >= si && ii < ei)) {  // non-survivor: conv-only output
        float4* op4 = (float4*)(out + (size_t)plane * 4096);
#pragma unroll
        for (int q = tid; q < 1024; q += 512) {
            float4 s = sb4[q];
            op4[q] = make_float4(c1 * s.x, c1 * s.y, c1 * s.z, c1 * s.w);
        }
        return;
    }
    const int j = ii - si;          // survivor index
    if (j & 1) return;              // handled by partner block (i-1)
    const bool haspart = (ii + 1 < ei);

    if (tid < 64) {
        float sn, cs;
        __sincosf(-6.283185307179586f * (float)tid * (1.0f / 64.0f), &sn, &cs);
        s_tw[tid] = make_float2(cs, sn);
    }
    __syncthreads();
    // forward FFT of packed pair z = x[b,i] + i*x[b,i+1]
    const float* xp0 = x + (size_t)plane * 4096;
    const float* xp1 = xp0 + 4096;  // valid only if haspart
    {
        const int g = tid >> 3, t = tid & 7;
        float2 v[8];
#pragma unroll
        for (int n1 = 0; n1 < 8; n1++) {
            int idx = g * 64 + 8 * n1 + t;
            v[n1] = make_float2(xp0[idx], haspart ? xp1[idx] : 0.f);
        }
        row_pass_reg<-1>(v, sm, s_tw, tid);
    }
    __syncthreads();
    fft_pass<-1, false>(sm, s_tw, tid);
    __syncthreads();
    // pointwise: split, filter with symmetrized g, re-pack Hermitian parts
    const float* G0 = d_G + i * 4096;
    const float* G1 = d_G + (i + 1) * 4096;  // read only if haspart
    float2 P[8];
#pragma unroll
    for (int n = 0; n < 8; n++) {
        int k = tid + n * 512;
        int r = k >> 6, c = k & 63;
        int rm = (64 - r) & 63, cm = (64 - c) & 63;
        int km = rm * 64 + cm;
        float2 Zk = sm[fft_phys(r, c)];
        float2 Zm = sm[fft_phys(rm, cm)];
        int hh = (r + 32) & 63, hhm = (rm + 32) & 63;
        float mr = (hh >= si && hh < ei) ? 0.5f : 0.f;
        float mrm = (hhm >= si && hhm < ei) ? 0.5f : 0.f;
        float g0 = G0[k] * mr + G0[km] * mrm;
        float g1 = haspart ? (G1[k] * mr + G1[km] * mrm) : 0.f;
        float y0x = 0.5f * (Zk.x + Zm.x), y0y = 0.5f * (Zk.y - Zm.y);
        float y1x = 0.5f * (Zk.y + Zm.y), y1y = -0.5f * (Zk.x - Zm.x);
        P[n] = make_float2(y0x * g0 - g1 * y1y, y0y * g0 + g1 * y1x);
    }
    __syncthreads();
#pragma unroll
    for (int n = 0; n < 8; n++) {
        int k = tid + n * 512;
        sm[fft_phys(k >> 6, k & 63)] = P[n];
    }
    __syncthreads();
    fft_pass<1, true>(sm, s_tw, tid);
    __syncthreads();
    fft_pass<1, false>(sm, s_tw, tid);
    __syncthreads();
    const float scale = mix * (1.f / 4096.f);
    float4* op0 = (float4*)(out + (size_t)plane * 4096);
    float4* op1 = (float4*)(out + (size_t)(plane + 1) * 4096);
#pragma unroll
    for (int q = tid; q < 1024; q += 512) {
        int r = q >> 4, c = (q & 15) * 4;
        float2 w0 = sm[fft_phys(r, c + 0)];
        float2 w1v = sm[fft_phys(r, c + 1)];
        float2 w2v = sm[fft_phys(r, c + 2)];
        float2 w3 = sm[fft_phys(r, c + 3)];
        float4 s = sb4[q];
        op0[q] = make_float4(fmaf(scale, w0.x, c1 * s.x), fmaf(scale, w1v.x, c1 * s.y),
                             fmaf(scale, w2v.x, c1 * s.z), fmaf(scale, w3.x, c1 * s.w));
        if (haspart)
            op1[q] = make_float4(fmaf(scale, w0.y, c1 * s.x), fmaf(scale, w1v.y, c1 * s.y),
                                 fmaf(scale, w2v.y, c1 * s.z), fmaf(scale, w3.y, c1 * s.w));
    }
}

// ---------------- launch ----------------
extern "C" void kernel_launch(void* const* d_in, const int* in_sizes, int n_in,
                              void* d_out, int out_size) {
    const float* x      = (const float*)d_in[0];
    const float* f0     = (const float*)d_in[1];
    const float* theta  = (const float*)d_in[2];
    const float* sigma  = (const float*)d_in[3];
    const float* theta0 = (const float*)d_in[4];
    const float* fbs    = (const float*)d_in[5];
    const float* mix    = (const float*)d_in[6];
    const float* w1     = (const float*)d_in[7];
    const float* b1     = (const float*)d_in[8];
    const float* w2     = (const float*)d_in[9];
    const float* b2     = (const float*)d_in[10];
    const float* conv_w = (const float*)d_in[11];
    float* out = (float*)d_out;

    k1_fft_conv<<<2304, 512>>>(x, conv_w);
    attn_kernel<<<1088, 256>>>(f0, theta, sigma, theta0, w1, b1, w2, b2);
    inv_kernel<<<4096, 512>>>(x, fbs, mix, out);
}

// round 8
// speedup vs baseline: 3.6755x; 1.0563x over previous
#include <cuda_runtime.h>
#include <cuda_fp16.h>
#include <math.h>
#include <stdint.h>

typedef unsigned long long ull;

// ---------------- device scratch (no allocs allowed) ----------------
__device__ __align__(16) __half d_Mh[4096ull * 4096ull];  // |FFT| magnitudes, fp16, 32MB
__device__ float d_G[64 * 4096];                          // G'[i,h,w], 1MB
__device__ float d_sp4[4 * 64 * 4096];                    // conv partials, 4MB
__device__ float d_sp[64 * 4096];                         // reduced conv, 1MB

// ---------------- packed f32x2 helpers ----------------
__device__ __forceinline__ ull PK(float x, float y) {
    ull r; asm("mov.b64 %0,{%1,%2};" : "=l"(r) : "f"(x), "f"(y)); return r;
}
__device__ __forceinline__ float2 UPK(ull v) {
    float2 r; asm("mov.b64 {%0,%1},%2;" : "=f"(r.x), "=f"(r.y) : "l"(v)); return r;
}
__device__ __forceinline__ ull PADD(ull a, ull b) {
    ull d; asm("add.rn.f32x2 %0,%1,%2;" : "=l"(d) : "l"(a), "l"(b)); return d;
}
__device__ __forceinline__ ull PFMA(ull a, ull b, ull c) {
    ull d; asm("fma.rn.f32x2 %0,%1,%2,%3;" : "=l"(d) : "l"(a), "l"(b), "l"(c)); return d;
}
__device__ __forceinline__ ull PSUB(ull a, ull b) {  // a - b = b*(-1) + a
    return PFMA(b, PK(-1.f, -1.f), a);
}

// ---------------- MMA helpers ----------------
__device__ __forceinline__ void ldsm_x4(uint32_t (&r)[4], uint32_t addr) {
    asm volatile("ldmatrix.sync.aligned.m8n8.x4.shared.b16 {%0,%1,%2,%3}, [%4];"
                 : "=r"(r[0]), "=r"(r[1]), "=r"(r[2]), "=r"(r[3]) : "r"(addr));
}
__device__ __forceinline__ void ldsm_x2_trans(uint32_t (&r)[2], uint32_t addr) {
    asm volatile("ldmatrix.sync.aligned.m8n8.x2.trans.shared.b16 {%0,%1}, [%2];"
                 : "=r"(r[0]), "=r"(r[1]) : "r"(addr));
}
__device__ __forceinline__ void mma16816(float (&d)[4], const uint32_t (&a)[4], const uint32_t (&b)[2]) {
    asm volatile(
        "mma.sync.aligned.m16n8k16.row.col.f32.f16.f16.f32 "
        "{%0,%1,%2,%3},{%4,%5,%6,%7},{%8,%9},{%0,%1,%2,%3};"
        : "+f"(d[0]), "+f"(d[1]), "+f"(d[2]), "+f"(d[3])
        : "r"(a[0]), "r"(a[1]), "r"(a[2]), "r"(a[3]), "r"(b[0]), "r"(b[1]));
}

// ---------------- FFT smem layout ----------------
#define FFT_SM_F2 (64 * 72)
__device__ __forceinline__ int fft_phys(int r, int c) { return r * 72 + (c ^ (r & 7)); }

// 8-point DIF FFT on packed complex (re,im) in f32x2 registers. SGN=-1 fwd, +1 inv.
template <int SGN>
__device__ __forceinline__ void fft8p(ull v[8]) {
    const float S = (float)SGN;
    const float C = 0.70710678118654752440f;
    ull t0 = PADD(v[0], v[4]), t4 = PSUB(v[0], v[4]);
    ull t1 = PADD(v[1], v[5]), t5 = PSUB(v[1], v[5]);
    ull t2 = PADD(v[2], v[6]), t6 = PSUB(v[2], v[6]);
    ull t3 = PADD(v[3], v[7]), t7 = PSUB(v[3], v[7]);
    float2 f5 = UPK(t5), f6 = UPK(t6), f7 = UPK(t7);
    t5 = PK(C * (f5.x - S * f5.y), C * (S * f5.x + f5.y));     // *(C, S*C)
    t6 = PK(-S * f6.y, S * f6.x);                              // *(0, S)
    t7 = PK(C * (-f7.x - S * f7.y), C * (S * f7.x - f7.y));    // *(-C, S*C)
    ull u0 = PADD(t0, t2), u2 = PSUB(t0, t2);
    ull u1 = PADD(t1, t3);
    float2 d13 = UPK(PSUB(t1, t3));
    ull u3 = PK(-S * d13.y, S * d13.x);
    ull u4 = PADD(t4, t6), u6 = PSUB(t4, t6);
    ull u5 = PADD(t5, t7);
    float2 d57 = UPK(PSUB(t5, t7));
    ull u7 = PK(-S * d57.y, S * d57.x);
    v[0] = PADD(u0, u1); v[4] = PSUB(u0, u1);
    v[2] = PADD(u2, u3); v[6] = PSUB(u2, u3);
    v[1] = PADD(u4, u5); v[5] = PSUB(u4, u5);
    v[3] = PADD(u6, u7); v[7] = PSUB(u6, u7);
}

__device__ __forceinline__ ull tw_mul(ull z, float2 w) {
    float2 f = UPK(z);
    return PK(f.x * w.x - f.y * w.y, f.x * w.y + f.y * w.x);
}

// Row pass with input already in registers (v[n1] = z[g][8*n1+t]).
template <int SGN>
__device__ __forceinline__ void row_pass_reg(ull v[8], float2* smf, const float2* s_tw, int tid) {
    ull* sm = (ull*)smf;
    const int g = tid >> 3, t = tid & 7;
    fft8p<SGN>(v);
#pragma unroll
    for (int k1 = 1; k1 < 8; k1++) {
        float2 w = s_tw[(t * k1) & 63];
        if (SGN == 1) w.y = -w.y;
        v[k1] = tw_mul(v[k1], w);
    }
    __syncwarp();
#pragma unroll
    for (int k1 = 0; k1 < 8; k1++) sm[fft_phys(g, 8 * k1 + (t ^ k1))] = v[k1];
    __syncwarp();
#pragma unroll
    for (int n2 = 0; n2 < 8; n2++) v[n2] = sm[fft_phys(g, 8 * t + (n2 ^ t))];
    fft8p<SGN>(v);
    __syncwarp();
#pragma unroll
    for (int k2 = 0; k2 < 8; k2++) sm[fft_phys(g, t + 8 * k2)] = v[k2];
}

// One pass (rows or cols) of a 64x64 2D FFT in shared memory (LDS-sourced).
template <int SGN, bool ROWS>
__device__ __forceinline__ void fft_pass(float2* smf, const float2* s_tw, int tid) {
    ull* sm = (ull*)smf;
    const int g = tid >> 3;
    const int t = tid & 7;
#define LIDX(m) (ROWS ? fft_phys(g, (m)) : fft_phys((m), g))
    ull v[8];
#pragma unroll
    for (int n1 = 0; n1 < 8; n1++) v[n1] = sm[LIDX(8 * n1 + t)];
    fft8p<SGN>(v);
#pragma unroll
    for (int k1 = 1; k1 < 8; k1++) {
        float2 w = s_tw[(t * k1) & 63];
        if (SGN == 1) w.y = -w.y;
        v[k1] = tw_mul(v[k1], w);
    }
    __syncwarp();
#pragma unroll
    for (int k1 = 0; k1 < 8; k1++) sm[LIDX(8 * k1 + (t ^ k1))] = v[k1];
    __syncwarp();
#pragma unroll
    for (int n2 = 0; n2 < 8; n2++) v[n2] = sm[LIDX(8 * t + (n2 ^ t))];
    fft8p<SGN>(v);
    __syncwarp();
#pragma unroll
    for (int k2 = 0; k2 < 8; k2++) sm[LIDX(t + 8 * k2)] = v[k2];
#undef LIDX
}

// ---------------- kernel 1: fused [two-for-one fwd FFT -> fp16 mags] + [3x3 conv] ----------------
// Blocks [0,2048): FFT of plane pair (b, 2u), (b, 2u+1).  Blocks [2048,2304): conv.
__global__ __launch_bounds__(512, 2) void k1_fft_conv(const float* __restrict__ x,
                                                      const float* __restrict__ cw) {
    __shared__ __align__(16) char sh[FFT_SM_F2 * 8 + 512];
    const int tid = threadIdx.x;

    if (blockIdx.x < 2048) {
        float2* sm = (float2*)sh;
        float2* s_tw = (float2*)(sh + FFT_SM_F2 * 8);
        const int b = blockIdx.x >> 5;
        const int i0 = (blockIdx.x & 31) * 2;
        if (tid < 64) {
            float sn, cs;
            __sincosf(-6.283185307179586f * (float)tid * (1.0f / 64.0f), &sn, &cs);
            s_tw[tid] = make_float2(cs, sn);
        }
        __syncthreads();
        const float* xp0 = x + ((size_t)(b * 64 + i0)) * 4096;
        const float* xp1 = xp0 + 4096;
        {
            const int g = tid >> 3, t = tid & 7;
            ull v[8];
#pragma unroll
            for (int n1 = 0; n1 < 8; n1++) {
                int idx = g * 64 + 8 * n1 + t;
                v[n1] = PK(xp0[idx], xp1[idx]);
            }
            row_pass_reg<-1>(v, sm, s_tw, tid);
        }
        __syncthreads();
        fft_pass<-1, false>(sm, s_tw, tid);
        __syncthreads();
        // Hermitian split magnitudes
        __half* m0 = d_Mh + ((size_t)(b * 64 + i0)) * 4096;
        __half* m1 = m0 + 4096;
#pragma unroll
        for (int n = 0; n < 8; n++) {
            int k = tid + n * 512;
            int r = k >> 6, c = k & 63;
            float2 Zk = sm[fft_phys(r, c)];
            float2 Zm = sm[fft_phys((64 - r) & 63, (64 - c) & 63)];
            float sx = Zk.x + Zm.x, sy = Zk.y - Zm.y;
            float dx = Zk.x - Zm.x, dy = Zk.y + Zm.y;
            m0[k] = __float2half(0.5f * sqrtf(sx * sx + sy * sy));
            m1[k] = __float2half(0.5f * sqrtf(dx * dx + dy * dy));
        }
    } else {
        // ---- conv path: vertical 8-row windows + f32x2 packed accumulation ----
        float* sp = (float*)sh;             // 66*66 floats
        float* sw = (float*)(sh + 17424);   // 144 floats
        const int idx = blockIdx.x - 2048;
        const int b = idx & 63, cg = idx >> 6;
        const int c0 = cg * 16;
        const int ww = tid & 63, hb8 = (tid >> 6) * 8;
        for (int k = tid; k < 66 * 66; k += 512) sp[k] = 0.f;
        for (int k = tid; k < 144; k += 512) sw[k] = cw[c0 * 9 + k];
        ull acc2[4];
#pragma unroll
        for (int q = 0; q < 4; q++) acc2[q] = PK(0.f, 0.f);
        const float* xb = x + ((size_t)b * 64 + c0) * 4096;
        for (int c = 0; c < 16; c++) {
            __syncthreads();
            for (int k = tid; k < 4096; k += 512)
                sp[((k >> 6) + 1) * 66 + (k & 63) + 1] = xb[c * 4096 + k];
            __syncthreads();
            ull wd[9];
#pragma unroll
            for (int j = 0; j < 9; j++) {
                float wv = sw[c * 9 + j];
                wd[j] = PK(wv, wv);
            }
#pragma unroll
            for (int kw = 0; kw < 3; kw++) {
                float wcol[10];
#pragma unroll
                for (int rr = 0; rr < 10; rr++) wcol[rr] = sp[(hb8 + rr) * 66 + ww + kw];
                ull pkc[6];
#pragma unroll
                for (int j = 0; j < 6; j++) pkc[j] = PK(wcol[j], wcol[j + 4]);
#pragma unroll
                for (int q = 0; q < 4; q++)
#pragma unroll
                    for (int kh = 0; kh < 3; kh++)
                        acc2[q] = PFMA(pkc[q + kh], wd[kh * 3 + kw], acc2[q]);
            }
        }
        float* o = d_sp4 + ((size_t)cg * 64 + b) * 4096;
#pragma unroll
        for (int q = 0; q < 4; q++) {
            float2 a = UPK(acc2[q]);
            o[(hb8 + q) * 64 + ww] = a.x;
            o[(hb8 + q + 4) * 64 + ww] = a.y;
        }
    }
}

// ---------------- kernel 2: tensor-core attention + log-Gabor -> G' (+ conv reduce) ----------------
__global__ __launch_bounds__(256, 2) void attn_kernel(
    const float* __restrict__ f0, const float* __restrict__ theta,
    const float* __restrict__ sigma, const float* __restrict__ theta0,
    const float* __restrict__ w1, const float* __restrict__ b1,
    const float* __restrict__ w2, const float* __restrict__ b2) {
    const int tid = threadIdx.x;
    if (blockIdx.x >= 1024) {  // conv reduce
        const int b = blockIdx.x - 1024;
        const float4* A = ((const float4*)d_sp4) + (size_t)b * 1024;
        float4* O = ((float4*)d_sp) + (size_t)b * 1024;
#pragma unroll
        for (int q = tid; q < 1024; q += 256) {
            float4 s0 = A[q], s1 = A[q + 65536], s2 = A[q + 131072], s3 = A[q + 196608];
            O[q] = make_float4((s0.x + s1.x) + (s2.x + s3.x), (s0.y + s1.y) + (s2.y + s3.y),
                               (s0.z + s1.z) + (s2.z + s3.z), (s0.w + s1.w) + (s2.w + s3.w));
        }
        return;
    }
    __shared__ __align__(16) __half sA[64 * 72];
    __shared__ __align__(16) __half sM[64 * 264];
    __shared__ float s_w2[3 * 64];
    __shared__ float s_b1[64];
    __shared__ float s_lf0[3], s_i2ls2[3], s_th[3], s_i2t02[3], s_b2[3];
    const int i = blockIdx.x >> 4;
    const int pbeg = (blockIdx.x & 15) * 256;

    for (int k = tid; k < 4096; k += 256) {
        int o = k >> 6, c = k & 63;
        sA[o * 72 + c] = __float2half(w1[o * 64 + ((c + 32) & 63)]);
    }
    for (int t = tid; t < 2048; t += 256) {
        int c = t >> 5, q = t & 31;
        uint4 v = *(const uint4*)(d_Mh + ((size_t)(i * 64 + c)) * 4096 + pbeg + q * 8);
        *(uint4*)&sM[c * 264 + q * 8] = v;
    }
    if (tid < 64) s_b1[tid] = b1[tid];
    if (tid < 192) s_w2[tid] = w2[tid];
    if (tid < 3) {
        s_b2[tid] = b2[tid];
        int ip = (i + 32) & 63;
        int idx = tid * 64 + ip;
        s_lf0[tid] = logf(f0[idx]);
        float ls = logf(sigma[idx]);
        s_i2ls2[tid] = 1.f / (2.f * ls * ls);
        s_th[tid] = theta[idx];
        float t0v = theta0[idx];
        s_i2t02[tid] = 1.f / (2.f * t0v * t0v);
    }
    __syncthreads();

    const int wid = tid >> 5, lane = tid & 31;
    const int o0 = (wid & 3) << 4, pw = (wid >> 2) << 7;
    const uint32_t sA_addr = (uint32_t)__cvta_generic_to_shared(sA);
    const uint32_t sM_addr = (uint32_t)__cvta_generic_to_shared(sM);

    uint32_t a[4][4];
#pragma unroll
    for (int ks = 0; ks < 4; ks++) {
        uint32_t addr = sA_addr + (uint32_t)(((o0 + (lane & 15)) * 72 + ks * 16 + ((lane >> 4) << 3)) * 2);
        ldsm_x4(a[ks], addr);
    }
    float acc[16][4];
#pragma unroll
    for (int j = 0; j < 16; j++)
#pragma unroll
        for (int q = 0; q < 4; q++) acc[j][q] = 0.f;
#pragma unroll
    for (int j = 0; j < 16; j++) {
#pragma unroll
        for (int ks = 0; ks < 4; ks++) {
            uint32_t b[2];
            uint32_t addr = sM_addr + (uint32_t)(((ks * 16 + (lane & 15)) * 264 + pw + j * 8) * 2);
            ldsm_x2_trans(b, addr);
            mma16816(acc[j], a[ks], b);
        }
    }
    __syncthreads();

    {
        const int r0 = o0 + (lane >> 2);
        const int cbase = pw + (lane & 3) * 2;
        float b1a = s_b1[r0], b1b = s_b1[r0 + 8];
#pragma unroll
        for (int j = 0; j < 16; j++) {
            int c = cbase + j * 8;
            *(__half2*)&sM[r0 * 264 + c] =
                __floats2half2_rn(fmaxf(acc[j][0] + b1a, 0.f), fmaxf(acc[j][1] + b1a, 0.f));
            *(__half2*)&sM[(r0 + 8) * 264 + c] =
                __floats2half2_rn(fmaxf(acc[j][2] + b1b, 0.f), fmaxf(acc[j][3] + b1b, 0.f));
        }
    }
    __syncthreads();

    {
        float l0 = s_b2[0], l1 = s_b2[1], l2 = s_b2[2];
#pragma unroll
        for (int o = 0; o < 64; o++) {
            float hv = __half2float(sM[o * 264 + tid]);
            l0 = fmaf(s_w2[o], hv, l0);
            l1 = fmaf(s_w2[64 + o], hv, l1);
            l2 = fmaf(s_w2[128 + o], hv, l2);
        }
        float mx = fmaxf(l0, fmaxf(l1, l2));
        float e0 = __expf(l0 - mx), e1 = __expf(l1 - mx), e2 = __expf(l2 - mx);
        float inv = 1.f / (e0 + e1 + e2);
        const int p = pbeg + tid;
        int hh = ((p >> 6) + 32) & 63;
        int ww = ((p & 63) + 32) & 63;
        float yv_ = -1.f + 2.f * (float)hh * (1.f / 63.f);
        float xv_ = -1.f + 2.f * (float)ww * (1.f / 63.f);
        float r2 = xv_ * xv_ + yv_ * yv_ + 1e-6f;
        float lr = 0.5f * logf(r2);
        float phi = atan2f(yv_, xv_);
        float G = 0.f;
        float awv[3] = {e0 * inv, e1 * inv, e2 * inv};
#pragma unroll
        for (int s = 0; s < 3; s++) {
            float dl = lr - s_lf0[s];
            float dp = phi - s_th[s];
            float F = __expf(-(dl * dl) * s_i2ls2[s] - (dp * dp) * s_i2t02[s]);
            G = fmaf(F, awv[s], G);
        }
        d_G[i * 4096 + p] = G;
    }
}

// ---------------- kernel 3: two-for-one masked filter + IFFT + mix ----------------
__global__ __launch_bounds__(512, 2) void inv_kernel(const float* __restrict__ x,
                                                     const float* __restrict__ fbs,
                                                     const float* __restrict__ mixp,
                                                     float* __restrict__ out) {
    __shared__ float2 sm[FFT_SM_F2];
    __shared__ float2 s_tw[64];
    const int plane = blockIdx.x;
    const int b = plane >> 6, i = plane & 63;
    const int tid = threadIdx.x;
    const float mix = mixp[0];
    const float c1 = 1.f - mix;
    const int bb = (b + 32) & 63;
    const int si = (int)floorf((fbs[bb * 2 + 0] + 1.f) * 0.5f * 64.f);
    const int ei = (int)floorf((fbs[bb * 2 + 1] + 1.f) * 0.5f * 64.f);
    const int ii = (i + 32) & 63;
    const float4* sb4 = ((const float4*)d_sp) + (size_t)b * 1024;

    if (!(ii >= si && ii < ei)) {  // non-survivor: conv-only output
        float4* op4 = (float4*)(out + (size_t)plane * 4096);
#pragma unroll
        for (int q = tid; q < 1024; q += 512) {
            float4 s = sb4[q];
            op4[q] = make_float4(c1 * s.x, c1 * s.y, c1 * s.z, c1 * s.w);
        }
        return;
    }
    const int j = ii - si;
    if (j & 1) return;              // handled by partner block (i-1)
    const bool haspart = (ii + 1 < ei);

    if (tid < 64) {
        float sn, cs;
        __sincosf(-6.283185307179586f * (float)tid * (1.0f / 64.0f), &sn, &cs);
        s_tw[tid] = make_float2(cs, sn);
    }
    __syncthreads();
    const float* xp0 = x + (size_t)plane * 4096;
    const float* xp1 = xp0 + 4096;
    {
        const int g = tid >> 3, t = tid & 7;
        ull v[8];
#pragma unroll
        for (int n1 = 0; n1 < 8; n1++) {
            int idx = g * 64 + 8 * n1 + t;
            v[n1] = PK(xp0[idx], haspart ? xp1[idx] : 0.f);
        }
        row_pass_reg<-1>(v, sm, s_tw, tid);
    }
    __syncthreads();
    fft_pass<-1, false>(sm, s_tw, tid);
    __syncthreads();
    const float* G0 = d_G + i * 4096;
    const float* G1 = d_G + (i + 1) * 4096;
    float2 P[8];
#pragma unroll
    for (int n = 0; n < 8; n++) {
        int k = tid + n * 512;
        int r = k >> 6, c = k & 63;
        int rm = (64 - r) & 63, cm = (64 - c) & 63;
        int km = rm * 64 + cm;
        float2 Zk = sm[fft_phys(r, c)];
        float2 Zm = sm[fft_phys(rm, cm)];
        int hh = (r + 32) & 63, hhm = (rm + 32) & 63;
        float mr = (hh >= si && hh < ei) ? 0.5f : 0.f;
        float mrm = (hhm >= si && hhm < ei) ? 0.5f : 0.f;
        float g0 = G0[k] * mr + G0[km] * mrm;
        float g1 = haspart ? (G1[k] * mr + G1[km] * mrm) : 0.f;
        float y0x = 0.5f * (Zk.x + Zm.x), y0y = 0.5f * (Zk.y - Zm.y);
        float y1x = 0.5f * (Zk.y + Zm.y), y1y = -0.5f * (Zk.x - Zm.x);
        P[n] = make_float2(y0x * g0 - g1 * y1y, y0y * g0 + g1 * y1x);
    }
    __syncthreads();
#pragma unroll
    for (int n = 0; n < 8; n++) {
        int k = tid + n * 512;
        sm[fft_phys(k >> 6, k & 63)] = P[n];
    }
    __syncthreads();
    fft_pass<1, true>(sm, s_tw, tid);
    __syncthreads();
    fft_pass<1, false>(sm, s_tw, tid);
    __syncthreads();
    const float scale = mix * (1.f / 4096.f);
    float4* op0 = (float4*)(out + (size_t)plane * 4096);
    float4* op1 = (float4*)(out + (size_t)(plane + 1) * 4096);
#pragma unroll
    for (int q = tid; q < 1024; q += 512) {
        int r = q >> 4, c = (q & 15) * 4;
        float2 w0 = sm[fft_phys(r, c + 0)];
        float2 w1v = sm[fft_phys(r, c + 1)];
        float2 w2v = sm[fft_phys(r, c + 2)];
        float2 w3 = sm[fft_phys(r, c + 3)];
        float4 s = sb4[q];
        op0[q] = make_float4(fmaf(scale, w0.x, c1 * s.x), fmaf(scale, w1v.x, c1 * s.y),
                             fmaf(scale, w2v.x, c1 * s.z), fmaf(scale, w3.x, c1 * s.w));
        if (haspart)
            op1[q] = make_float4(fmaf(scale, w0.y, c1 * s.x), fmaf(scale, w1v.y, c1 * s.y),
                                 fmaf(scale, w2v.y, c1 * s.z), fmaf(scale, w3.y, c1 * s.w));
    }
}

// ---------------- launch ----------------
extern "C" void kernel_launch(void* const* d_in, const int* in_sizes, int n_in,
                              void* d_out, int out_size) {
    const float* x      = (const float*)d_in[0];
    const float* f0     = (const float*)d_in[1];
    const float* theta  = (const float*)d_in[2];
    const float* sigma  = (const float*)d_in[3];
    const float* theta0 = (const float*)d_in[4];
    const float* fbs    = (const float*)d_in[5];
    const float* mix    = (const float*)d_in[6];
    const float* w1     = (const float*)d_in[7];
    const float* b1     = (const float*)d_in[8];
    const float* w2     = (const float*)d_in[9];
    const float* b2     = (const float*)d_in[10];
    const float* conv_w = (const float*)d_in[11];
    float* out = (float*)d_out;

    k1_fft_conv<<<2304, 512>>>(x, conv_w);
    attn_kernel<<<1088, 256>>>(f0, theta, sigma, theta0, w1, b1, w2, b2);
    inv_kernel<<<4096, 512>>>(x, fbs, mix, out);
}

// round 9
// speedup vs baseline: 4.9014x; 1.3335x over previous
#include <cuda_runtime.h>
#include <cuda_fp16.h>
#include <math.h>
#include <stdint.h>

typedef unsigned long long ull;

// ---------------- device scratch (no allocs allowed) ----------------
__device__ __align__(16) __half d_Mh[4096ull * 4096ull];  // |FFT| magnitudes, fp16, 32MB
__device__ float d_G[64 * 4096];                          // G'[i,h,w], 1MB
__device__ float d_sp4[4 * 64 * 4096];                    // conv partials, 4MB
__device__ float d_sp[64 * 4096];                         // reduced conv, 1MB

// ---------------- packed f32x2 helpers ----------------
__device__ __forceinline__ ull PK(float x, float y) {
    ull r; asm("mov.b64 %0,{%1,%2};" : "=l"(r) : "f"(x), "f"(y)); return r;
}
__device__ __forceinline__ float2 UPK(ull v) {
    float2 r; asm("mov.b64 {%0,%1},%2;" : "=f"(r.x), "=f"(r.y) : "l"(v)); return r;
}
__device__ __forceinline__ ull PADD(ull a, ull b) {
    ull d; asm("add.rn.f32x2 %0,%1,%2;" : "=l"(d) : "l"(a), "l"(b)); return d;
}
__device__ __forceinline__ ull PFMA(ull a, ull b, ull c) {
    ull d; asm("fma.rn.f32x2 %0,%1,%2,%3;" : "=l"(d) : "l"(a), "l"(b), "l"(c)); return d;
}
__device__ __forceinline__ ull PSUB(ull a, ull b) {  // a - b = b*(-1) + a
    return PFMA(b, PK(-1.f, -1.f), a);
}

// ---------------- MMA helpers ----------------
__device__ __forceinline__ void ldsm_x4(uint32_t (&r)[4], uint32_t addr) {
    asm volatile("ldmatrix.sync.aligned.m8n8.x4.shared.b16 {%0,%1,%2,%3}, [%4];"
                 : "=r"(r[0]), "=r"(r[1]), "=r"(r[2]), "=r"(r[3]) : "r"(addr));
}
__device__ __forceinline__ void ldsm_x2_trans(uint32_t (&r)[2], uint32_t addr) {
    asm volatile("ldmatrix.sync.aligned.m8n8.x2.trans.shared.b16 {%0,%1}, [%2];"
                 : "=r"(r[0]), "=r"(r[1]) : "r"(addr));
}
__device__ __forceinline__ void mma16816(float (&d)[4], const uint32_t (&a)[4], const uint32_t (&b)[2]) {
    asm volatile(
        "mma.sync.aligned.m16n8k16.row.col.f32.f16.f16.f32 "
        "{%0,%1,%2,%3},{%4,%5,%6,%7},{%8,%9},{%0,%1,%2,%3};"
        : "+f"(d[0]), "+f"(d[1]), "+f"(d[2]), "+f"(d[3])
        : "r"(a[0]), "r"(a[1]), "r"(a[2]), "r"(a[3]), "r"(b[0]), "r"(b[1]));
}

// ---------------- FFT smem layout ----------------
#define FFT_SM_F2 (64 * 72)
__device__ __forceinline__ int fft_phys(int r, int c) { return r * 72 + (c ^ (r & 7)); }

// 8-point DIF FFT on packed complex (re,im) in f32x2 registers. SGN=-1 fwd, +1 inv.
template <int SGN>
__device__ __forceinline__ void fft8p(ull v[8]) {
    const float S = (float)SGN;
    const float C = 0.70710678118654752440f;
    ull t0 = PADD(v[0], v[4]), t4 = PSUB(v[0], v[4]);
    ull t1 = PADD(v[1], v[5]), t5 = PSUB(v[1], v[5]);
    ull t2 = PADD(v[2], v[6]), t6 = PSUB(v[2], v[6]);
    ull t3 = PADD(v[3], v[7]), t7 = PSUB(v[3], v[7]);
    float2 f5 = UPK(t5), f6 = UPK(t6), f7 = UPK(t7);
    t5 = PK(C * (f5.x - S * f5.y), C * (S * f5.x + f5.y));
    t6 = PK(-S * f6.y, S * f6.x);
    t7 = PK(C * (-f7.x - S * f7.y), C * (S * f7.x - f7.y));
    ull u0 = PADD(t0, t2), u2 = PSUB(t0, t2);
    ull u1 = PADD(t1, t3);
    float2 d13 = UPK(PSUB(t1, t3));
    ull u3 = PK(-S * d13.y, S * d13.x);
    ull u4 = PADD(t4, t6), u6 = PSUB(t4, t6);
    ull u5 = PADD(t5, t7);
    float2 d57 = UPK(PSUB(t5, t7));
    ull u7 = PK(-S * d57.y, S * d57.x);
    v[0] = PADD(u0, u1); v[4] = PSUB(u0, u1);
    v[2] = PADD(u2, u3); v[6] = PSUB(u2, u3);
    v[1] = PADD(u4, u5); v[5] = PSUB(u4, u5);
    v[3] = PADD(u6, u7); v[7] = PSUB(u6, u7);
}

__device__ __forceinline__ ull tw_mul(ull z, float2 w) {
    float2 f = UPK(z);
    return PK(f.x * w.x - f.y * w.y, f.x * w.y + f.y * w.x);
}

// Row pass with input already in registers (v[n1] = z[g][8*n1+t]).
template <int SGN>
__device__ __forceinline__ void row_pass_reg(ull v[8], float2* smf, const float2* s_tw, int tid) {
    ull* sm = (ull*)smf;
    const int g = tid >> 3, t = tid & 7;
    fft8p<SGN>(v);
#pragma unroll
    for (int k1 = 1; k1 < 8; k1++) {
        float2 w = s_tw[(t * k1) & 63];
        if (SGN == 1) w.y = -w.y;
        v[k1] = tw_mul(v[k1], w);
    }
    __syncwarp();
#pragma unroll
    for (int k1 = 0; k1 < 8; k1++) sm[fft_phys(g, 8 * k1 + (t ^ k1))] = v[k1];
    __syncwarp();
#pragma unroll
    for (int n2 = 0; n2 < 8; n2++) v[n2] = sm[fft_phys(g, 8 * t + (n2 ^ t))];
    fft8p<SGN>(v);
    __syncwarp();
#pragma unroll
    for (int k2 = 0; k2 < 8; k2++) sm[fft_phys(g, t + 8 * k2)] = v[k2];
}

// One pass (rows or cols) of a 64x64 2D FFT in shared memory (LDS-sourced).
template <int SGN, bool ROWS>
__device__ __forceinline__ void fft_pass(float2* smf, const float2* s_tw, int tid) {
    ull* sm = (ull*)smf;
    const int g = tid >> 3;
    const int t = tid & 7;
#define LIDX(m) (ROWS ? fft_phys(g, (m)) : fft_phys((m), g))
    ull v[8];
#pragma unroll
    for (int n1 = 0; n1 < 8; n1++) v[n1] = sm[LIDX(8 * n1 + t)];
    fft8p<SGN>(v);
#pragma unroll
    for (int k1 = 1; k1 < 8; k1++) {
        float2 w = s_tw[(t * k1) & 63];
        if (SGN == 1) w.y = -w.y;
        v[k1] = tw_mul(v[k1], w);
    }
    __syncwarp();
#pragma unroll
    for (int k1 = 0; k1 < 8; k1++) sm[LIDX(8 * k1 + (t ^ k1))] = v[k1];
    __syncwarp();
#pragma unroll
    for (int n2 = 0; n2 < 8; n2++) v[n2] = sm[LIDX(8 * t + (n2 ^ t))];
    fft8p<SGN>(v);
    __syncwarp();
#pragma unroll
    for (int k2 = 0; k2 < 8; k2++) sm[LIDX(t + 8 * k2)] = v[k2];
#undef LIDX
}

// needed(B): does G[B] (built from batch-B magnitudes) feed any surviving plane?
// Survivor (b, i=B) exists iff (B+32)&63 in [si(m), ei(m)) for some m.
// Threads 0..63 each test one m; flag reduced through shared memory.
__device__ __forceinline__ bool batch_needed(const float* __restrict__ fbs, int B,
                                             int tid, int* s_flag) {
    if (tid == 0) *s_flag = 0;
    __syncthreads();
    if (tid < 64) {
        int si = (int)floorf((fbs[tid * 2 + 0] + 1.f) * 0.5f * 64.f);
        int ei = (int)floorf((fbs[tid * 2 + 1] + 1.f) * 0.5f * 64.f);
        int iB = (B + 32) & 63;
        if (iB >= si && iB < ei) *s_flag = 1;  // benign same-value race
    }
    __syncthreads();
    return *s_flag != 0;
}

// ---------------- kernel 1: fused [two-for-one fwd FFT -> fp16 mags] + [3x3 conv] ----------------
// Blocks [0,2048): FFT of plane pair (b, 2u), (b, 2u+1) — skipped when batch b unused.
// Blocks [2048,2304): conv.
__global__ __launch_bounds__(512, 2) void k1_fft_conv(const float* __restrict__ x,
                                                      const float* __restrict__ cw,
                                                      const float* __restrict__ fbs) {
    __shared__ __align__(16) char sh[FFT_SM_F2 * 8 + 512];
    __shared__ int s_flag;
    const int tid = threadIdx.x;

    if (blockIdx.x < 2048) {
        const int b = blockIdx.x >> 5;
        if (!batch_needed(fbs, b, tid, &s_flag)) return;  // dead magnitudes
        float2* sm = (float2*)sh;
        float2* s_tw = (float2*)(sh + FFT_SM_F2 * 8);
        const int i0 = (blockIdx.x & 31) * 2;
        if (tid < 64) {
            float sn, cs;
            __sincosf(-6.283185307179586f * (float)tid * (1.0f / 64.0f), &sn, &cs);
            s_tw[tid] = make_float2(cs, sn);
        }
        __syncthreads();
        const float* xp0 = x + ((size_t)(b * 64 + i0)) * 4096;
        const float* xp1 = xp0 + 4096;
        {
            const int g = tid >> 3, t = tid & 7;
            ull v[8];
#pragma unroll
            for (int n1 = 0; n1 < 8; n1++) {
                int idx = g * 64 + 8 * n1 + t;
                v[n1] = PK(xp0[idx], xp1[idx]);
            }
            row_pass_reg<-1>(v, sm, s_tw, tid);
        }
        __syncthreads();
        fft_pass<-1, false>(sm, s_tw, tid);
        __syncthreads();
        __half* m0 = d_Mh + ((size_t)(b * 64 + i0)) * 4096;
        __half* m1 = m0 + 4096;
#pragma unroll
        for (int n = 0; n < 8; n++) {
            int k = tid + n * 512;
            int r = k >> 6, c = k & 63;
            float2 Zk = sm[fft_phys(r, c)];
            float2 Zm = sm[fft_phys((64 - r) & 63, (64 - c) & 63)];
            float sx = Zk.x + Zm.x, sy = Zk.y - Zm.y;
            float dx = Zk.x - Zm.x, dy = Zk.y + Zm.y;
            m0[k] = __float2half(0.5f * sqrtf(sx * sx + sy * sy));
            m1[k] = __float2half(0.5f * sqrtf(dx * dx + dy * dy));
        }
    } else {
        // ---- conv path: vertical 8-row windows + f32x2 packed accumulation ----
        float* sp = (float*)sh;
        float* sw = (float*)(sh + 17424);
        const int idx = blockIdx.x - 2048;
        const int b = idx & 63, cg = idx >> 6;
        const int c0 = cg * 16;
        const int ww = tid & 63, hb8 = (tid >> 6) * 8;
        for (int k = tid; k < 66 * 66; k += 512) sp[k] = 0.f;
        for (int k = tid; k < 144; k += 512) sw[k] = cw[c0 * 9 + k];
        ull acc2[4];
#pragma unroll
        for (int q = 0; q < 4; q++) acc2[q] = PK(0.f, 0.f);
        const float* xb = x + ((size_t)b * 64 + c0) * 4096;
        for (int c = 0; c < 16; c++) {
            __syncthreads();
            for (int k = tid; k < 4096; k += 512)
                sp[((k >> 6) + 1) * 66 + (k & 63) + 1] = xb[c * 4096 + k];
            __syncthreads();
            ull wd[9];
#pragma unroll
            for (int j = 0; j < 9; j++) {
                float wv = sw[c * 9 + j];
                wd[j] = PK(wv, wv);
            }
#pragma unroll
            for (int kw = 0; kw < 3; kw++) {
                float wcol[10];
#pragma unroll
                for (int rr = 0; rr < 10; rr++) wcol[rr] = sp[(hb8 + rr) * 66 + ww + kw];
                ull pkc[6];
#pragma unroll
                for (int j = 0; j < 6; j++) pkc[j] = PK(wcol[j], wcol[j + 4]);
#pragma unroll
                for (int q = 0; q < 4; q++)
#pragma unroll
                    for (int kh = 0; kh < 3; kh++)
                        acc2[q] = PFMA(pkc[q + kh], wd[kh * 3 + kw], acc2[q]);
            }
        }
        float* o = d_sp4 + ((size_t)cg * 64 + b) * 4096;
#pragma unroll
        for (int q = 0; q < 4; q++) {
            float2 a = UPK(acc2[q]);
            o[(hb8 + q) * 64 + ww] = a.x;
            o[(hb8 + q + 4) * 64 + ww] = a.y;
        }
    }
}

// ---------------- kernel 2: tensor-core attention + log-Gabor -> G' (+ conv reduce) ----------------
__global__ __launch_bounds__(256, 2) void attn_kernel(
    const float* __restrict__ f0, const float* __restrict__ theta,
    const float* __restrict__ sigma, const float* __restrict__ theta0,
    const float* __restrict__ w1, const float* __restrict__ b1,
    const float* __restrict__ w2, const float* __restrict__ b2,
    const float* __restrict__ fbs) {
    const int tid = threadIdx.x;
    if (blockIdx.x >= 1024) {  // conv reduce
        const int b = blockIdx.x - 1024;
        const float4* A = ((const float4*)d_sp4) + (size_t)b * 1024;
        float4* O = ((float4*)d_sp) + (size_t)b * 1024;
#pragma unroll
        for (int q = tid; q < 1024; q += 256) {
            float4 s0 = A[q], s1 = A[q + 65536], s2 = A[q + 131072], s3 = A[q + 196608];
            O[q] = make_float4((s0.x + s1.x) + (s2.x + s3.x), (s0.y + s1.y) + (s2.y + s3.y),
                               (s0.z + s1.z) + (s2.z + s3.z), (s0.w + s1.w) + (s2.w + s3.w));
        }
        return;
    }
    __shared__ int s_flag;
    const int i = blockIdx.x >> 4;
    if (!batch_needed(fbs, i, tid, &s_flag)) return;  // G[i] never read
    __shared__ __align__(16) __half sA[64 * 72];
    __shared__ __align__(16) __half sM[64 * 264];
    __shared__ float s_w2[3 * 64];
    __shared__ float s_b1[64];
    __shared__ float s_lf0[3], s_i2ls2[3], s_th[3], s_i2t02[3], s_b2[3];
    const int pbeg = (blockIdx.x & 15) * 256;

    for (int k = tid; k < 4096; k += 256) {
        int o = k >> 6, c = k & 63;
        sA[o * 72 + c] = __float2half(w1[o * 64 + ((c + 32) & 63)]);
    }
    for (int t = tid; t < 2048; t += 256) {
        int c = t >> 5, q = t & 31;
        uint4 v = *(const uint4*)(d_Mh + ((size_t)(i * 64 + c)) * 4096 + pbeg + q * 8);
        *(uint4*)&sM[c * 264 + q * 8] = v;
    }
    if (tid < 64) s_b1[tid] = b1[tid];
    if (tid < 192) s_w2[tid] = w2[tid];
    if (tid < 3) {
        s_b2[tid] = b2[tid];
        int ip = (i + 32) & 63;
        int idx = tid * 64 + ip;
        s_lf0[tid] = logf(f0[idx]);
        float ls = logf(sigma[idx]);
        s_i2ls2[tid] = 1.f / (2.f * ls * ls);
        s_th[tid] = theta[idx];
        float t0v = theta0[idx];
        s_i2t02[tid] = 1.f / (2.f * t0v * t0v);
    }
    __syncthreads();

    const int wid = tid >> 5, lane = tid & 31;
    const int o0 = (wid & 3) << 4, pw = (wid >> 2) << 7;
    const uint32_t sA_addr = (uint32_t)__cvta_generic_to_shared(sA);
    const uint32_t sM_addr = (uint32_t)__cvta_generic_to_shared(sM);

    uint32_t a[4][4];
#pragma unroll
    for (int ks = 0; ks < 4; ks++) {
        uint32_t addr = sA_addr + (uint32_t)(((o0 + (lane & 15)) * 72 + ks * 16 + ((lane >> 4) << 3)) * 2);
        ldsm_x4(a[ks], addr);
    }
    float acc[16][4];
#pragma unroll
    for (int j = 0; j < 16; j++)
#pragma unroll
        for (int q = 0; q < 4; q++) acc[j][q] = 0.f;
#pragma unroll
    for (int j = 0; j < 16; j++) {
#pragma unroll
        for (int ks = 0; ks < 4; ks++) {
            uint32_t b[2];
            uint32_t addr = sM_addr + (uint32_t)(((ks * 16 + (lane & 15)) * 264 + pw + j * 8) * 2);
            ldsm_x2_trans(b, addr);
            mma16816(acc[j], a[ks], b);
        }
    }
    __syncthreads();

    {
        const int r0 = o0 + (lane >> 2);
        const int cbase = pw + (lane & 3) * 2;
        float b1a = s_b1[r0], b1b = s_b1[r0 + 8];
#pragma unroll
        for (int j = 0; j < 16; j++) {
            int c = cbase + j * 8;
            *(__half2*)&sM[r0 * 264 + c] =
                __floats2half2_rn(fmaxf(acc[j][0] + b1a, 0.f), fmaxf(acc[j][1] + b1a, 0.f));
            *(__half2*)&sM[(r0 + 8) * 264 + c] =
                __floats2half2_rn(fmaxf(acc[j][2] + b1b, 0.f), fmaxf(acc[j][3] + b1b, 0.f));
        }
    }
    __syncthreads();

    {
        float l0 = s_b2[0], l1 = s_b2[1], l2 = s_b2[2];
#pragma unroll
        for (int o = 0; o < 64; o++) {
            float hv = __half2float(sM[o * 264 + tid]);
            l0 = fmaf(s_w2[o], hv, l0);
            l1 = fmaf(s_w2[64 + o], hv, l1);
            l2 = fmaf(s_w2[128 + o], hv, l2);
        }
        float mx = fmaxf(l0, fmaxf(l1, l2));
        float e0 = __expf(l0 - mx), e1 = __expf(l1 - mx), e2 = __expf(l2 - mx);
        float inv = 1.f / (e0 + e1 + e2);
        const int p = pbeg + tid;
        int hh = ((p >> 6) + 32) & 63;
        int ww = ((p & 63) + 32) & 63;
        float yv_ = -1.f + 2.f * (float)hh * (1.f / 63.f);
        float xv_ = -1.f + 2.f * (float)ww * (1.f / 63.f);
        float r2 = xv_ * xv_ + yv_ * yv_ + 1e-6f;
        float lr = 0.5f * logf(r2);
        float phi = atan2f(yv_, xv_);
        float G = 0.f;
        float awv[3] = {e0 * inv, e1 * inv, e2 * inv};
#pragma unroll
        for (int s = 0; s < 3; s++) {
            float dl = lr - s_lf0[s];
            float dp = phi - s_th[s];
            float F = __expf(-(dl * dl) * s_i2ls2[s] - (dp * dp) * s_i2t02[s]);
            G = fmaf(F, awv[s], G);
        }
        d_G[i * 4096 + p] = G;
    }
}

// ---------------- kernel 3: two-for-one masked filter + IFFT + mix ----------------
__global__ __launch_bounds__(512, 2) void inv_kernel(const float* __restrict__ x,
                                                     const float* __restrict__ fbs,
                                                     const float* __restrict__ mixp,
                                                     float* __restrict__ out) {
    __shared__ float2 sm[FFT_SM_F2];
    __shared__ float2 s_tw[64];
    const int plane = blockIdx.x;
    const int b = plane >> 6, i = plane & 63;
    const int tid = threadIdx.x;
    const float mix = mixp[0];
    const float c1 = 1.f - mix;
    const int bb = (b + 32) & 63;
    const int si = (int)floorf((fbs[bb * 2 + 0] + 1.f) * 0.5f * 64.f);
    const int ei = (int)floorf((fbs[bb * 2 + 1] + 1.f) * 0.5f * 64.f);
    const int ii = (i + 32) & 63;
    const float4* sb4 = ((const float4*)d_sp) + (size_t)b * 1024;

    if (!(ii >= si && ii < ei)) {  // non-survivor: conv-only output
        float4* op4 = (float4*)(out + (size_t)plane * 4096);
#pragma unroll
        for (int q = tid; q < 1024; q += 512) {
            float4 s = sb4[q];
            op4[q] = make_float4(c1 * s.x, c1 * s.y, c1 * s.z, c1 * s.w);
        }
        return;
    }
    const int j = ii - si;
    if (j & 1) return;              // handled by partner block (i-1)
    const bool haspart = (ii + 1 < ei);

    if (tid < 64) {
        float sn, cs;
        __sincosf(-6.283185307179586f * (float)tid * (1.0f / 64.0f), &sn, &cs);
        s_tw[tid] = make_float2(cs, sn);
    }
    __syncthreads();
    const float* xp0 = x + (size_t)plane * 4096;
    const float* xp1 = xp0 + 4096;
    {
        const int g = tid >> 3, t = tid & 7;
        ull v[8];
#pragma unroll
        for (int n1 = 0; n1 < 8; n1++) {
            int idx = g * 64 + 8 * n1 + t;
            v[n1] = PK(xp0[idx], haspart ? xp1[idx] : 0.f);
        }
        row_pass_reg<-1>(v, sm, s_tw, tid);
    }
    __syncthreads();
    fft_pass<-1, false>(sm, s_tw, tid);
    __syncthreads();
    const float* G0 = d_G + i * 4096;
    const float* G1 = d_G + (i + 1) * 4096;
    float2 P[8];
#pragma unroll
    for (int n = 0; n < 8; n++) {
        int k = tid + n * 512;
        int r = k >> 6, c = k & 63;
        int rm = (64 - r) & 63, cm = (64 - c) & 63;
        int km = rm * 64 + cm;
        float2 Zk = sm[fft_phys(r, c)];
        float2 Zm = sm[fft_phys(rm, cm)];
        int hh = (r + 32) & 63, hhm = (rm + 32) & 63;
        float mr = (hh >= si && hh < ei) ? 0.5f : 0.f;
        float mrm = (hhm >= si && hhm < ei) ? 0.5f : 0.f;
        float g0 = G0[k] * mr + G0[km] * mrm;
        float g1 = haspart ? (G1[k] * mr + G1[km] * mrm) : 0.f;
        float y0x = 0.5f * (Zk.x + Zm.x), y0y = 0.5f * (Zk.y - Zm.y);
        float y1x = 0.5f * (Zk.y + Zm.y), y1y = -0.5f * (Zk.x - Zm.x);
        P[n] = make_float2(y0x * g0 - g1 * y1y, y0y * g0 + g1 * y1x);
    }
    __syncthreads();
#pragma unroll
    for (int n = 0; n < 8; n++) {
        int k = tid + n * 512;
        sm[fft_phys(k >> 6, k & 63)] = P[n];
    }
    __syncthreads();
    fft_pass<1, true>(sm, s_tw, tid);
    __syncthreads();
    fft_pass<1, false>(sm, s_tw, tid);
    __syncthreads();
    const float scale = mix * (1.f / 4096.f);
    float4* op0 = (float4*)(out + (size_t)plane * 4096);
    float4* op1 = (float4*)(out + (size_t)(plane + 1) * 4096);
#pragma unroll
    for (int q = tid; q < 1024; q += 512) {
        int r = q >> 4, c = (q & 15) * 4;
        float2 w0 = sm[fft_phys(r, c + 0)];
        float2 w1v = sm[fft_phys(r, c + 1)];
        float2 w2v = sm[fft_phys(r, c + 2)];
        float2 w3 = sm[fft_phys(r, c + 3)];
        float4 s = sb4[q];
        op0[q] = make_float4(fmaf(scale, w0.x, c1 * s.x), fmaf(scale, w1v.x, c1 * s.y),
                             fmaf(scale, w2v.x, c1 * s.z), fmaf(scale, w3.x, c1 * s.w));
        if (haspart)
            op1[q] = make_float4(fmaf(scale, w0.y, c1 * s.x), fmaf(scale, w1v.y, c1 * s.y),
                                 fmaf(scale, w2v.y, c1 * s.z), fmaf(scale, w3.y, c1 * s.w));
    }
}

// ---------------- launch ----------------
extern "C" void kernel_launch(void* const* d_in, const int* in_sizes, int n_in,
                              void* d_out, int out_size) {
    const float* x      = (const float*)d_in[0];
    const float* f0     = (const float*)d_in[1];
    const float* theta  = (const float*)d_in[2];
    const float* sigma  = (const float*)d_in[3];
    const float* theta0 = (const float*)d_in[4];
    const float* fbs    = (const float*)d_in[5];
    const float* mix    = (const float*)d_in[6];
    const float* w1     = (const float*)d_in[7];
    const float* b1     = (const float*)d_in[8];
    const float* w2     = (const float*)d_in[9];
    const float* b2     = (const float*)d_in[10];
    const float* conv_w = (const float*)d_in[11];
    float* out = (float*)d_out;

    k1_fft_conv<<<2304, 512>>>(x, conv_w, fbs);
    attn_kernel<<<1088, 256>>>(f0, theta, sigma, theta0, w1, b1, w2, b2, fbs);
    inv_kernel<<<4096, 512>>>(x, fbs, mix, out);
}

// round 10
// speedup vs baseline: 5.7957x; 1.1824x over previous
#include <cuda_runtime.h>
#include <cuda_fp16.h>
#include <math.h>
#include <stdint.h>

typedef unsigned long long ull;

// ---------------- device scratch (no allocs allowed) ----------------
__device__ __align__(16) __half d_Mh[4096ull * 4096ull];  // |FFT| magnitudes, fp16, 32MB
__device__ float d_G[64 * 4096];                          // G'[i,h,w], 1MB
__device__ float d_sp4[16 * 64 * 4096];                   // conv partials (16 groups), 16MB
__device__ float d_sp[64 * 4096];                         // reduced conv, 1MB

// ---------------- packed f32x2 helpers ----------------
__device__ __forceinline__ ull PK(float x, float y) {
    ull r; asm("mov.b64 %0,{%1,%2};" : "=l"(r) : "f"(x), "f"(y)); return r;
}
__device__ __forceinline__ float2 UPK(ull v) {
    float2 r; asm("mov.b64 {%0,%1},%2;" : "=f"(r.x), "=f"(r.y) : "l"(v)); return r;
}
__device__ __forceinline__ ull PADD(ull a, ull b) {
    ull d; asm("add.rn.f32x2 %0,%1,%2;" : "=l"(d) : "l"(a), "l"(b)); return d;
}
__device__ __forceinline__ ull PFMA(ull a, ull b, ull c) {
    ull d; asm("fma.rn.f32x2 %0,%1,%2,%3;" : "=l"(d) : "l"(a), "l"(b), "l"(c)); return d;
}
__device__ __forceinline__ ull PSUB(ull a, ull b) {
    return PFMA(b, PK(-1.f, -1.f), a);
}

// ---------------- MMA helpers ----------------
__device__ __forceinline__ void ldsm_x4(uint32_t (&r)[4], uint32_t addr) {
    asm volatile("ldmatrix.sync.aligned.m8n8.x4.shared.b16 {%0,%1,%2,%3}, [%4];"
                 : "=r"(r[0]), "=r"(r[1]), "=r"(r[2]), "=r"(r[3]) : "r"(addr));
}
__device__ __forceinline__ void ldsm_x2_trans(uint32_t (&r)[2], uint32_t addr) {
    asm volatile("ldmatrix.sync.aligned.m8n8.x2.trans.shared.b16 {%0,%1}, [%2];"
                 : "=r"(r[0]), "=r"(r[1]) : "r"(addr));
}
__device__ __forceinline__ void mma16816(float (&d)[4], const uint32_t (&a)[4], const uint32_t (&b)[2]) {
    asm volatile(
        "mma.sync.aligned.m16n8k16.row.col.f32.f16.f16.f32 "
        "{%0,%1,%2,%3},{%4,%5,%6,%7},{%8,%9},{%0,%1,%2,%3};"
        : "+f"(d[0]), "+f"(d[1]), "+f"(d[2]), "+f"(d[3])
        : "r"(a[0]), "r"(a[1]), "r"(a[2]), "r"(a[3]), "r"(b[0]), "r"(b[1]));
}

// ---------------- FFT smem layout ----------------
#define FFT_SM_F2 (64 * 72)
__device__ __forceinline__ int fft_phys(int r, int c) { return r * 72 + (c ^ (r & 7)); }

// 8-point DIF FFT on packed complex (re,im) in f32x2 registers. SGN=-1 fwd, +1 inv.
template <int SGN>
__device__ __forceinline__ void fft8p(ull v[8]) {
    const float S = (float)SGN;
    const float C = 0.70710678118654752440f;
    ull t0 = PADD(v[0], v[4]), t4 = PSUB(v[0], v[4]);
    ull t1 = PADD(v[1], v[5]), t5 = PSUB(v[1], v[5]);
    ull t2 = PADD(v[2], v[6]), t6 = PSUB(v[2], v[6]);
    ull t3 = PADD(v[3], v[7]), t7 = PSUB(v[3], v[7]);
    float2 f5 = UPK(t5), f6 = UPK(t6), f7 = UPK(t7);
    t5 = PK(C * (f5.x - S * f5.y), C * (S * f5.x + f5.y));
    t6 = PK(-S * f6.y, S * f6.x);
    t7 = PK(C * (-f7.x - S * f7.y), C * (S * f7.x - f7.y));
    ull u0 = PADD(t0, t2), u2 = PSUB(t0, t2);
    ull u1 = PADD(t1, t3);
    float2 d13 = UPK(PSUB(t1, t3));
    ull u3 = PK(-S * d13.y, S * d13.x);
    ull u4 = PADD(t4, t6), u6 = PSUB(t4, t6);
    ull u5 = PADD(t5, t7);
    float2 d57 = UPK(PSUB(t5, t7));
    ull u7 = PK(-S * d57.y, S * d57.x);
    v[0] = PADD(u0, u1); v[4] = PSUB(u0, u1);
    v[2] = PADD(u2, u3); v[6] = PSUB(u2, u3);
    v[1] = PADD(u4, u5); v[5] = PSUB(u4, u5);
    v[3] = PADD(u6, u7); v[7] = PSUB(u6, u7);
}

__device__ __forceinline__ ull tw_mul(ull z, float2 w) {
    float2 f = UPK(z);
    return PK(f.x * w.x - f.y * w.y, f.x * w.y + f.y * w.x);
}

// Row pass with input already in registers (v[n1] = z[g][8*n1+t]).
template <int SGN>
__device__ __forceinline__ void row_pass_reg(ull v[8], float2* smf, const float2* s_tw, int tid) {
    ull* sm = (ull*)smf;
    const int g = tid >> 3, t = tid & 7;
    fft8p<SGN>(v);
#pragma unroll
    for (int k1 = 1; k1 < 8; k1++) {
        float2 w = s_tw[(t * k1) & 63];
        if (SGN == 1) w.y = -w.y;
        v[k1] = tw_mul(v[k1], w);
    }
    __syncwarp();
#pragma unroll
    for (int k1 = 0; k1 < 8; k1++) sm[fft_phys(g, 8 * k1 + (t ^ k1))] = v[k1];
    __syncwarp();
#pragma unroll
    for (int n2 = 0; n2 < 8; n2++) v[n2] = sm[fft_phys(g, 8 * t + (n2 ^ t))];
    fft8p<SGN>(v);
    __syncwarp();
#pragma unroll
    for (int k2 = 0; k2 < 8; k2++) sm[fft_phys(g, t + 8 * k2)] = v[k2];
}

// One pass (rows or cols) of a 64x64 2D FFT in shared memory (LDS-sourced).
template <int SGN, bool ROWS>
__device__ __forceinline__ void fft_pass(float2* smf, const float2* s_tw, int tid) {
    ull* sm = (ull*)smf;
    const int g = tid >> 3;
    const int t = tid & 7;
#define LIDX(m) (ROWS ? fft_phys(g, (m)) : fft_phys((m), g))
    ull v[8];
#pragma unroll
    for (int n1 = 0; n1 < 8; n1++) v[n1] = sm[LIDX(8 * n1 + t)];
    fft8p<SGN>(v);
#pragma unroll
    for (int k1 = 1; k1 < 8; k1++) {
        float2 w = s_tw[(t * k1) & 63];
        if (SGN == 1) w.y = -w.y;
        v[k1] = tw_mul(v[k1], w);
    }
    __syncwarp();
#pragma unroll
    for (int k1 = 0; k1 < 8; k1++) sm[LIDX(8 * k1 + (t ^ k1))] = v[k1];
    __syncwarp();
#pragma unroll
    for (int n2 = 0; n2 < 8; n2++) v[n2] = sm[LIDX(8 * t + (n2 ^ t))];
    fft8p<SGN>(v);
    __syncwarp();
#pragma unroll
    for (int k2 = 0; k2 < 8; k2++) sm[LIDX(t + 8 * k2)] = v[k2];
#undef LIDX
}

// needed(B): does G[B] (built from batch-B magnitudes) feed any surviving plane?
__device__ __forceinline__ bool batch_needed(const float* __restrict__ fbs, int B,
                                             int tid, int* s_flag) {
    if (tid == 0) *s_flag = 0;
    __syncthreads();
    if (tid < 64) {
        int si = (int)floorf((fbs[tid * 2 + 0] + 1.f) * 0.5f * 64.f);
        int ei = (int)floorf((fbs[tid * 2 + 1] + 1.f) * 0.5f * 64.f);
        int iB = (B + 32) & 63;
        if (iB >= si && iB < ei) *s_flag = 1;
    }
    __syncthreads();
    return *s_flag != 0;
}

// ---------------- kernel 1: fused [3x3 conv partials (4ch/block)] + [two-for-one fwd FFT] ----------
// Blocks [0,1024): conv (b, 4-channel group).  Blocks [1024,3072): FFT pair (skipped if unused).
__global__ __launch_bounds__(512, 2) void k1_fft_conv(const float* __restrict__ x,
                                                      const float* __restrict__ cw,
                                                      const float* __restrict__ fbs) {
    __shared__ __align__(16) char sh[FFT_SM_F2 * 8 + 512];
    __shared__ int s_flag;
    const int tid = threadIdx.x;

    if (blockIdx.x < 1024) {
        // ---- conv path: 4 channels, padded stride-72 layout, float4 fills ----
        float* sp = (float*)sh;            // 66 rows x 72 floats = 19008 B
        float* sw = (float*)(sh + 19008);  // 36 floats
        const int idx = blockIdx.x;
        const int b = idx & 63, cg = idx >> 6;
        const int c0 = cg * 4;
        const int ww = tid & 63, hb8 = (tid >> 6) * 8;
        for (int k = tid; k < 66 * 72; k += 512) sp[k] = 0.f;
        for (int k = tid; k < 36; k += 512) sw[k] = cw[c0 * 9 + k];
        ull acc2[4];
#pragma unroll
        for (int q = 0; q < 4; q++) acc2[q] = PK(0.f, 0.f);
        const float4* xb4 = (const float4*)(x + ((size_t)b * 64 + c0) * 4096);
#pragma unroll
        for (int c = 0; c < 4; c++) {
            __syncthreads();
#pragma unroll
            for (int k = tid; k < 1024; k += 512) {
                int row = k >> 4, q4 = (k & 15) * 4;
                *(float4*)&sp[(row + 1) * 72 + 4 + q4] = xb4[c * 1024 + k];
            }
            __syncthreads();
            ull wd[9];
#pragma unroll
            for (int j = 0; j < 9; j++) {
                float wv = sw[c * 9 + j];
                wd[j] = PK(wv, wv);
            }
#pragma unroll
            for (int kw = 0; kw < 3; kw++) {
                float wcol[10];
#pragma unroll
                for (int rr = 0; rr < 10; rr++) wcol[rr] = sp[(hb8 + rr) * 72 + 3 + ww + kw];
                ull pkc[6];
#pragma unroll
                for (int j = 0; j < 6; j++) pkc[j] = PK(wcol[j], wcol[j + 4]);
#pragma unroll
                for (int q = 0; q < 4; q++)
#pragma unroll
                    for (int kh = 0; kh < 3; kh++)
                        acc2[q] = PFMA(pkc[q + kh], wd[kh * 3 + kw], acc2[q]);
            }
        }
        float* o = d_sp4 + ((size_t)cg * 64 + b) * 4096;
#pragma unroll
        for (int q = 0; q < 4; q++) {
            float2 a = UPK(acc2[q]);
            o[(hb8 + q) * 64 + ww] = a.x;
            o[(hb8 + q + 4) * 64 + ww] = a.y;
        }
    } else {
        const int fb = blockIdx.x - 1024;
        const int b = fb >> 5;
        if (!batch_needed(fbs, b, tid, &s_flag)) return;  // dead magnitudes
        float2* sm = (float2*)sh;
        float2* s_tw = (float2*)(sh + FFT_SM_F2 * 8);
        const int i0 = (fb & 31) * 2;
        if (tid < 64) {
            float sn, cs;
            __sincosf(-6.283185307179586f * (float)tid * (1.0f / 64.0f), &sn, &cs);
            s_tw[tid] = make_float2(cs, sn);
        }
        __syncthreads();
        const float* xp0 = x + ((size_t)(b * 64 + i0)) * 4096;
        const float* xp1 = xp0 + 4096;
        {
            const int g = tid >> 3, t = tid & 7;
            ull v[8];
#pragma unroll
            for (int n1 = 0; n1 < 8; n1++) {
                int idx = g * 64 + 8 * n1 + t;
                v[n1] = PK(xp0[idx], xp1[idx]);
            }
            row_pass_reg<-1>(v, sm, s_tw, tid);
        }
        __syncthreads();
        fft_pass<-1, false>(sm, s_tw, tid);
        __syncthreads();
        __half* m0 = d_Mh + ((size_t)(b * 64 + i0)) * 4096;
        __half* m1 = m0 + 4096;
#pragma unroll
        for (int n = 0; n < 8; n++) {
            int k = tid + n * 512;
            int r = k >> 6, c = k & 63;
            float2 Zk = sm[fft_phys(r, c)];
            float2 Zm = sm[fft_phys((64 - r) & 63, (64 - c) & 63)];
            float sx = Zk.x + Zm.x, sy = Zk.y - Zm.y;
            float dx = Zk.x - Zm.x, dy = Zk.y + Zm.y;
            m0[k] = __float2half(0.5f * sqrtf(sx * sx + sy * sy));
            m1[k] = __float2half(0.5f * sqrtf(dx * dx + dy * dy));
        }
    }
}

// ---------------- kernel 2: [conv reduce + conv-only out stream] + [tensor-core attention] ------
// Blocks [0,64): reduce partials for batch b, write d_sp AND write c1*conv to ALL 64 out planes.
// Blocks [64,1088): attention tile (skipped if i unused).
__global__ __launch_bounds__(256, 2) void attn_kernel(
    const float* __restrict__ f0, const float* __restrict__ theta,
    const float* __restrict__ sigma, const float* __restrict__ theta0,
    const float* __restrict__ w1, const float* __restrict__ b1,
    const float* __restrict__ w2, const float* __restrict__ b2,
    const float* __restrict__ fbs, const float* __restrict__ mixp,
    float* __restrict__ out) {
    const int tid = threadIdx.x;
    if (blockIdx.x < 64) {  // conv reduce + out stream
        const int b = blockIdx.x;
        const float c1 = 1.f - mixp[0];
        const float4* A = ((const float4*)d_sp4) + (size_t)b * 1024;
        float4* O = ((float4*)d_sp) + (size_t)b * 1024;
        float4* ob = ((float4*)out) + (size_t)b * 65536;
#pragma unroll
        for (int q = tid; q < 1024; q += 256) {
            float4 s = A[q];
#pragma unroll
            for (int j = 1; j < 16; j++) {
                float4 p = A[q + j * 65536];
                s.x += p.x; s.y += p.y; s.z += p.z; s.w += p.w;
            }
            O[q] = s;
            float4 w = make_float4(c1 * s.x, c1 * s.y, c1 * s.z, c1 * s.w);
            for (int i = 0; i < 64; i++) ob[i * 1024 + q] = w;
        }
        return;
    }
    __shared__ int s_flag;
    const int i = (blockIdx.x - 64) >> 4;
    if (!batch_needed(fbs, i, tid, &s_flag)) return;  // G[i] never read
    __shared__ __align__(16) __half sA[64 * 72];
    __shared__ __align__(16) __half sM[64 * 264];
    __shared__ float s_w2[3 * 64];
    __shared__ float s_b1[64];
    __shared__ float s_lf0[3], s_i2ls2[3], s_th[3], s_i2t02[3], s_b2[3];
    const int pbeg = ((blockIdx.x - 64) & 15) * 256;

    for (int k = tid; k < 4096; k += 256) {
        int o = k >> 6, c = k & 63;
        sA[o * 72 + c] = __float2half(w1[o * 64 + ((c + 32) & 63)]);
    }
    for (int t = tid; t < 2048; t += 256) {
        int c = t >> 5, q = t & 31;
        uint4 v = *(const uint4*)(d_Mh + ((size_t)(i * 64 + c)) * 4096 + pbeg + q * 8);
        *(uint4*)&sM[c * 264 + q * 8] = v;
    }
    if (tid < 64) s_b1[tid] = b1[tid];
    if (tid < 192) s_w2[tid] = w2[tid];
    if (tid < 3) {
        s_b2[tid] = b2[tid];
        int ip = (i + 32) & 63;
        int idx = tid * 64 + ip;
        s_lf0[tid] = logf(f0[idx]);
        float ls = logf(sigma[idx]);
        s_i2ls2[tid] = 1.f / (2.f * ls * ls);
        s_th[tid] = theta[idx];
        float t0v = theta0[idx];
        s_i2t02[tid] = 1.f / (2.f * t0v * t0v);
    }
    __syncthreads();

    const int wid = tid >> 5, lane = tid & 31;
    const int o0 = (wid & 3) << 4, pw = (wid >> 2) << 7;
    const uint32_t sA_addr = (uint32_t)__cvta_generic_to_shared(sA);
    const uint32_t sM_addr = (uint32_t)__cvta_generic_to_shared(sM);

    uint32_t a[4][4];
#pragma unroll
    for (int ks = 0; ks < 4; ks++) {
        uint32_t addr = sA_addr + (uint32_t)(((o0 + (lane & 15)) * 72 + ks * 16 + ((lane >> 4) << 3)) * 2);
        ldsm_x4(a[ks], addr);
    }
    float acc[16][4];
#pragma unroll
    for (int j = 0; j < 16; j++)
#pragma unroll
        for (int q = 0; q < 4; q++) acc[j][q] = 0.f;
#pragma unroll
    for (int j = 0; j < 16; j++) {
#pragma unroll
        for (int ks = 0; ks < 4; ks++) {
            uint32_t b[2];
            uint32_t addr = sM_addr + (uint32_t)(((ks * 16 + (lane & 15)) * 264 + pw + j * 8) * 2);
            ldsm_x2_trans(b, addr);
            mma16816(acc[j], a[ks], b);
        }
    }
    __syncthreads();

    {
        const int r0 = o0 + (lane >> 2);
        const int cbase = pw + (lane & 3) * 2;
        float b1a = s_b1[r0], b1b = s_b1[r0 + 8];
#pragma unroll
        for (int j = 0; j < 16; j++) {
            int c = cbase + j * 8;
            *(__half2*)&sM[r0 * 264 + c] =
                __floats2half2_rn(fmaxf(acc[j][0] + b1a, 0.f), fmaxf(acc[j][1] + b1a, 0.f));
            *(__half2*)&sM[(r0 + 8) * 264 + c] =
                __floats2half2_rn(fmaxf(acc[j][2] + b1b, 0.f), fmaxf(acc[j][3] + b1b, 0.f));
        }
    }
    __syncthreads();

    {
        float l0 = s_b2[0], l1 = s_b2[1], l2 = s_b2[2];
#pragma unroll
        for (int o = 0; o < 64; o++) {
            float hv = __half2float(sM[o * 264 + tid]);
            l0 = fmaf(s_w2[o], hv, l0);
            l1 = fmaf(s_w2[64 + o], hv, l1);
            l2 = fmaf(s_w2[128 + o], hv, l2);
        }
        float mx = fmaxf(l0, fmaxf(l1, l2));
        float e0 = __expf(l0 - mx), e1 = __expf(l1 - mx), e2 = __expf(l2 - mx);
        float inv = 1.f / (e0 + e1 + e2);
        const int p = pbeg + tid;
        int hh = ((p >> 6) + 32) & 63;
        int ww = ((p & 63) + 32) & 63;
        float yv_ = -1.f + 2.f * (float)hh * (1.f / 63.f);
        float xv_ = -1.f + 2.f * (float)ww * (1.f / 63.f);
        float r2 = xv_ * xv_ + yv_ * yv_ + 1e-6f;
        float lr = 0.5f * logf(r2);
        float phi = atan2f(yv_, xv_);
        float G = 0.f;
        float awv[3] = {e0 * inv, e1 * inv, e2 * inv};
#pragma unroll
        for (int s = 0; s < 3; s++) {
            float dl = lr - s_lf0[s];
            float dp = phi - s_th[s];
            float F = __expf(-(dl * dl) * s_i2ls2[s] - (dp * dp) * s_i2t02[s]);
            G = fmaf(F, awv[s], G);
        }
        d_G[i * 4096 + p] = G;
    }
}

// ---------------- kernel 3: survivors only — two-for-one filter + IFFT, overwrite out ------------
__global__ __launch_bounds__(512, 2) void inv_kernel(const float* __restrict__ x,
                                                     const float* __restrict__ fbs,
                                                     const float* __restrict__ mixp,
                                                     float* __restrict__ out) {
    __shared__ float2 sm[FFT_SM_F2];
    __shared__ float2 s_tw[64];
    const int plane = blockIdx.x;
    const int b = plane >> 6, i = plane & 63;
    const int tid = threadIdx.x;
    const int bb = (b + 32) & 63;
    const int si = (int)floorf((fbs[bb * 2 + 0] + 1.f) * 0.5f * 64.f);
    const int ei = (int)floorf((fbs[bb * 2 + 1] + 1.f) * 0.5f * 64.f);
    const int ii = (i + 32) & 63;
    if (!(ii >= si && ii < ei)) return;     // conv-only planes already written by attn
    const int j = ii - si;
    if (j & 1) return;                      // handled by partner block (i-1)
    const bool haspart = (ii + 1 < ei);
    const float mix = mixp[0];
    const float c1 = 1.f - mix;
    const float4* sb4 = ((const float4*)d_sp) + (size_t)b * 1024;

    if (tid < 64) {
        float sn, cs;
        __sincosf(-6.283185307179586f * (float)tid * (1.0f / 64.0f), &sn, &cs);
        s_tw[tid] = make_float2(cs, sn);
    }
    __syncthreads();
    const float* xp0 = x + (size_t)plane * 4096;
    const float* xp1 = xp0 + 4096;
    {
        const int g = tid >> 3, t = tid & 7;
        ull v[8];
#pragma unroll
        for (int n1 = 0; n1 < 8; n1++) {
            int idx = g * 64 + 8 * n1 + t;
            v[n1] = PK(xp0[idx], haspart ? xp1[idx] : 0.f);
        }
        row_pass_reg<-1>(v, sm, s_tw, tid);
    }
    __syncthreads();
    fft_pass<-1, false>(sm, s_tw, tid);
    __syncthreads();
    const float* G0 = d_G + i * 4096;
    const float* G1 = d_G + (i + 1) * 4096;
    float2 P[8];
#pragma unroll
    for (int n = 0; n < 8; n++) {
        int k = tid + n * 512;
        int r = k >> 6, c = k & 63;
        int rm = (64 - r) & 63, cm = (64 - c) & 63;
        int km = rm * 64 + cm;
        float2 Zk = sm[fft_phys(r, c)];
        float2 Zm = sm[fft_phys(rm, cm)];
        int hh = (r + 32) & 63, hhm = (rm + 32) & 63;
        float mr = (hh >= si && hh < ei) ? 0.5f : 0.f;
        float mrm = (hhm >= si && hhm < ei) ? 0.5f : 0.f;
        float g0 = G0[k] * mr + G0[km] * mrm;
        float g1 = haspart ? (G1[k] * mr + G1[km] * mrm) : 0.f;
        float y0x = 0.5f * (Zk.x + Zm.x), y0y = 0.5f * (Zk.y - Zm.y);
        float y1x = 0.5f * (Zk.y + Zm.y), y1y = -0.5f * (Zk.x - Zm.x);
        P[n] = make_float2(y0x * g0 - g1 * y1y, y0y * g0 + g1 * y1x);
    }
    __syncthreads();
#pragma unroll
    for (int n = 0; n < 8; n++) {
        int k = tid + n * 512;
        sm[fft_phys(k >> 6, k & 63)] = P[n];
    }
    __syncthreads();
    fft_pass<1, true>(sm, s_tw, tid);
    __syncthreads();
    fft_pass<1, false>(sm, s_tw, tid);
    __syncthreads();
    const float scale = mix * (1.f / 4096.f);
    float4* op0 = (float4*)(out + (size_t)plane * 4096);
    float4* op1 = (float4*)(out + (size_t)(plane + 1) * 4096);
#pragma unroll
    for (int q = tid; q < 1024; q += 512) {
        int r = q >> 4, c = (q & 15) * 4;
        float2 w0 = sm[fft_phys(r, c + 0)];
        float2 w1v = sm[fft_phys(r, c + 1)];
        float2 w2v = sm[fft_phys(r, c + 2)];
        float2 w3 = sm[fft_phys(r, c + 3)];
        float4 s = sb4[q];
        op0[q] = make_float4(fmaf(scale, w0.x, c1 * s.x), fmaf(scale, w1v.x, c1 * s.y),
                             fmaf(scale, w2v.x, c1 * s.z), fmaf(scale, w3.x, c1 * s.w));
        if (haspart)
            op1[q] = make_float4(fmaf(scale, w0.y, c1 * s.x), fmaf(scale, w1v.y, c1 * s.y),
                                 fmaf(scale, w2v.y, c1 * s.z), fmaf(scale, w3.y, c1 * s.w));
    }
}

// ---------------- launch ----------------
extern "C" void kernel_launch(void* const* d_in, const int* in_sizes, int n_in,
                              void* d_out, int out_size) {
    const float* x      = (const float*)d_in[0];
    const float* f0     = (const float*)d_in[1];
    const float* theta  = (const float*)d_in[2];
    const float* sigma  = (const float*)d_in[3];
    const float* theta0 = (const float*)d_in[4];
    const float* fbs    = (const float*)d_in[5];
    const float* mix    = (const float*)d_in[6];
    const float* w1     = (const float*)d_in[7];
    const float* b1     = (const float*)d_in[8];
    const float* w2     = (const float*)d_in[9];
    const float* b2     = (const float*)d_in[10];
    const float* conv_w = (const float*)d_in[11];
    float* out = (float*)d_out;

    k1_fft_conv<<<3072, 512>>>(x, conv_w, fbs);
    attn_kernel<<<1088, 256>>>(f0, theta, sigma, theta0, w1, b1, w2, b2, fbs, mix, out);
    inv_kernel<<<4096, 512>>>(x, fbs, mix, out);
}